// round 3
// baseline (speedup 1.0000x reference)
#include <cuda_runtime.h>
#include <cstdint>
#include <cmath>

#define HIDDEN 768
#define NHEADS 12
#define HDIM 64
#define BB 8
#define SS 512
#define ROWS (BB*SS)              // 4096
#define HEADROWS (BB*NHEADS*SS)   // 49152

// ---------------- scratch (static device allocations; no cudaMalloc) ----------------
__device__ float g_Xd[(size_t)ROWS*HIDDEN];        // dequant hidden_states (fp32, = ref's quantize(x))
__device__ float g_Wd[(size_t)3*HIDDEN*HIDDEN];    // dequant Wq|Wk|Wv
__device__ float g_Wod[(size_t)HIDDEN*HIDDEN];     // dequant Wo
__device__ float g_QKV[(size_t)ROWS*3*HIDDEN];     // projection output (fp32)
__device__ float g_Qd[(size_t)HEADROWS*HDIM];      // dequant per-head q
__device__ float g_Kd[(size_t)HEADROWS*HDIM];
__device__ float g_Vd[(size_t)HEADROWS*HDIM];
__device__ float g_P [(size_t)HEADROWS*SS];        // dequant quantized probs
__device__ float g_CTX[(size_t)ROWS*HIDDEN];
__device__ float g_Cd[(size_t)ROWS*HIDDEN];        // dequant quantized ctx

struct PLA { float m[12]; float c[12]; float iv[13]; };

// ---------------- per-row (768) symmetric int8 fake-quant -> dequant fp32 ----------------
__global__ void rowquant_dq(const float* __restrict__ src, float* __restrict__ dst) {
    int row = blockIdx.x;
    const float* x = src + (size_t)row * HIDDEN;
    int t = threadIdx.x;
    float v0 = x[t], v1 = x[t+256], v2 = x[t+512];
    float loc = fmaxf(fabsf(v0), fmaxf(fabsf(v1), fabsf(v2)));
    #pragma unroll
    for (int o=16;o>0;o>>=1) loc = fmaxf(loc, __shfl_xor_sync(0xffffffffu, loc, o));
    __shared__ float wm[8];
    __shared__ float s_scale;
    if ((t&31)==0) wm[t>>5]=loc;
    __syncthreads();
    if (t==0) {
        float m = wm[0];
        #pragma unroll
        for (int i=1;i<8;i++) m = fmaxf(m, wm[i]);
        float sc = __fdiv_rn(m, 127.0f);
        if (sc == 0.0f) sc = 1.0f;
        s_scale = sc;
    }
    __syncthreads();
    float sc = s_scale;
    float* d = dst + (size_t)row*HIDDEN;
    float r0 = fminf(fmaxf(rintf(__fdiv_rn(v0, sc)), -127.0f), 127.0f);
    float r1 = fminf(fmaxf(rintf(__fdiv_rn(v1, sc)), -127.0f), 127.0f);
    float r2 = fminf(fmaxf(rintf(__fdiv_rn(v2, sc)), -127.0f), 127.0f);
    d[t]     = __fmul_rn(r0, sc);
    d[t+256] = __fmul_rn(r1, sc);
    d[t+512] = __fmul_rn(r2, sc);
}

// ---------------- fp32 GEMM, Eigen-order: per-output strict ascending-k fused FMA ----------------
// C[m,n] = sum_k A[m,k]*B[n,k] (fma chain, k ascending) + bias[n]
// A [M,768], B [N,768] row-major f32. Tile 128(M) x 64(N), BK=16, 256 threads, 8x4 per thread.
__global__ void __launch_bounds__(256) gemm_seq(const float* __restrict__ A,
                                                const float* __restrict__ B,
                                                const float* __restrict__ b0,
                                                const float* __restrict__ b1,
                                                const float* __restrict__ b2,
                                                float* __restrict__ C, int N) {
    __shared__ float As[16][132];
    __shared__ float Bs[16][68];
    int t = threadIdx.x;
    int m0 = blockIdx.y * 128;
    int n0 = blockIdx.x * 64;
    int tx = t & 15;          // n group (tx*4)
    int ty = t >> 4;          // m group (ty*8)
    float acc[8][4];
    #pragma unroll
    for (int i=0;i<8;i++){acc[i][0]=0;acc[i][1]=0;acc[i][2]=0;acc[i][3]=0;}
    for (int kt = 0; kt < 48; ++kt) {
        #pragma unroll
        for (int l=0;l<2;l++) {
            int lin = t + l*256;          // 0..511
            int r = lin >> 2;             // 0..127
            int c4 = lin & 3;             // 0..3
            float4 v = *(const float4*)(A + (size_t)(m0+r)*HIDDEN + kt*16 + c4*4);
            As[c4*4+0][r]=v.x; As[c4*4+1][r]=v.y; As[c4*4+2][r]=v.z; As[c4*4+3][r]=v.w;
        }
        {
            int r = t >> 2, c4 = t & 3;
            float4 v = *(const float4*)(B + (size_t)(n0+r)*HIDDEN + kt*16 + c4*4);
            Bs[c4*4+0][r]=v.x; Bs[c4*4+1][r]=v.y; Bs[c4*4+2][r]=v.z; Bs[c4*4+3][r]=v.w;
        }
        __syncthreads();
        #pragma unroll
        for (int k=0;k<16;k++) {          // ascending k within tile; tiles ascending -> global ascending
            float a[8], b[4];
            *(float4*)&a[0] = *(const float4*)&As[k][ty*8];
            *(float4*)&a[4] = *(const float4*)&As[k][ty*8+4];
            *(float4*)&b[0] = *(const float4*)&Bs[k][tx*4];
            #pragma unroll
            for (int i=0;i<8;i++)
                #pragma unroll
                for (int j=0;j<4;j++)
                    acc[i][j] = fmaf(a[i], b[j], acc[i][j]);
        }
        __syncthreads();
    }
    #pragma unroll
    for (int i=0;i<8;i++) {
        int gm = m0 + ty*8 + i;
        #pragma unroll
        for (int j=0;j<4;j++) {
            int gn = n0 + tx*4 + j;
            float bias;
            if (gn < 768) bias = b0[gn];
            else if (gn < 1536) bias = b1[gn-768];
            else bias = b2[gn-1536];
            acc[i][j] = __fadd_rn(acc[i][j], bias);
        }
        *(float4*)(C + (size_t)gm*N + n0 + tx*4) = *(float4*)&acc[i][0];
    }
}

// ---------------- per-head (64) fake-quant of q/k/v -> dequant fp32 [B,H,S,64] ----------------
__global__ void quant_heads_dq() {
    int w = blockIdx.x * 8 + (threadIdx.x >> 5);
    int lane = threadIdx.x & 31;
    int tsel = w / HEADROWS;     // 0=q,1=k,2=v
    int rem = w - tsel*HEADROWS; // (b*12+h)*512+s
    int b = rem / (NHEADS*SS);
    int h = (rem / SS) % NHEADS;
    int s = rem % SS;
    const float* src = g_QKV + ((size_t)(b*SS+s)*(3*HIDDEN)) + tsel*HIDDEN + h*HDIM + lane*2;
    float2 v = *(const float2*)src;
    float loc = fmaxf(fabsf(v.x), fabsf(v.y));
    #pragma unroll
    for (int o=16;o>0;o>>=1) loc = fmaxf(loc, __shfl_xor_sync(0xffffffffu, loc, o));
    float sc = __fdiv_rn(loc, 127.0f);
    if (sc == 0.0f) sc = 1.0f;
    float* dst = (tsel==0)? g_Qd : (tsel==1? g_Kd : g_Vd);
    float rx = fminf(fmaxf(rintf(__fdiv_rn(v.x, sc)), -127.0f), 127.0f);
    float ry = fminf(fmaxf(rintf(__fdiv_rn(v.y, sc)), -127.0f), 127.0f);
    float2 o2;
    o2.x = __fmul_rn(rx, sc);
    o2.y = __fmul_rn(ry, sc);
    *(float2*)(dst + (size_t)rem*HDIM + lane*2) = o2;
}

// ---------------- attention phase A: scores (seq-k fma) + PLA softmax (strict-seq sum) + prob quant ----------------
// grid (96, 8): CTA = (b,h) x 64 q-rows; 8 warps x 8 rows.
#define SMEM_A (512*68*4 + 8*64*4 + 8*512*4)
__global__ void __launch_bounds__(256,1) attnA(PLA pla) {
    extern __shared__ char smem[];
    float* Ks   = (float*)smem;                          // [512][68]
    float* qs   = (float*)(smem + 512*68*4);             // [8][64]
    float* ebuf = (float*)(smem + 512*68*4 + 8*64*4);    // [8 warps][512]
    int t = threadIdx.x;
    int w = t >> 5, lane = t & 31;
    int bh = blockIdx.x;

    const float* Kg = g_Kd + (size_t)bh*SS*HDIM;
    for (int i = t; i < SS*HDIM; i += 256) {
        int k = i >> 6, d = i & 63;
        Ks[k*68 + d] = Kg[i];
    }
    __syncthreads();

    int rowbase = blockIdx.y*64 + w*8;
    float* q = qs + w*64;
    float* eb = ebuf + w*512;

    for (int rr = 0; rr < 8; ++rr) {
        int srow = rowbase + rr;
        const float* Qg = g_Qd + ((size_t)bh*SS + srow)*HDIM;
        q[lane] = Qg[lane];
        q[lane+32] = Qg[lane+32];
        __syncwarp();
        float sc[16];
        #pragma unroll
        for (int j=0;j<16;j++) sc[j] = 0.0f;
        #pragma unroll
        for (int d4 = 0; d4 < 16; ++d4) {    // ascending d, fused fma per score element
            float4 qv = *(const float4*)&q[d4*4];
            #pragma unroll
            for (int j = 0; j < 16; j++) {
                int kk = lane + 32*j;
                float4 kv = *(const float4*)&Ks[kk*68 + d4*4];
                sc[j] = fmaf(qv.x, kv.x, sc[j]);
                sc[j] = fmaf(qv.y, kv.y, sc[j]);
                sc[j] = fmaf(qv.z, kv.z, sc[j]);
                sc[j] = fmaf(qv.w, kv.w, sc[j]);
            }
        }
        #pragma unroll
        for (int j=0;j<16;j++) sc[j] = __fmul_rn(sc[j], 0.125f);
        float mx = sc[0];
        #pragma unroll
        for (int j=1;j<16;j++) mx = fmaxf(mx, sc[j]);
        #pragma unroll
        for (int o=16;o>0;o>>=1) mx = fmaxf(mx, __shfl_xor_sync(0xffffffffu, mx, o));
        #pragma unroll
        for (int j = 0; j < 16; j++) {
            float sh = __fadd_rn(sc[j], -mx);
            float fr = rintf(__fmul_rn(sh, 67108864.0f));
            fr = fminf(fmaxf(fr, -2147483648.0f), 2147483648.0f);
            float fx = __fmul_rn(fr, 1.4901161193847656e-8f); // * 2^-26
            float xc = fminf(fmaxf(fx, -10.0f), 0.0f);
            int cnt = 0;
            #pragma unroll
            for (int i = 0; i < 13; i++) cnt += (xc >= pla.iv[i]) ? 1 : 0;
            int idx = cnt - 1; if (idx < 0) idx = 0; if (idx > 11) idx = 11;
            float e = __fadd_rn(__fmul_rn(pla.m[idx], xc), pla.c[idx]);
            sc[j] = e;
            eb[lane + 32*j] = e;   // stash exps for strict-sequential sum
        }
        __syncwarp();
        // strict in-order sum of 512 exps (replicates XLA strict reduce)
        float ssum = 0.0f;
        if (lane == 0) {
            #pragma unroll 8
            for (int i = 0; i < 512; i++) ssum = __fadd_rn(ssum, eb[i]);
        }
        ssum = __shfl_sync(0xffffffffu, ssum, 0);
        float denom = __fadd_rn(ssum, 1e-9f);
        float qmx = 0.0f;
        #pragma unroll
        for (int j = 0; j < 16; j++) {
            float smv = __fdiv_rn(sc[j], denom);
            sc[j] = smv;
            qmx = fmaxf(qmx, fabsf(smv));
        }
        #pragma unroll
        for (int o=16;o>0;o>>=1) qmx = fmaxf(qmx, __shfl_xor_sync(0xffffffffu, qmx, o));
        float sp = __fdiv_rn(qmx, 127.0f);
        if (sp == 0.0f) sp = 1.0f;
        float* prow = g_P + ((size_t)bh*SS + srow)*SS;
        #pragma unroll
        for (int j = 0; j < 16; j++) {
            float r = fminf(fmaxf(rintf(__fdiv_rn(sc[j], sp)), -127.0f), 127.0f);
            prow[lane + 32*j] = __fmul_rn(r, sp);
        }
        __syncwarp();
    }
}

// ---------------- attention phase B: ctx = P @ Vd (seq ascending-k fused fma) ----------------
// grid (96, 4): CTA = (b,h) x 128 q-rows.
#define SMEM_B (512*68*4 + 128*33*4)
__global__ void __launch_bounds__(256,1) attnB() {
    extern __shared__ char smem[];
    float* Vs = (float*)smem;                   // [512][68]
    float* Ps = (float*)(smem + 512*68*4);      // [128][33]
    int t = threadIdx.x;
    int bh = blockIdx.x;
    int m0 = blockIdx.y * 128;
    int tx = t & 15;     // d group (tx*4)
    int ty = t >> 4;     // m group (ty*8)

    const float* Vg = g_Vd + (size_t)bh*SS*HDIM;
    for (int i = t; i < SS*HDIM; i += 256) {
        int k = i >> 6, d = i & 63;
        Vs[k*68 + d] = Vg[i];
    }
    __syncthreads();

    float acc[8][4];
    #pragma unroll
    for (int i=0;i<8;i++){acc[i][0]=0;acc[i][1]=0;acc[i][2]=0;acc[i][3]=0;}

    const float* Pg = g_P + ((size_t)bh*SS + m0)*SS;
    for (int kt = 0; kt < 16; ++kt) {           // ascending k chunks
        #pragma unroll
        for (int l=0;l<4;l++) {
            int lin = t + l*256;                // 0..1023
            int m = lin >> 3;                   // 0..127
            int k4 = lin & 7;                   // 0..7
            float4 v = *(const float4*)(Pg + (size_t)m*SS + kt*32 + k4*4);
            Ps[m*33 + k4*4+0]=v.x; Ps[m*33 + k4*4+1]=v.y;
            Ps[m*33 + k4*4+2]=v.z; Ps[m*33 + k4*4+3]=v.w;
        }
        __syncthreads();
        #pragma unroll 8
        for (int kk = 0; kk < 32; ++kk) {       // ascending within chunk
            float4 vv = *(const float4*)&Vs[(kt*32+kk)*68 + tx*4];
            #pragma unroll
            for (int i=0;i<8;i++) {
                float p = Ps[(ty*8+i)*33 + kk];
                acc[i][0] = fmaf(p, vv.x, acc[i][0]);
                acc[i][1] = fmaf(p, vv.y, acc[i][1]);
                acc[i][2] = fmaf(p, vv.z, acc[i][2]);
                acc[i][3] = fmaf(p, vv.w, acc[i][3]);
            }
        }
        __syncthreads();
    }
    int b = bh / NHEADS, h = bh % NHEADS;
    #pragma unroll
    for (int i=0;i<8;i++) {
        int s = m0 + ty*8 + i;
        *(float4*)(g_CTX + ((size_t)(b*SS + s))*HIDDEN + h*HDIM + tx*4) = *(float4*)&acc[i][0];
    }
}

// ---------------- host: replicate np.polyfit coefficients in double ----------------
static void build_pla(PLA& p) {
    double xs[1001], ys[1001];
    double step = 10.0 / 1000.0;
    for (int j = 0; j <= 1000; j++) xs[j] = -10.0 + (double)j * step;
    xs[1000] = 0.0;
    for (int j = 0; j <= 1000; j++) ys[j] = exp(xs[j]);
    double iv[13];
    double st2 = 10.0 / 12.0;
    for (int i = 0; i < 13; i++) iv[i] = -10.0 + (double)i * st2;
    iv[12] = 0.0;
    for (int i = 0; i < 12; i++) {
        double a = iv[i], b = iv[i+1];
        double n = 0, Sx = 0, Sy = 0, Sxx = 0, Sxy = 0;
        for (int j = 0; j <= 1000; j++) {
            if (xs[j] >= a && xs[j] <= b) {
                n += 1.0; Sx += xs[j]; Sy += ys[j];
                Sxx += xs[j]*xs[j]; Sxy += xs[j]*ys[j];
            }
        }
        double m = (n*Sxy - Sx*Sy) / (n*Sxx - Sx*Sx);
        double c = (Sy - m*Sx) / n;
        p.m[i] = (float)m;
        p.c[i] = (float)c;
    }
    for (int i = 0; i < 13; i++) p.iv[i] = (float)iv[i];
}

extern "C" void kernel_launch(void* const* d_in, const int* in_sizes, int n_in,
                              void* d_out, int out_size) {
    (void)in_sizes; (void)n_in; (void)out_size;
    const float* hs = (const float*)d_in[0];
    const float* Wq = (const float*)d_in[1];
    const float* bq = (const float*)d_in[2];
    const float* Wk = (const float*)d_in[3];
    const float* bk = (const float*)d_in[4];
    const float* Wv = (const float*)d_in[5];
    const float* bv = (const float*)d_in[6];
    const float* Wo = (const float*)d_in[7];
    const float* bo = (const float*)d_in[8];

    void *pXd, *pWd, *pWod, *pQKV, *pCTX, *pCd;
    cudaGetSymbolAddress(&pXd, g_Xd);
    cudaGetSymbolAddress(&pWd, g_Wd);
    cudaGetSymbolAddress(&pWod, g_Wod);
    cudaGetSymbolAddress(&pQKV, g_QKV);
    cudaGetSymbolAddress(&pCTX, g_CTX);
    cudaGetSymbolAddress(&pCd, g_Cd);

    PLA pla;
    build_pla(pla);

    // 1) fake-quant (dequantized fp32) activations and weights
    rowquant_dq<<<ROWS, 256>>>(hs, (float*)pXd);
    rowquant_dq<<<HIDDEN, 256>>>(Wq, (float*)pWd);
    rowquant_dq<<<HIDDEN, 256>>>(Wk, (float*)pWd + (size_t)HIDDEN*HIDDEN);
    rowquant_dq<<<HIDDEN, 256>>>(Wv, (float*)pWd + (size_t)2*HIDDEN*HIDDEN);
    rowquant_dq<<<HIDDEN, 256>>>(Wo, (float*)pWod);

    // 2) fused QKV projection (Eigen-order fp32 gemm + bias)
    gemm_seq<<<dim3(36, 32), 256>>>((const float*)pXd, (const float*)pWd,
                                    bq, bk, bv, (float*)pQKV, 3*HIDDEN);

    // 3) per-head fake-quant (dequant fp32) of q/k/v
    quant_heads_dq<<<(3*HEADROWS)/8, 256>>>();

    // 4) attention: scores + PLA softmax + prob quant, then P@V
    cudaFuncSetAttribute(attnA, cudaFuncAttributeMaxDynamicSharedMemorySize, SMEM_A);
    attnA<<<dim3(BB*NHEADS, 8), 256, SMEM_A>>>(pla);
    cudaFuncSetAttribute(attnB, cudaFuncAttributeMaxDynamicSharedMemorySize, SMEM_B);
    attnB<<<dim3(BB*NHEADS, 4), 256, SMEM_B>>>();

    // 5) fake-quant ctx rows + output projection
    rowquant_dq<<<ROWS, 256>>>((const float*)pCTX, (float*)pCd);
    gemm_seq<<<dim3(12, 32), 256>>>((const float*)pCd, (const float*)pWod,
                                    bo, bo, bo, (float*)d_out, HIDDEN);
}

// round 4
// speedup vs baseline: 1.0127x; 1.0127x over previous
#include <cuda_runtime.h>
#include <cstdint>
#include <cmath>

#define HIDDEN 768
#define NHEADS 12
#define HDIM 64
#define BB 8
#define SS 512
#define ROWS (BB*SS)              // 4096
#define HEADROWS (BB*NHEADS*SS)   // 49152

// ---------------- scratch (static device allocations; no cudaMalloc) ----------------
__device__ float g_Xd[(size_t)ROWS*HIDDEN];        // dequant hidden_states
__device__ float g_Wd[(size_t)3*HIDDEN*HIDDEN];    // dequant Wq|Wk|Wv
__device__ float g_Wod[(size_t)HIDDEN*HIDDEN];     // dequant Wo
__device__ float g_Qd[(size_t)HEADROWS*HDIM];      // dequant per-head q
__device__ float g_Kd[(size_t)HEADROWS*HDIM];
__device__ float g_Vd[(size_t)HEADROWS*HDIM];
__device__ float g_P [(size_t)HEADROWS*SS];        // dequant quantized probs
__device__ float g_CTX[(size_t)ROWS*HIDDEN];
__device__ float g_Cd[(size_t)ROWS*HIDDEN];        // dequant quantized ctx

struct PLA { float m[12]; float c[12]; float iv[13]; };

typedef unsigned long long ull;

// packed f32x2 FMA: two independent IEEE RN fmas in one instruction (FFMA2)
__device__ __forceinline__ ull ffma2(ull a, ull b, ull c) {
    ull d;
    asm("fma.rn.f32x2 %0, %1, %2, %3;" : "=l"(d) : "l"(a), "l"(b), "l"(c));
    return d;
}
__device__ __forceinline__ float2 up2(ull v) {
    float2 r;
    asm("mov.b64 {%0, %1}, %2;" : "=f"(r.x), "=f"(r.y) : "l"(v));
    return r;
}

// ---------------- per-row (768) symmetric int8 fake-quant -> dequant fp32 ----------------
__device__ __forceinline__ void rowquant_body(const float* __restrict__ x,
                                              float* __restrict__ d) {
    int t = threadIdx.x;
    float v0 = x[t], v1 = x[t+256], v2 = x[t+512];
    float loc = fmaxf(fabsf(v0), fmaxf(fabsf(v1), fabsf(v2)));
    #pragma unroll
    for (int o=16;o>0;o>>=1) loc = fmaxf(loc, __shfl_xor_sync(0xffffffffu, loc, o));
    __shared__ float wm[8];
    __shared__ float s_scale;
    if ((t&31)==0) wm[t>>5]=loc;
    __syncthreads();
    if (t==0) {
        float m = wm[0];
        #pragma unroll
        for (int i=1;i<8;i++) m = fmaxf(m, wm[i]);
        float sc = __fdiv_rn(m, 127.0f);
        if (sc == 0.0f) sc = 1.0f;
        s_scale = sc;
    }
    __syncthreads();
    float sc = s_scale;
    float r0 = fminf(fmaxf(rintf(__fdiv_rn(v0, sc)), -127.0f), 127.0f);
    float r1 = fminf(fmaxf(rintf(__fdiv_rn(v1, sc)), -127.0f), 127.0f);
    float r2 = fminf(fmaxf(rintf(__fdiv_rn(v2, sc)), -127.0f), 127.0f);
    d[t]     = __fmul_rn(r0, sc);
    d[t+256] = __fmul_rn(r1, sc);
    d[t+512] = __fmul_rn(r2, sc);
}

__global__ void rowquant_dq(const float* __restrict__ src, float* __restrict__ dst) {
    int row = blockIdx.x;
    rowquant_body(src + (size_t)row*HIDDEN, dst + (size_t)row*HIDDEN);
}

// merged: X (4096 rows) + Wq + Wk + Wv + Wo (768 each)
__global__ void rowquant_all(const float* __restrict__ x,
                             const float* __restrict__ wq, const float* __restrict__ wk,
                             const float* __restrict__ wv, const float* __restrict__ wo,
                             float* __restrict__ xd, float* __restrict__ wd,
                             float* __restrict__ wod) {
    int row = blockIdx.x;
    const float* src; float* dst; int r;
    if (row < 4096)      { r = row;      src = wq ? x : x; src = x;  dst = xd; }
    else if (row < 4864) { r = row-4096; src = wq; dst = wd; }
    else if (row < 5632) { r = row-4864; src = wk; dst = wd + (size_t)HIDDEN*HIDDEN; }
    else if (row < 6400) { r = row-5632; src = wv; dst = wd + (size_t)2*HIDDEN*HIDDEN; }
    else                 { r = row-6400; src = wo; dst = wod; }
    rowquant_body(src + (size_t)r*HIDDEN, dst + (size_t)r*HIDDEN);
}

// ---------------- fp32 GEMM 128x128, FFMA2, double-buffered, ascending-k fused FMA ----------------
// C[m,n] = sum_k A[m,k]*B[n,k] (+ bias). QUANT=1: fused per-head (64) quantize epilogue -> Qd/Kd/Vd.
// A [M,768], B [N,768] row-major. 256 threads, 8x8 per thread (as 8x4 f32x2 pairs).
#define GEMM_SMEM (2*16*256*4 + 2*16*132*4)   // As dup + Bs = 49664 B
template<int QUANT>
__global__ void __launch_bounds__(256) gemm128(const float* __restrict__ A,
                                               const float* __restrict__ B,
                                               const float* __restrict__ b0,
                                               const float* __restrict__ b1,
                                               const float* __restrict__ b2,
                                               float* __restrict__ C,
                                               float* __restrict__ Qd,
                                               float* __restrict__ Kd,
                                               float* __restrict__ Vd) {
    extern __shared__ float smemf[];
    float* As = smemf;                 // [2][16][256]  (m duplicated)
    float* Bs = smemf + 2*16*256;      // [2][16][132]
    int t = threadIdx.x;
    int m0 = blockIdx.y * 128;
    int n0 = blockIdx.x * 128;
    int w = t >> 5, lane = t & 31;
    int wm = w & 3, wn = w >> 2;       // warp tile: m 4 x n 2
    int lm = lane & 3, ln = lane >> 2; // lane tile
    int ar = t >> 2, ac4 = t & 3;

    ull acc2[8][4];
    #pragma unroll
    for (int i=0;i<8;i++) { acc2[i][0]=0ULL; acc2[i][1]=0ULL; acc2[i][2]=0ULL; acc2[i][3]=0ULL; }

    float4 pa0, pa1, pb0, pb1;
    #define GEMM_LDG(kt) do { \
        const float* Ap = A + (size_t)(m0+ar)*HIDDEN + (kt)*16 + ac4*4; \
        pa0 = *(const float4*)Ap; \
        pa1 = *(const float4*)(Ap + (size_t)64*HIDDEN); \
        const float* Bp = B + (size_t)(n0+ar)*HIDDEN + (kt)*16 + ac4*4; \
        pb0 = *(const float4*)Bp; \
        pb1 = *(const float4*)(Bp + (size_t)64*HIDDEN); \
    } while(0)
    #define GEMM_STS(buf) do { \
        float* Ab = As + (buf)*16*256; \
        float* Bb = Bs + (buf)*16*132; \
        *(float2*)&Ab[(ac4*4+0)*256 + 2*ar] = make_float2(pa0.x, pa0.x); \
        *(float2*)&Ab[(ac4*4+1)*256 + 2*ar] = make_float2(pa0.y, pa0.y); \
        *(float2*)&Ab[(ac4*4+2)*256 + 2*ar] = make_float2(pa0.z, pa0.z); \
        *(float2*)&Ab[(ac4*4+3)*256 + 2*ar] = make_float2(pa0.w, pa0.w); \
        *(float2*)&Ab[(ac4*4+0)*256 + 2*(ar+64)] = make_float2(pa1.x, pa1.x); \
        *(float2*)&Ab[(ac4*4+1)*256 + 2*(ar+64)] = make_float2(pa1.y, pa1.y); \
        *(float2*)&Ab[(ac4*4+2)*256 + 2*(ar+64)] = make_float2(pa1.z, pa1.z); \
        *(float2*)&Ab[(ac4*4+3)*256 + 2*(ar+64)] = make_float2(pa1.w, pa1.w); \
        Bb[(ac4*4+0)*132 + ar] = pb0.x; Bb[(ac4*4+1)*132 + ar] = pb0.y; \
        Bb[(ac4*4+2)*132 + ar] = pb0.z; Bb[(ac4*4+3)*132 + ar] = pb0.w; \
        Bb[(ac4*4+0)*132 + ar+64] = pb1.x; Bb[(ac4*4+1)*132 + ar+64] = pb1.y; \
        Bb[(ac4*4+2)*132 + ar+64] = pb1.z; Bb[(ac4*4+3)*132 + ar+64] = pb1.w; \
    } while(0)

    GEMM_LDG(0);
    GEMM_STS(0);
    __syncthreads();

    int aoff = 2*(wm*32 + lm*4);
    int boff = wn*64 + ln*4;
    for (int kt = 0; kt < 48; ++kt) {
        int buf = kt & 1;
        if (kt < 47) GEMM_LDG(kt+1);
        const float* Ab = As + buf*16*256;
        const float* Bb = Bs + buf*16*132;
        #pragma unroll
        for (int k = 0; k < 16; ++k) {     // ascending k; fused fma per output
            ulonglong2 aA = *(const ulonglong2*)&Ab[k*256 + aoff];
            ulonglong2 aB = *(const ulonglong2*)&Ab[k*256 + aoff + 4];
            ulonglong2 aC = *(const ulonglong2*)&Ab[k*256 + aoff + 32];
            ulonglong2 aD = *(const ulonglong2*)&Ab[k*256 + aoff + 36];
            ulonglong2 bL = *(const ulonglong2*)&Bb[k*132 + boff];
            ulonglong2 bH = *(const ulonglong2*)&Bb[k*132 + boff + 32];
            ull am[8] = {aA.x, aA.y, aB.x, aB.y, aC.x, aC.y, aD.x, aD.y};
            ull bn[4] = {bL.x, bL.y, bH.x, bH.y};
            #pragma unroll
            for (int i=0;i<8;i++) {
                acc2[i][0] = ffma2(am[i], bn[0], acc2[i][0]);
                acc2[i][1] = ffma2(am[i], bn[1], acc2[i][1]);
                acc2[i][2] = ffma2(am[i], bn[2], acc2[i][2]);
                acc2[i][3] = ffma2(am[i], bn[3], acc2[i][3]);
            }
        }
        if (kt < 47) {
            __syncthreads();
            GEMM_STS(buf ^ 1);
            __syncthreads();
        }
    }

    // ---------------- epilogue ----------------
    if (QUANT) {
        int nrel = n0 % 768;
        int tsel = n0 / 768;
        const float* bias = (tsel==0) ? b0 : (tsel==1 ? b1 : b2);
        float* dstbase = (tsel==0) ? Qd : (tsel==1 ? Kd : Vd);
        int hh = (nrel >> 6) + wn;
        int cb = nrel + wn*64 + ln*4;
        #pragma unroll
        for (int i=0;i<8;i++) {
            int gm = m0 + wm*32 + lm*4 + ((i<4) ? i : 12+i);
            float v[8]; float2 f;
            f = up2(acc2[i][0]); v[0]=f.x; v[1]=f.y;
            f = up2(acc2[i][1]); v[2]=f.x; v[3]=f.y;
            f = up2(acc2[i][2]); v[4]=f.x; v[5]=f.y;
            f = up2(acc2[i][3]); v[6]=f.x; v[7]=f.y;
            #pragma unroll
            for (int j=0;j<4;j++) v[j]   = __fadd_rn(v[j],   bias[cb+j]);
            #pragma unroll
            for (int j=0;j<4;j++) v[4+j] = __fadd_rn(v[4+j], bias[cb+32+j]);
            float mxv = fabsf(v[0]);
            #pragma unroll
            for (int j=1;j<8;j++) mxv = fmaxf(mxv, fabsf(v[j]));
            mxv = fmaxf(mxv, __shfl_xor_sync(0xffffffffu, mxv, 4));
            mxv = fmaxf(mxv, __shfl_xor_sync(0xffffffffu, mxv, 8));
            mxv = fmaxf(mxv, __shfl_xor_sync(0xffffffffu, mxv, 16));
            float sc = __fdiv_rn(mxv, 127.0f);
            if (sc == 0.0f) sc = 1.0f;
            float q[8];
            #pragma unroll
            for (int j=0;j<8;j++)
                q[j] = __fmul_rn(fminf(fmaxf(rintf(__fdiv_rn(v[j], sc)), -127.0f), 127.0f), sc);
            int b = gm >> 9, s = gm & 511;
            float* drow = dstbase + ((size_t)((b*NHEADS + hh)*SS + s))*HDIM;
            *(float4*)(drow + ln*4)      = make_float4(q[0],q[1],q[2],q[3]);
            *(float4*)(drow + 32 + ln*4) = make_float4(q[4],q[5],q[6],q[7]);
        }
    } else {
        int cb = n0 + wn*64 + ln*4;
        #pragma unroll
        for (int i=0;i<8;i++) {
            int gm = m0 + wm*32 + lm*4 + ((i<4) ? i : 12+i);
            float v[8]; float2 f;
            f = up2(acc2[i][0]); v[0]=f.x; v[1]=f.y;
            f = up2(acc2[i][1]); v[2]=f.x; v[3]=f.y;
            f = up2(acc2[i][2]); v[4]=f.x; v[5]=f.y;
            f = up2(acc2[i][3]); v[6]=f.x; v[7]=f.y;
            #pragma unroll
            for (int j=0;j<4;j++) v[j]   = __fadd_rn(v[j],   b0[cb+j]);
            #pragma unroll
            for (int j=0;j<4;j++) v[4+j] = __fadd_rn(v[4+j], b0[cb+32+j]);
            float* crow = C + (size_t)gm*768;
            *(float4*)(crow + cb)      = make_float4(v[0],v[1],v[2],v[3]);
            *(float4*)(crow + cb + 32) = make_float4(v[4],v[5],v[6],v[7]);
        }
    }
}

// ---------------- attention phase A: scores + PLA softmax (strict-seq sum, 4-way batched) ----------------
// grid (96, 8): CTA = (b,h) x 64 q-rows; 8 warps x 8 rows (two batches of 4).
#define SMEM_A (512*68*4 + 8*64*4 + 8*4*512*4)   // 206848
__global__ void __launch_bounds__(256,1) attnA(PLA pla) {
    extern __shared__ char smem[];
    float* Ks   = (float*)smem;                          // [512][68]
    float* qs   = (float*)(smem + 512*68*4);             // [8][64]
    float* ebuf = (float*)(smem + 512*68*4 + 8*64*4);    // [8 warps][4 rows][512]
    int t = threadIdx.x;
    int w = t >> 5, lane = t & 31;
    int bh = blockIdx.x;

    const float* Kg = g_Kd + (size_t)bh*SS*HDIM;
    for (int i = t; i < SS*HDIM; i += 256) {
        int k = i >> 6, d = i & 63;
        Ks[k*68 + d] = Kg[i];
    }
    __syncthreads();

    int rowbase = blockIdx.y*64 + w*8;
    float* q = qs + w*64;
    float* eb = ebuf + w*4*512;

    for (int batch = 0; batch < 2; ++batch) {
        // phase 1: dots + exps for 4 rows
        for (int r4 = 0; r4 < 4; ++r4) {
            int srow = rowbase + batch*4 + r4;
            const float* Qg = g_Qd + ((size_t)bh*SS + srow)*HDIM;
            q[lane] = Qg[lane];
            q[lane+32] = Qg[lane+32];
            __syncwarp();
            float sc[16];
            #pragma unroll
            for (int j=0;j<16;j++) sc[j] = 0.0f;
            #pragma unroll
            for (int d4 = 0; d4 < 16; ++d4) {    // ascending d, fused fma per score
                float4 qv = *(const float4*)&q[d4*4];
                #pragma unroll
                for (int j = 0; j < 16; j++) {
                    int kk = lane + 32*j;
                    float4 kv = *(const float4*)&Ks[kk*68 + d4*4];
                    sc[j] = fmaf(qv.x, kv.x, sc[j]);
                    sc[j] = fmaf(qv.y, kv.y, sc[j]);
                    sc[j] = fmaf(qv.z, kv.z, sc[j]);
                    sc[j] = fmaf(qv.w, kv.w, sc[j]);
                }
            }
            #pragma unroll
            for (int j=0;j<16;j++) sc[j] = __fmul_rn(sc[j], 0.125f);
            float mx = sc[0];
            #pragma unroll
            for (int j=1;j<16;j++) mx = fmaxf(mx, sc[j]);
            #pragma unroll
            for (int o=16;o>0;o>>=1) mx = fmaxf(mx, __shfl_xor_sync(0xffffffffu, mx, o));
            float* er = eb + r4*512;
            #pragma unroll
            for (int j = 0; j < 16; j++) {
                float sh = __fadd_rn(sc[j], -mx);
                float fr = rintf(__fmul_rn(sh, 67108864.0f));
                fr = fminf(fmaxf(fr, -2147483648.0f), 2147483648.0f);
                float fx = __fmul_rn(fr, 1.4901161193847656e-8f); // * 2^-26
                float xc = fminf(fmaxf(fx, -10.0f), 0.0f);
                int cnt = 0;
                #pragma unroll
                for (int i = 0; i < 13; i++) cnt += (xc >= pla.iv[i]) ? 1 : 0;
                int idx = cnt - 1; if (idx < 0) idx = 0; if (idx > 11) idx = 11;
                float e = __fadd_rn(__fmul_rn(pla.m[idx], xc), pla.c[idx]);
                er[lane + 32*j] = e;
            }
            __syncwarp();
        }
        // phase 2: strict in-order sums, 4 rows in parallel on lanes 0-3
        float ssum = 0.0f;
        if (lane < 4) {
            const float* er = eb + lane*512;
            #pragma unroll 8
            for (int i = 0; i < 512; i++) ssum = __fadd_rn(ssum, er[i]);
        }
        __syncwarp();
        // phase 3: normalize + quantize + write
        for (int r4 = 0; r4 < 4; ++r4) {
            int srow = rowbase + batch*4 + r4;
            float denom = __fadd_rn(__shfl_sync(0xffffffffu, ssum, r4), 1e-9f);
            const float* er = eb + r4*512;
            float sc[16];
            float qmx = 0.0f;
            #pragma unroll
            for (int j = 0; j < 16; j++) {
                float smv = __fdiv_rn(er[lane + 32*j], denom);
                sc[j] = smv;
                qmx = fmaxf(qmx, fabsf(smv));
            }
            #pragma unroll
            for (int o=16;o>0;o>>=1) qmx = fmaxf(qmx, __shfl_xor_sync(0xffffffffu, qmx, o));
            float sp = __fdiv_rn(qmx, 127.0f);
            if (sp == 0.0f) sp = 1.0f;
            float* prow = g_P + ((size_t)bh*SS + srow)*SS;
            #pragma unroll
            for (int j = 0; j < 16; j++) {
                float r = fminf(fmaxf(rintf(__fdiv_rn(sc[j], sp)), -127.0f), 127.0f);
                prow[lane + 32*j] = __fmul_rn(r, sp);
            }
        }
        __syncwarp();
    }
}

// ---------------- attention phase B: ctx = P @ Vd (ascending-k fused fma) ----------------
#define SMEM_B (512*68*4 + 128*33*4)
__global__ void __launch_bounds__(256,1) attnB() {
    extern __shared__ char smem[];
    float* Vs = (float*)smem;                   // [512][68]
    float* Ps = (float*)(smem + 512*68*4);      // [128][33]
    int t = threadIdx.x;
    int bh = blockIdx.x;
    int m0 = blockIdx.y * 128;
    int tx = t & 15;     // d group (tx*4)
    int ty = t >> 4;     // m group (ty*8)

    const float* Vg = g_Vd + (size_t)bh*SS*HDIM;
    for (int i = t; i < SS*HDIM; i += 256) {
        int k = i >> 6, d = i & 63;
        Vs[k*68 + d] = Vg[i];
    }
    __syncthreads();

    float acc[8][4];
    #pragma unroll
    for (int i=0;i<8;i++){acc[i][0]=0;acc[i][1]=0;acc[i][2]=0;acc[i][3]=0;}

    const float* Pg = g_P + ((size_t)bh*SS + m0)*SS;
    for (int kt = 0; kt < 16; ++kt) {
        #pragma unroll
        for (int l=0;l<4;l++) {
            int lin = t + l*256;
            int m = lin >> 3;
            int k4 = lin & 7;
            float4 v = *(const float4*)(Pg + (size_t)m*SS + kt*32 + k4*4);
            Ps[m*33 + k4*4+0]=v.x; Ps[m*33 + k4*4+1]=v.y;
            Ps[m*33 + k4*4+2]=v.z; Ps[m*33 + k4*4+3]=v.w;
        }
        __syncthreads();
        #pragma unroll 8
        for (int kk = 0; kk < 32; ++kk) {
            float4 vv = *(const float4*)&Vs[(kt*32+kk)*68 + tx*4];
            #pragma unroll
            for (int i=0;i<8;i++) {
                float p = Ps[(ty*8+i)*33 + kk];
                acc[i][0] = fmaf(p, vv.x, acc[i][0]);
                acc[i][1] = fmaf(p, vv.y, acc[i][1]);
                acc[i][2] = fmaf(p, vv.z, acc[i][2]);
                acc[i][3] = fmaf(p, vv.w, acc[i][3]);
            }
        }
        __syncthreads();
    }
    int b = bh / NHEADS, h = bh % NHEADS;
    #pragma unroll
    for (int i=0;i<8;i++) {
        int s = m0 + ty*8 + i;
        *(float4*)(g_CTX + ((size_t)(b*SS + s))*HIDDEN + h*HDIM + tx*4) = *(float4*)&acc[i][0];
    }
}

// ---------------- host: replicate np.polyfit coefficients in double ----------------
static void build_pla(PLA& p) {
    double xs[1001], ys[1001];
    double step = 10.0 / 1000.0;
    for (int j = 0; j <= 1000; j++) xs[j] = -10.0 + (double)j * step;
    xs[1000] = 0.0;
    for (int j = 0; j <= 1000; j++) ys[j] = exp(xs[j]);
    double iv[13];
    double st2 = 10.0 / 12.0;
    for (int i = 0; i < 13; i++) iv[i] = -10.0 + (double)i * st2;
    iv[12] = 0.0;
    for (int i = 0; i < 12; i++) {
        double a = iv[i], b = iv[i+1];
        double n = 0, Sx = 0, Sy = 0, Sxx = 0, Sxy = 0;
        for (int j = 0; j <= 1000; j++) {
            if (xs[j] >= a && xs[j] <= b) {
                n += 1.0; Sx += xs[j]; Sy += ys[j];
                Sxx += xs[j]*xs[j]; Sxy += xs[j]*ys[j];
            }
        }
        double m = (n*Sxy - Sx*Sy) / (n*Sxx - Sx*Sx);
        double c = (Sy - m*Sx) / n;
        p.m[i] = (float)m;
        p.c[i] = (float)c;
    }
    for (int i = 0; i < 13; i++) p.iv[i] = (float)iv[i];
}

extern "C" void kernel_launch(void* const* d_in, const int* in_sizes, int n_in,
                              void* d_out, int out_size) {
    (void)in_sizes; (void)n_in; (void)out_size;
    const float* hs = (const float*)d_in[0];
    const float* Wq = (const float*)d_in[1];
    const float* bq = (const float*)d_in[2];
    const float* Wk = (const float*)d_in[3];
    const float* bk = (const float*)d_in[4];
    const float* Wv = (const float*)d_in[5];
    const float* bv = (const float*)d_in[6];
    const float* Wo = (const float*)d_in[7];
    const float* bo = (const float*)d_in[8];

    void *pXd, *pWd, *pWod, *pCTX, *pCd, *pQd, *pKd, *pVd;
    cudaGetSymbolAddress(&pXd, g_Xd);
    cudaGetSymbolAddress(&pWd, g_Wd);
    cudaGetSymbolAddress(&pWod, g_Wod);
    cudaGetSymbolAddress(&pCTX, g_CTX);
    cudaGetSymbolAddress(&pCd, g_Cd);
    cudaGetSymbolAddress(&pQd, g_Qd);
    cudaGetSymbolAddress(&pKd, g_Kd);
    cudaGetSymbolAddress(&pVd, g_Vd);

    PLA pla;
    build_pla(pla);

    // 1) fake-quant (dequantized fp32) activations + all weights, one launch
    rowquant_all<<<7168, 256>>>(hs, Wq, Wk, Wv, Wo,
                                (float*)pXd, (float*)pWd, (float*)pWod);

    // 2) fused QKV projection + per-head quantize epilogue -> Qd/Kd/Vd
    cudaFuncSetAttribute(gemm128<1>, cudaFuncAttributeMaxDynamicSharedMemorySize, GEMM_SMEM);
    gemm128<1><<<dim3(18, 32), 256, GEMM_SMEM>>>((const float*)pXd, (const float*)pWd,
                                                 bq, bk, bv, nullptr,
                                                 (float*)pQd, (float*)pKd, (float*)pVd);

    // 3) attention: scores + PLA softmax + prob quant, then P@V
    cudaFuncSetAttribute(attnA, cudaFuncAttributeMaxDynamicSharedMemorySize, SMEM_A);
    attnA<<<dim3(BB*NHEADS, 8), 256, SMEM_A>>>(pla);
    cudaFuncSetAttribute(attnB, cudaFuncAttributeMaxDynamicSharedMemorySize, SMEM_B);
    attnB<<<dim3(BB*NHEADS, 4), 256, SMEM_B>>>();

    // 4) fake-quant ctx rows + output projection
    rowquant_dq<<<ROWS, 256>>>((const float*)pCTX, (float*)pCd);
    cudaFuncSetAttribute(gemm128<0>, cudaFuncAttributeMaxDynamicSharedMemorySize, GEMM_SMEM);
    gemm128<0><<<dim3(6, 32), 256, GEMM_SMEM>>>((const float*)pCd, (const float*)pWod,
                                                bo, nullptr, nullptr, (float*)d_out,
                                                nullptr, nullptr, nullptr);
}

// round 5
// speedup vs baseline: 1.2883x; 1.2721x over previous
#include <cuda_runtime.h>
#include <cstdint>
#include <cmath>

#define HIDDEN 768
#define NHEADS 12
#define HDIM 64
#define BB 8
#define SS 512
#define ROWS (BB*SS)              // 4096
#define HEADROWS (BB*NHEADS*SS)   // 49152

// ---------------- scratch (static device allocations; no cudaMalloc) ----------------
__device__ float g_Xd[(size_t)ROWS*HIDDEN];        // dequant hidden_states
__device__ float g_Wd[(size_t)3*HIDDEN*HIDDEN];    // dequant Wq|Wk|Wv
__device__ float g_Wod[(size_t)HIDDEN*HIDDEN];     // dequant Wo
__device__ float g_Qd[(size_t)HEADROWS*HDIM];      // dequant per-head q
__device__ float g_Kd[(size_t)HEADROWS*HDIM];
__device__ float g_Vd[(size_t)HEADROWS*HDIM];
__device__ float g_P [(size_t)HEADROWS*SS];        // dequant quantized probs
__device__ float g_CTX[(size_t)ROWS*HIDDEN];
__device__ float g_Cd[(size_t)ROWS*HIDDEN];        // dequant quantized ctx

struct PLA { float m[12]; float c[12]; float iv[13]; };

typedef unsigned long long ull;

// packed f32x2 FMA: two independent IEEE RN fmas in one instruction (FFMA2)
__device__ __forceinline__ ull ffma2(ull a, ull b, ull c) {
    ull d;
    asm("fma.rn.f32x2 %0, %1, %2, %3;" : "=l"(d) : "l"(a), "l"(b), "l"(c));
    return d;
}
__device__ __forceinline__ float2 up2(ull v) {
    float2 r;
    asm("mov.b64 {%0, %1}, %2;" : "=f"(r.x), "=f"(r.y) : "l"(v));
    return r;
}
__device__ __forceinline__ ull dup2(float x) {
    ull d;
    asm("mov.b64 %0, {%1, %1};" : "=l"(d) : "f"(x));
    return d;
}

// ---------------- per-row (768) symmetric int8 fake-quant -> dequant fp32 ----------------
__device__ __forceinline__ void rowquant_body(const float* __restrict__ x,
                                              float* __restrict__ d) {
    int t = threadIdx.x;
    float v0 = x[t], v1 = x[t+256], v2 = x[t+512];
    float loc = fmaxf(fabsf(v0), fmaxf(fabsf(v1), fabsf(v2)));
    #pragma unroll
    for (int o=16;o>0;o>>=1) loc = fmaxf(loc, __shfl_xor_sync(0xffffffffu, loc, o));
    __shared__ float wm[8];
    __shared__ float s_scale;
    if ((t&31)==0) wm[t>>5]=loc;
    __syncthreads();
    if (t==0) {
        float m = wm[0];
        #pragma unroll
        for (int i=1;i<8;i++) m = fmaxf(m, wm[i]);
        float sc = __fdiv_rn(m, 127.0f);
        if (sc == 0.0f) sc = 1.0f;
        s_scale = sc;
    }
    __syncthreads();
    float sc = s_scale;
    float r0 = fminf(fmaxf(rintf(__fdiv_rn(v0, sc)), -127.0f), 127.0f);
    float r1 = fminf(fmaxf(rintf(__fdiv_rn(v1, sc)), -127.0f), 127.0f);
    float r2 = fminf(fmaxf(rintf(__fdiv_rn(v2, sc)), -127.0f), 127.0f);
    d[t]     = __fmul_rn(r0, sc);
    d[t+256] = __fmul_rn(r1, sc);
    d[t+512] = __fmul_rn(r2, sc);
}

__global__ void rowquant_dq(const float* __restrict__ src, float* __restrict__ dst) {
    int row = blockIdx.x;
    rowquant_body(src + (size_t)row*HIDDEN, dst + (size_t)row*HIDDEN);
}

// merged: X (4096 rows) + Wq + Wk + Wv + Wo (768 each)
__global__ void rowquant_all(const float* __restrict__ x,
                             const float* __restrict__ wq, const float* __restrict__ wk,
                             const float* __restrict__ wv, const float* __restrict__ wo,
                             float* __restrict__ xd, float* __restrict__ wd,
                             float* __restrict__ wod) {
    int row = blockIdx.x;
    const float* src; float* dst; int r;
    if (row < 4096)      { r = row;      src = x;  dst = xd; }
    else if (row < 4864) { r = row-4096; src = wq; dst = wd; }
    else if (row < 5632) { r = row-4864; src = wk; dst = wd + (size_t)HIDDEN*HIDDEN; }
    else if (row < 6400) { r = row-5632; src = wv; dst = wd + (size_t)2*HIDDEN*HIDDEN; }
    else                 { r = row-6400; src = wo; dst = wod; }
    rowquant_body(src + (size_t)r*HIDDEN, dst + (size_t)r*HIDDEN);
}

// ---------------- fp32 GEMM 128x128: m-pair FFMA2, plain smem, double-buffered ----------------
// C[m,n] = fused ascending-k fma of A[m,:].B[n,:] (+ bias).
// QUANT=1: fused per-head (64) quantize epilogue -> Qd/Kd/Vd.
#define GPAD 136
template<int QUANT>
__global__ void __launch_bounds__(256) gemm2(const float* __restrict__ A,
                                             const float* __restrict__ B,
                                             const float* __restrict__ b0,
                                             const float* __restrict__ b1,
                                             const float* __restrict__ b2,
                                             float* __restrict__ C,
                                             float* __restrict__ Qd,
                                             float* __restrict__ Kd,
                                             float* __restrict__ Vd) {
    __shared__ __align__(16) float As[2*16*GPAD];
    __shared__ __align__(16) float Bs[2*16*GPAD];
    int t = threadIdx.x;
    int m0 = blockIdx.y * 128;
    int n0 = blockIdx.x * 128;
    int w = t >> 5, lane = t & 31;
    int wm = w & 3, wn = w >> 2;       // warp tile: 32m x 64n
    int lm = lane & 3, ln = lane >> 2; // lane tile: 8m x 8n
    int ar = t >> 2, ac4 = t & 3;

    ull acc2[4][8];
    #pragma unroll
    for (int p=0;p<4;p++)
        #pragma unroll
        for (int j=0;j<8;j++) acc2[p][j]=0ULL;

    float4 pa0, pa1, pb0, pb1;
    #define G_LDG(kt) do { \
        const float* Ap = A + (size_t)(m0+ar)*HIDDEN + (kt)*16 + ac4*4; \
        pa0 = *(const float4*)Ap; \
        pa1 = *(const float4*)(Ap + (size_t)64*HIDDEN); \
        const float* Bp = B + (size_t)(n0+ar)*HIDDEN + (kt)*16 + ac4*4; \
        pb0 = *(const float4*)Bp; \
        pb1 = *(const float4*)(Bp + (size_t)64*HIDDEN); \
    } while(0)
    #define G_STS(buf) do { \
        float* Ab = As + (buf)*16*GPAD; \
        float* Bb = Bs + (buf)*16*GPAD; \
        Ab[(ac4*4+0)*GPAD + ar] = pa0.x; Ab[(ac4*4+1)*GPAD + ar] = pa0.y; \
        Ab[(ac4*4+2)*GPAD + ar] = pa0.z; Ab[(ac4*4+3)*GPAD + ar] = pa0.w; \
        Ab[(ac4*4+0)*GPAD + ar+64] = pa1.x; Ab[(ac4*4+1)*GPAD + ar+64] = pa1.y; \
        Ab[(ac4*4+2)*GPAD + ar+64] = pa1.z; Ab[(ac4*4+3)*GPAD + ar+64] = pa1.w; \
        Bb[(ac4*4+0)*GPAD + ar] = pb0.x; Bb[(ac4*4+1)*GPAD + ar] = pb0.y; \
        Bb[(ac4*4+2)*GPAD + ar] = pb0.z; Bb[(ac4*4+3)*GPAD + ar] = pb0.w; \
        Bb[(ac4*4+0)*GPAD + ar+64] = pb1.x; Bb[(ac4*4+1)*GPAD + ar+64] = pb1.y; \
        Bb[(ac4*4+2)*GPAD + ar+64] = pb1.z; Bb[(ac4*4+3)*GPAD + ar+64] = pb1.w; \
    } while(0)

    G_LDG(0);
    G_STS(0);
    __syncthreads();

    int aull = wm*16 + lm*4;           // ull offset of 8-m group within A row
    int boff = wn*64 + ln*8;
    for (int kt = 0; kt < 48; ++kt) {
        int buf = kt & 1;
        if (kt < 47) G_LDG(kt+1);
        const float* Ab = As + buf*16*GPAD;
        const float* Bb = Bs + buf*16*GPAD;
        #pragma unroll
        for (int k = 0; k < 16; ++k) {     // ascending k; fused fma per output
            const ull* Arow = (const ull*)(Ab + k*GPAD);
            ulonglong2 aA = *(const ulonglong2*)&Arow[aull];
            ulonglong2 aB = *(const ulonglong2*)&Arow[aull+2];
            ull am[4] = {aA.x, aA.y, aB.x, aB.y};
            const float* Brow = Bb + k*GPAD + boff;
            float4 bl = *(const float4*)Brow;
            float4 bh = *(const float4*)(Brow+4);
            ull bd[8];
            bd[0]=dup2(bl.x); bd[1]=dup2(bl.y); bd[2]=dup2(bl.z); bd[3]=dup2(bl.w);
            bd[4]=dup2(bh.x); bd[5]=dup2(bh.y); bd[6]=dup2(bh.z); bd[7]=dup2(bh.w);
            #pragma unroll
            for (int p=0;p<4;p++)
                #pragma unroll
                for (int j=0;j<8;j++)
                    acc2[p][j] = ffma2(am[p], bd[j], acc2[p][j]);
        }
        if (kt < 47) {
            __syncthreads();
            G_STS(buf ^ 1);
            __syncthreads();
        }
    }

    // ---------------- epilogue: each ull pair = rows (2p, 2p+1) ----------------
    if (QUANT) {
        int nrel = n0 % 768;
        int tsel = n0 / 768;
        const float* bias = (tsel==0) ? b0 : (tsel==1 ? b1 : b2);
        float* dstbase = (tsel==0) ? Qd : (tsel==1 ? Kd : Vd);
        int hh = (nrel >> 6) + wn;
        int cb = nrel + wn*64 + ln*8;
        #pragma unroll
        for (int p=0;p<4;p++) {
            float ve[8], vo[8];
            #pragma unroll
            for (int j=0;j<8;j++) {
                float2 f = up2(acc2[p][j]);
                ve[j] = __fadd_rn(f.x, bias[cb+j]);
                vo[j] = __fadd_rn(f.y, bias[cb+j]);
            }
            #pragma unroll
            for (int half=0; half<2; ++half) {
                float* v = half ? vo : ve;
                int gm = m0 + wm*32 + lm*8 + 2*p + half;
                float mxv = fabsf(v[0]);
                #pragma unroll
                for (int j=1;j<8;j++) mxv = fmaxf(mxv, fabsf(v[j]));
                mxv = fmaxf(mxv, __shfl_xor_sync(0xffffffffu, mxv, 4));
                mxv = fmaxf(mxv, __shfl_xor_sync(0xffffffffu, mxv, 8));
                mxv = fmaxf(mxv, __shfl_xor_sync(0xffffffffu, mxv, 16));
                float sc = __fdiv_rn(mxv, 127.0f);
                if (sc == 0.0f) sc = 1.0f;
                float q[8];
                #pragma unroll
                for (int j=0;j<8;j++)
                    q[j] = __fmul_rn(fminf(fmaxf(rintf(__fdiv_rn(v[j], sc)), -127.0f), 127.0f), sc);
                int b = gm >> 9, s = gm & 511;
                float* drow = dstbase + ((size_t)((b*NHEADS + hh)*SS + s))*HDIM + ln*8;
                *(float4*)drow       = make_float4(q[0],q[1],q[2],q[3]);
                *(float4*)(drow + 4) = make_float4(q[4],q[5],q[6],q[7]);
            }
        }
    } else {
        int cb = n0 + wn*64 + ln*8;
        #pragma unroll
        for (int p=0;p<4;p++) {
            float ve[8], vo[8];
            #pragma unroll
            for (int j=0;j<8;j++) {
                float2 f = up2(acc2[p][j]);
                ve[j] = __fadd_rn(f.x, b0[cb+j]);
                vo[j] = __fadd_rn(f.y, b0[cb+j]);
            }
            int gm = m0 + wm*32 + lm*8 + 2*p;
            float* ce = C + (size_t)gm*768 + cb;
            float* co = C + (size_t)(gm+1)*768 + cb;
            *(float4*)ce     = make_float4(ve[0],ve[1],ve[2],ve[3]);
            *(float4*)(ce+4) = make_float4(ve[4],ve[5],ve[6],ve[7]);
            *(float4*)co     = make_float4(vo[0],vo[1],vo[2],vo[3]);
            *(float4*)(co+4) = make_float4(vo[4],vo[5],vo[6],vo[7]);
        }
    }
}

// ---------------- attention phase A: FFMA2 scores (K^T smem) + PLA softmax + prob quant ----------------
// grid (96, 8): CTA = (b,h) x 64 q-rows; 8 warps x 8 rows (two batches of 4).
// KsT [64][520], qsT [8w][64][8], ebuf [8w][4][512]
#define SMEM_A (64*520*4 + 8*64*8*4 + 8*4*512*4)   // 215040
__global__ void __launch_bounds__(256,1) attnA(PLA pla) {
    extern __shared__ char smem[];
    float* KsT  = (float*)smem;                          // [64][520]
    float* qsT  = (float*)(smem + 64*520*4);             // [8][64][8]
    float* ebuf = (float*)(smem + 64*520*4 + 8*64*8*4);  // [8][4][512]
    int t = threadIdx.x;
    int w = t >> 5, lane = t & 31;
    int bh = blockIdx.x;

    const float* Kg = g_Kd + (size_t)bh*SS*HDIM;
    for (int i = t; i < SS*HDIM; i += 256) {
        int k = i >> 6, d = i & 63;
        KsT[d*520 + k] = Kg[i];
    }
    __syncthreads();

    int rowbase = blockIdx.y*64 + w*8;
    float* qw = qsT + w*512;           // [64][8]
    float* eb = ebuf + w*4*512;        // [4][512]
    const ull* Ku = (const ull*)KsT;   // row d: 260 ulls, pairs 0..255 valid

    for (int batch = 0; batch < 2; ++batch) {
        // phase 0: stage q for 4 rows (d-major)
        #pragma unroll
        for (int r = 0; r < 4; ++r) {
            const float* Qg = g_Qd + ((size_t)bh*SS + rowbase + batch*4 + r)*HDIM;
            qw[lane*8 + r]      = Qg[lane];
            qw[(lane+32)*8 + r] = Qg[lane+32];
        }
        __syncwarp();

        // phase 1: dots — 4 rows x 8 k-pairs per lane, ascending-d fused FFMA2
        ull acc2[4][8];
        #pragma unroll
        for (int r=0;r<4;r++)
            #pragma unroll
            for (int j=0;j<8;j++) acc2[r][j]=0ULL;
        #pragma unroll 4
        for (int d = 0; d < 64; ++d) {
            ull qd[4];
            qd[0] = dup2(qw[d*8+0]); qd[1] = dup2(qw[d*8+1]);
            qd[2] = dup2(qw[d*8+2]); qd[3] = dup2(qw[d*8+3]);
            const ull* Kr = Ku + d*260;
            #pragma unroll
            for (int j = 0; j < 8; ++j) {
                ull kp = Kr[lane + 32*j];
                acc2[0][j] = ffma2(qd[0], kp, acc2[0][j]);
                acc2[1][j] = ffma2(qd[1], kp, acc2[1][j]);
                acc2[2][j] = ffma2(qd[2], kp, acc2[2][j]);
                acc2[3][j] = ffma2(qd[3], kp, acc2[3][j]);
            }
        }

        // per-row: scale, max, PLA exp, stash
        for (int r = 0; r < 4; ++r) {
            float sc[16];
            #pragma unroll
            for (int j=0;j<8;j++) {
                float2 f = up2(acc2[r][j]);
                sc[2*j]   = __fmul_rn(f.x, 0.125f);
                sc[2*j+1] = __fmul_rn(f.y, 0.125f);
            }
            float mx = sc[0];
            #pragma unroll
            for (int j=1;j<16;j++) mx = fmaxf(mx, sc[j]);
            #pragma unroll
            for (int o=16;o>0;o>>=1) mx = fmaxf(mx, __shfl_xor_sync(0xffffffffu, mx, o));
            float* er = eb + r*512;
            #pragma unroll
            for (int j = 0; j < 8; j++) {
                float e2[2];
                #pragma unroll
                for (int u = 0; u < 2; ++u) {
                    float sh = __fadd_rn(sc[2*j+u], -mx);
                    float fr = rintf(__fmul_rn(sh, 67108864.0f));
                    fr = fminf(fmaxf(fr, -2147483648.0f), 2147483648.0f);
                    float fx = __fmul_rn(fr, 1.4901161193847656e-8f); // * 2^-26
                    float xc = fminf(fmaxf(fx, -10.0f), 0.0f);
                    int cnt = 0;
                    #pragma unroll
                    for (int i = 0; i < 13; i++) cnt += (xc >= pla.iv[i]) ? 1 : 0;
                    int idx = cnt - 1; if (idx < 0) idx = 0; if (idx > 11) idx = 11;
                    e2[u] = __fadd_rn(__fmul_rn(pla.m[idx], xc), pla.c[idx]);
                }
                *(float2*)&er[2*(lane + 32*j)] = make_float2(e2[0], e2[1]);
            }
            __syncwarp();
        }
        // phase 2: strict in-order sums, 4 rows on lanes 0-3
        float ssum = 0.0f;
        if (lane < 4) {
            const float* er = eb + lane*512;
            #pragma unroll 8
            for (int i = 0; i < 512; i++) ssum = __fadd_rn(ssum, er[i]);
        }
        __syncwarp();
        // phase 3: normalize + quantize + write
        for (int r = 0; r < 4; ++r) {
            int srow = rowbase + batch*4 + r;
            float denom = __fadd_rn(__shfl_sync(0xffffffffu, ssum, r), 1e-9f);
            const float* er = eb + r*512;
            float sc[16];
            float qmx = 0.0f;
            #pragma unroll
            for (int j = 0; j < 16; j++) {
                float smv = __fdiv_rn(er[lane + 32*j], denom);
                sc[j] = smv;
                qmx = fmaxf(qmx, fabsf(smv));
            }
            #pragma unroll
            for (int o=16;o>0;o>>=1) qmx = fmaxf(qmx, __shfl_xor_sync(0xffffffffu, qmx, o));
            float sp = __fdiv_rn(qmx, 127.0f);
            if (sp == 0.0f) sp = 1.0f;
            float* prow = g_P + ((size_t)bh*SS + srow)*SS;
            #pragma unroll
            for (int j = 0; j < 16; j++) {
                float rq = fminf(fmaxf(rintf(__fdiv_rn(sc[j], sp)), -127.0f), 127.0f);
                prow[lane + 32*j] = __fmul_rn(rq, sp);
            }
        }
        __syncwarp();
    }
}

// ---------------- attention phase B: ctx = P @ Vd, FFMA2 d-pairs, P direct from gmem ----------------
// grid (96, 4): CTA = (b,h) x 128 q-rows. 256 threads: tx(8)=8d, ty(32)=4m.
#define SMEM_B (512*64*4)
__global__ void __launch_bounds__(256,1) attnB() {
    extern __shared__ float Vs[];       // [512][64]
    int t = threadIdx.x;
    int tx = t & 7, ty = t >> 3;
    int bh = blockIdx.x;
    int m0 = blockIdx.y * 128;

    const float* Vg = g_Vd + (size_t)bh*SS*HDIM;
    for (int i = t*4; i < SS*HDIM; i += 1024)
        *(float4*)&Vs[i] = *(const float4*)&Vg[i];
    __syncthreads();

    ull acc2[4][4];
    #pragma unroll
    for (int i=0;i<4;i++)
        #pragma unroll
        for (int u=0;u<4;u++) acc2[i][u]=0ULL;

    const float* Pg = g_P + ((size_t)bh*SS + m0 + ty*4)*SS;
    const ull* Vu = (const ull*)Vs;
    #pragma unroll 2
    for (int kb = 0; kb < 128; ++kb) {
        float pa[4][4];
        #pragma unroll
        for (int i=0;i<4;i++)
            *(float4*)pa[i] = *(const float4*)&Pg[(size_t)i*SS + kb*4];
        #pragma unroll
        for (int kk = 0; kk < 4; ++kk) {        // ascending k, fused fma per output
            int k = kb*4 + kk;
            ulonglong2 v0 = *(const ulonglong2*)&Vu[k*32 + tx*4];
            ulonglong2 v1 = *(const ulonglong2*)&Vu[k*32 + tx*4 + 2];
            ull vp[4] = {v0.x, v0.y, v1.x, v1.y};
            #pragma unroll
            for (int i=0;i<4;i++) {
                ull pd = dup2(pa[i][kk]);
                acc2[i][0] = ffma2(pd, vp[0], acc2[i][0]);
                acc2[i][1] = ffma2(pd, vp[1], acc2[i][1]);
                acc2[i][2] = ffma2(pd, vp[2], acc2[i][2]);
                acc2[i][3] = ffma2(pd, vp[3], acc2[i][3]);
            }
        }
    }
    int b = bh / NHEADS, h = bh % NHEADS;
    #pragma unroll
    for (int i=0;i<4;i++) {
        int s = m0 + ty*4 + i;
        float* Co = g_CTX + ((size_t)(b*SS + s))*HIDDEN + h*HDIM + tx*8;
        float2 f0 = up2(acc2[i][0]), f1 = up2(acc2[i][1]);
        float2 f2 = up2(acc2[i][2]), f3 = up2(acc2[i][3]);
        *(float4*)Co     = make_float4(f0.x, f0.y, f1.x, f1.y);
        *(float4*)(Co+4) = make_float4(f2.x, f2.y, f3.x, f3.y);
    }
}

// ---------------- host: replicate np.polyfit coefficients in double ----------------
static void build_pla(PLA& p) {
    double xs[1001], ys[1001];
    double step = 10.0 / 1000.0;
    for (int j = 0; j <= 1000; j++) xs[j] = -10.0 + (double)j * step;
    xs[1000] = 0.0;
    for (int j = 0; j <= 1000; j++) ys[j] = exp(xs[j]);
    double iv[13];
    double st2 = 10.0 / 12.0;
    for (int i = 0; i < 13; i++) iv[i] = -10.0 + (double)i * st2;
    iv[12] = 0.0;
    for (int i = 0; i < 12; i++) {
        double a = iv[i], b = iv[i+1];
        double n = 0, Sx = 0, Sy = 0, Sxx = 0, Sxy = 0;
        for (int j = 0; j <= 1000; j++) {
            if (xs[j] >= a && xs[j] <= b) {
                n += 1.0; Sx += xs[j]; Sy += ys[j];
                Sxx += xs[j]*xs[j]; Sxy += xs[j]*ys[j];
            }
        }
        double m = (n*Sxy - Sx*Sy) / (n*Sxx - Sx*Sx);
        double c = (Sy - m*Sx) / n;
        p.m[i] = (float)m;
        p.c[i] = (float)c;
    }
    for (int i = 0; i < 13; i++) p.iv[i] = (float)iv[i];
}

extern "C" void kernel_launch(void* const* d_in, const int* in_sizes, int n_in,
                              void* d_out, int out_size) {
    (void)in_sizes; (void)n_in; (void)out_size;
    const float* hs = (const float*)d_in[0];
    const float* Wq = (const float*)d_in[1];
    const float* bq = (const float*)d_in[2];
    const float* Wk = (const float*)d_in[3];
    const float* bk = (const float*)d_in[4];
    const float* Wv = (const float*)d_in[5];
    const float* bv = (const float*)d_in[6];
    const float* Wo = (const float*)d_in[7];
    const float* bo = (const float*)d_in[8];

    void *pXd, *pWd, *pWod, *pCTX, *pCd, *pQd, *pKd, *pVd;
    cudaGetSymbolAddress(&pXd, g_Xd);
    cudaGetSymbolAddress(&pWd, g_Wd);
    cudaGetSymbolAddress(&pWod, g_Wod);
    cudaGetSymbolAddress(&pCTX, g_CTX);
    cudaGetSymbolAddress(&pCd, g_Cd);
    cudaGetSymbolAddress(&pQd, g_Qd);
    cudaGetSymbolAddress(&pKd, g_Kd);
    cudaGetSymbolAddress(&pVd, g_Vd);

    PLA pla;
    build_pla(pla);

    // 1) fake-quant (dequantized fp32) activations + all weights, one launch
    rowquant_all<<<7168, 256>>>(hs, Wq, Wk, Wv, Wo,
                                (float*)pXd, (float*)pWd, (float*)pWod);

    // 2) fused QKV projection + per-head quantize epilogue -> Qd/Kd/Vd
    gemm2<1><<<dim3(18, 32), 256>>>((const float*)pXd, (const float*)pWd,
                                    bq, bk, bv, nullptr,
                                    (float*)pQd, (float*)pKd, (float*)pVd);

    // 3) attention: scores + PLA softmax + prob quant, then P@V
    cudaFuncSetAttribute(attnA, cudaFuncAttributeMaxDynamicSharedMemorySize, SMEM_A);
    attnA<<<dim3(BB*NHEADS, 8), 256, SMEM_A>>>(pla);
    cudaFuncSetAttribute(attnB, cudaFuncAttributeMaxDynamicSharedMemorySize, SMEM_B);
    attnB<<<dim3(BB*NHEADS, 4), 256, SMEM_B>>>();

    // 4) fake-quant ctx rows + output projection
    rowquant_dq<<<ROWS, 256>>>((const float*)pCTX, (float*)pCd);
    gemm2<0><<<dim3(6, 32), 256>>>((const float*)pCd, (const float*)pWod,
                                   bo, nullptr, nullptr, (float*)d_out,
                                   nullptr, nullptr, nullptr);
}

// round 6
// speedup vs baseline: 1.4919x; 1.1581x over previous
#include <cuda_runtime.h>
#include <cstdint>
#include <cmath>

#define HIDDEN 768
#define NHEADS 12
#define HDIM 64
#define BB 8
#define SS 512
#define ROWS (BB*SS)              // 4096
#define HEADROWS (BB*NHEADS*SS)   // 49152

// ---------------- scratch (static device allocations; no cudaMalloc) ----------------
__device__ float g_Xd[(size_t)ROWS*HIDDEN];        // dequant hidden_states
__device__ float g_Wd[(size_t)3*HIDDEN*HIDDEN];    // dequant Wq|Wk|Wv
__device__ float g_Wod[(size_t)HIDDEN*HIDDEN];     // dequant Wo
__device__ float g_Qd[(size_t)HEADROWS*HDIM];      // dequant per-head q
__device__ float g_Kd[(size_t)HEADROWS*HDIM];
__device__ float g_Vd[(size_t)HEADROWS*HDIM];
__device__ float g_P [(size_t)HEADROWS*SS];        // scores, then (in-place) dequant probs
__device__ float g_CTX[(size_t)ROWS*HIDDEN];
__device__ float g_Cd[(size_t)ROWS*HIDDEN];        // dequant quantized ctx

struct PLA { float m[12]; float c[12]; float iv[13]; };

typedef unsigned long long ull;

// packed f32x2 FMA: two independent IEEE RN fmas in one instruction (FFMA2)
__device__ __forceinline__ ull ffma2(ull a, ull b, ull c) {
    ull d;
    asm("fma.rn.f32x2 %0, %1, %2, %3;" : "=l"(d) : "l"(a), "l"(b), "l"(c));
    return d;
}
__device__ __forceinline__ float2 up2(ull v) {
    float2 r;
    asm("mov.b64 {%0, %1}, %2;" : "=f"(r.x), "=f"(r.y) : "l"(v));
    return r;
}
__device__ __forceinline__ ull dup2(float x) {
    ull d;
    asm("mov.b64 %0, {%1, %1};" : "=l"(d) : "f"(x));
    return d;
}

// ---------------- warp-per-row (768) symmetric int8 fake-quant -> dequant fp32 ----------------
__device__ __forceinline__ void wrow_body(const float* __restrict__ x,
                                          float* __restrict__ d, int lane) {
    float v[24];
    #pragma unroll
    for (int j=0;j<6;j++) *(float4*)&v[j*4] = *(const float4*)&x[j*128 + lane*4];
    float mx = fabsf(v[0]);
    #pragma unroll
    for (int j=1;j<24;j++) mx = fmaxf(mx, fabsf(v[j]));
    #pragma unroll
    for (int o=16;o>0;o>>=1) mx = fmaxf(mx, __shfl_xor_sync(0xffffffffu, mx, o));
    float sc = __fdiv_rn(mx, 127.0f);
    if (sc == 0.0f) sc = 1.0f;
    #pragma unroll
    for (int j=0;j<24;j++)
        v[j] = __fmul_rn(fminf(fmaxf(rintf(__fdiv_rn(v[j], sc)), -127.0f), 127.0f), sc);
    #pragma unroll
    for (int j=0;j<6;j++) *(float4*)&d[j*128 + lane*4] = *(float4*)&v[j*4];
}

// merged: X (4096 rows) + Wq + Wk + Wv + Wo (768 each) = 7168 rows, warp per row
__global__ void __launch_bounds__(256) wrowquant_all(const float* __restrict__ x,
                             const float* __restrict__ wq, const float* __restrict__ wk,
                             const float* __restrict__ wv, const float* __restrict__ wo,
                             float* __restrict__ xd, float* __restrict__ wd,
                             float* __restrict__ wod) {
    int row = blockIdx.x*8 + (threadIdx.x>>5);
    int lane = threadIdx.x & 31;
    const float* src; float* dst; int r;
    if (row < 4096)      { r = row;      src = x;  dst = xd; }
    else if (row < 4864) { r = row-4096; src = wq; dst = wd; }
    else if (row < 5632) { r = row-4864; src = wk; dst = wd + (size_t)HIDDEN*HIDDEN; }
    else if (row < 6400) { r = row-5632; src = wv; dst = wd + (size_t)2*HIDDEN*HIDDEN; }
    else                 { r = row-6400; src = wo; dst = wod; }
    wrow_body(src + (size_t)r*HIDDEN, dst + (size_t)r*HIDDEN, lane);
}

__global__ void __launch_bounds__(256) wrowquant_one(const float* __restrict__ src,
                                                     float* __restrict__ dst) {
    int row = blockIdx.x*8 + (threadIdx.x>>5);
    int lane = threadIdx.x & 31;
    wrow_body(src + (size_t)row*HIDDEN, dst + (size_t)row*HIDDEN, lane);
}

// ---------------- QKV GEMM 256x128, 16m x 8n per thread, FFMA2 m-pairs, db smem ----------------
// fused per-head (64) quantize epilogue -> Qd/Kd/Vd
#define QKV_APAD 260
#define QKV_BPAD 132
#define QKV_SMEM ((2*16*QKV_APAD + 2*16*QKV_BPAD)*4)   // 50176
__global__ void __launch_bounds__(256,1) gemmQKV(const float* __restrict__ A,
                                                 const float* __restrict__ B,
                                                 const float* __restrict__ b0,
                                                 const float* __restrict__ b1,
                                                 const float* __restrict__ b2,
                                                 float* __restrict__ Qd,
                                                 float* __restrict__ Kd,
                                                 float* __restrict__ Vd) {
    extern __shared__ float sm[];
    float* As = sm;                        // [2][16][260]
    float* Bs = sm + 2*16*QKV_APAD;        // [2][16][132]
    int t = threadIdx.x;
    int m0 = blockIdx.y * 256;
    int n0 = blockIdx.x * 128;
    int w = t >> 5, lane = t & 31;
    int wm = w & 3, wn = w >> 2;           // warp: 64m x 64n
    int lm = lane & 3, ln = lane >> 2;     // lane: 16m x 8n
    int ar = t >> 2, ac4 = t & 3;

    ull acc[8][8];
    #pragma unroll
    for (int p=0;p<8;p++)
        #pragma unroll
        for (int j=0;j<8;j++) acc[p][j]=0ULL;

    float4 pa[4], pb[2];
    #define Q_LDG(kt) do { \
        const float* Ap = A + (size_t)(m0+ar)*HIDDEN + (kt)*16 + ac4*4; \
        pa[0] = *(const float4*)Ap; \
        pa[1] = *(const float4*)(Ap + (size_t)64*HIDDEN); \
        pa[2] = *(const float4*)(Ap + (size_t)128*HIDDEN); \
        pa[3] = *(const float4*)(Ap + (size_t)192*HIDDEN); \
        const float* Bp = B + (size_t)(n0+ar)*HIDDEN + (kt)*16 + ac4*4; \
        pb[0] = *(const float4*)Bp; \
        pb[1] = *(const float4*)(Bp + (size_t)64*HIDDEN); \
    } while(0)
    #define Q_STS(buf) do { \
        float* Ab = As + (buf)*16*QKV_APAD; \
        float* Bb = Bs + (buf)*16*QKV_BPAD; \
        _Pragma("unroll") \
        for (int l=0;l<4;l++) { \
            Ab[(ac4*4+0)*QKV_APAD + ar + 64*l] = pa[l].x; \
            Ab[(ac4*4+1)*QKV_APAD + ar + 64*l] = pa[l].y; \
            Ab[(ac4*4+2)*QKV_APAD + ar + 64*l] = pa[l].z; \
            Ab[(ac4*4+3)*QKV_APAD + ar + 64*l] = pa[l].w; \
        } \
        _Pragma("unroll") \
        for (int l=0;l<2;l++) { \
            Bb[(ac4*4+0)*QKV_BPAD + ar + 64*l] = pb[l].x; \
            Bb[(ac4*4+1)*QKV_BPAD + ar + 64*l] = pb[l].y; \
            Bb[(ac4*4+2)*QKV_BPAD + ar + 64*l] = pb[l].z; \
            Bb[(ac4*4+3)*QKV_BPAD + ar + 64*l] = pb[l].w; \
        } \
    } while(0)

    Q_LDG(0);
    Q_STS(0);
    __syncthreads();

    int aull = wm*32 + lm*8;               // ull offset (16 m = 8 ull)
    int boff = wn*64 + ln*8;
    for (int kt = 0; kt < 48; ++kt) {
        int buf = kt & 1;
        if (kt < 47) Q_LDG(kt+1);
        const float* Ab = As + buf*16*QKV_APAD;
        const float* Bb = Bs + buf*16*QKV_BPAD;
        #pragma unroll
        for (int k = 0; k < 16; ++k) {     // ascending k; fused fma per output
            const ull* Au = (const ull*)(Ab + k*QKV_APAD);
            ulonglong2 a0 = *(const ulonglong2*)&Au[aull];
            ulonglong2 a1 = *(const ulonglong2*)&Au[aull+2];
            ulonglong2 a2 = *(const ulonglong2*)&Au[aull+4];
            ulonglong2 a3 = *(const ulonglong2*)&Au[aull+6];
            ull am[8] = {a0.x,a0.y,a1.x,a1.y,a2.x,a2.y,a3.x,a3.y};
            const float* Brow = Bb + k*QKV_BPAD + boff;
            float4 bl = *(const float4*)Brow;
            float4 bh = *(const float4*)(Brow+4);
            ull bd[8];
            bd[0]=dup2(bl.x); bd[1]=dup2(bl.y); bd[2]=dup2(bl.z); bd[3]=dup2(bl.w);
            bd[4]=dup2(bh.x); bd[5]=dup2(bh.y); bd[6]=dup2(bh.z); bd[7]=dup2(bh.w);
            #pragma unroll
            for (int p=0;p<8;p++)
                #pragma unroll
                for (int j=0;j<8;j++)
                    acc[p][j] = ffma2(am[p], bd[j], acc[p][j]);
        }
        if (kt < 47) {
            __syncthreads();
            Q_STS(buf ^ 1);
            __syncthreads();
        }
    }

    // epilogue: bias + per-head (64) quantize -> Qd/Kd/Vd
    int nrel = n0 % 768;
    int tsel = n0 / 768;
    const float* bias = (tsel==0) ? b0 : (tsel==1 ? b1 : b2);
    float* dstbase = (tsel==0) ? Qd : (tsel==1 ? Kd : Vd);
    int hh = (nrel >> 6) + wn;
    int cb = nrel + wn*64 + ln*8;
    #pragma unroll
    for (int p=0;p<8;p++) {
        float ve[8], vo[8];
        #pragma unroll
        for (int j=0;j<8;j++) {
            float2 f = up2(acc[p][j]);
            ve[j] = __fadd_rn(f.x, bias[cb+j]);
            vo[j] = __fadd_rn(f.y, bias[cb+j]);
        }
        #pragma unroll
        for (int half=0; half<2; ++half) {
            float* v = half ? vo : ve;
            int gm = m0 + wm*64 + lm*16 + 2*p + half;
            float mxv = fabsf(v[0]);
            #pragma unroll
            for (int j=1;j<8;j++) mxv = fmaxf(mxv, fabsf(v[j]));
            mxv = fmaxf(mxv, __shfl_xor_sync(0xffffffffu, mxv, 4));
            mxv = fmaxf(mxv, __shfl_xor_sync(0xffffffffu, mxv, 8));
            mxv = fmaxf(mxv, __shfl_xor_sync(0xffffffffu, mxv, 16));
            float sc = __fdiv_rn(mxv, 127.0f);
            if (sc == 0.0f) sc = 1.0f;
            float q[8];
            #pragma unroll
            for (int j=0;j<8;j++)
                q[j] = __fmul_rn(fminf(fmaxf(rintf(__fdiv_rn(v[j], sc)), -127.0f), 127.0f), sc);
            int b = gm >> 9, s = gm & 511;
            float* drow = dstbase + ((size_t)((b*NHEADS + hh)*SS + s))*HDIM + ln*8;
            *(float4*)drow       = make_float4(q[0],q[1],q[2],q[3]);
            *(float4*)(drow + 4) = make_float4(q[4],q[5],q[6],q[7]);
        }
    }
}

// ---------------- generic 128x128 GEMM (out projection), FFMA2 m-pairs ----------------
#define GPAD 136
__global__ void __launch_bounds__(256) gemmOut(const float* __restrict__ A,
                                               const float* __restrict__ B,
                                               const float* __restrict__ b0,
                                               float* __restrict__ C) {
    __shared__ __align__(16) float As[2*16*GPAD];
    __shared__ __align__(16) float Bs[2*16*GPAD];
    int t = threadIdx.x;
    int m0 = blockIdx.y * 128;
    int n0 = blockIdx.x * 128;
    int w = t >> 5, lane = t & 31;
    int wm = w & 3, wn = w >> 2;
    int lm = lane & 3, ln = lane >> 2;
    int ar = t >> 2, ac4 = t & 3;

    ull acc2[4][8];
    #pragma unroll
    for (int p=0;p<4;p++)
        #pragma unroll
        for (int j=0;j<8;j++) acc2[p][j]=0ULL;

    float4 pa0, pa1, pb0, pb1;
    #define O_LDG(kt) do { \
        const float* Ap = A + (size_t)(m0+ar)*HIDDEN + (kt)*16 + ac4*4; \
        pa0 = *(const float4*)Ap; \
        pa1 = *(const float4*)(Ap + (size_t)64*HIDDEN); \
        const float* Bp = B + (size_t)(n0+ar)*HIDDEN + (kt)*16 + ac4*4; \
        pb0 = *(const float4*)Bp; \
        pb1 = *(const float4*)(Bp + (size_t)64*HIDDEN); \
    } while(0)
    #define O_STS(buf) do { \
        float* Ab = As + (buf)*16*GPAD; \
        float* Bb = Bs + (buf)*16*GPAD; \
        Ab[(ac4*4+0)*GPAD + ar] = pa0.x; Ab[(ac4*4+1)*GPAD + ar] = pa0.y; \
        Ab[(ac4*4+2)*GPAD + ar] = pa0.z; Ab[(ac4*4+3)*GPAD + ar] = pa0.w; \
        Ab[(ac4*4+0)*GPAD + ar+64] = pa1.x; Ab[(ac4*4+1)*GPAD + ar+64] = pa1.y; \
        Ab[(ac4*4+2)*GPAD + ar+64] = pa1.z; Ab[(ac4*4+3)*GPAD + ar+64] = pa1.w; \
        Bb[(ac4*4+0)*GPAD + ar] = pb0.x; Bb[(ac4*4+1)*GPAD + ar] = pb0.y; \
        Bb[(ac4*4+2)*GPAD + ar] = pb0.z; Bb[(ac4*4+3)*GPAD + ar] = pb0.w; \
        Bb[(ac4*4+0)*GPAD + ar+64] = pb1.x; Bb[(ac4*4+1)*GPAD + ar+64] = pb1.y; \
        Bb[(ac4*4+2)*GPAD + ar+64] = pb1.z; Bb[(ac4*4+3)*GPAD + ar+64] = pb1.w; \
    } while(0)

    O_LDG(0);
    O_STS(0);
    __syncthreads();

    int aull = wm*16 + lm*4;
    int boff = wn*64 + ln*8;
    for (int kt = 0; kt < 48; ++kt) {
        int buf = kt & 1;
        if (kt < 47) O_LDG(kt+1);
        const float* Ab = As + buf*16*GPAD;
        const float* Bb = Bs + buf*16*GPAD;
        #pragma unroll
        for (int k = 0; k < 16; ++k) {
            const ull* Arow = (const ull*)(Ab + k*GPAD);
            ulonglong2 aA = *(const ulonglong2*)&Arow[aull];
            ulonglong2 aB = *(const ulonglong2*)&Arow[aull+2];
            ull am[4] = {aA.x, aA.y, aB.x, aB.y};
            const float* Brow = Bb + k*GPAD + boff;
            float4 bl = *(const float4*)Brow;
            float4 bh = *(const float4*)(Brow+4);
            ull bd[8];
            bd[0]=dup2(bl.x); bd[1]=dup2(bl.y); bd[2]=dup2(bl.z); bd[3]=dup2(bl.w);
            bd[4]=dup2(bh.x); bd[5]=dup2(bh.y); bd[6]=dup2(bh.z); bd[7]=dup2(bh.w);
            #pragma unroll
            for (int p=0;p<4;p++)
                #pragma unroll
                for (int j=0;j<8;j++)
                    acc2[p][j] = ffma2(am[p], bd[j], acc2[p][j]);
        }
        if (kt < 47) {
            __syncthreads();
            O_STS(buf ^ 1);
            __syncthreads();
        }
    }

    int cb = n0 + wn*64 + ln*8;
    #pragma unroll
    for (int p=0;p<4;p++) {
        float ve[8], vo[8];
        #pragma unroll
        for (int j=0;j<8;j++) {
            float2 f = up2(acc2[p][j]);
            ve[j] = __fadd_rn(f.x, b0[cb+j]);
            vo[j] = __fadd_rn(f.y, b0[cb+j]);
        }
        int gm = m0 + wm*32 + lm*8 + 2*p;
        float* ce = C + (size_t)gm*768 + cb;
        float* co = C + (size_t)(gm+1)*768 + cb;
        *(float4*)ce     = make_float4(ve[0],ve[1],ve[2],ve[3]);
        *(float4*)(ce+4) = make_float4(ve[4],ve[5],ve[6],ve[7]);
        *(float4*)co     = make_float4(vo[0],vo[1],vo[2],vo[3]);
        *(float4*)(co+4) = make_float4(vo[4],vo[5],vo[6],vo[7]);
    }
}

// ---------------- attention scores GEMM: S[m,n] = (q[m,:].k[n,:]) * 0.125 -> g_P ----------------
// per head 512x512x64; block 128x128; d=64 in one staged shot (ascending-d fused chain).
#define SC_SMEM (2*64*128*4)   // Qs[64][128] + Ks[64][128] = 65536
__global__ void __launch_bounds__(256,1) attnSc() {
    extern __shared__ float sm[];
    float* Qs = sm;            // [d 64][m 128]  (m-pairs contiguous)
    float* Ks = sm + 64*128;   // [d 64][n 128]
    int t = threadIdx.x;
    int bh = blockIdx.x;
    int m0 = (blockIdx.y & 3) * 128;
    int n0 = (blockIdx.y >> 2) * 128;
    int w = t >> 5, lane = t & 31;
    int wm = w & 3, wn = w >> 2;
    int lm = lane & 3, ln = lane >> 2;

    {   // stage Q,K transposed: thread covers one row, 32 d
        int r = t & 127, d0 = (t >> 7) * 32;
        const float* Qg = g_Qd + ((size_t)bh*SS + m0 + r)*HDIM + d0;
        const float* Kg = g_Kd + ((size_t)bh*SS + n0 + r)*HDIM + d0;
        #pragma unroll
        for (int j=0;j<8;j++) {
            float4 q = *(const float4*)(Qg + j*4);
            Qs[(d0+j*4+0)*128 + r] = q.x; Qs[(d0+j*4+1)*128 + r] = q.y;
            Qs[(d0+j*4+2)*128 + r] = q.z; Qs[(d0+j*4+3)*128 + r] = q.w;
            float4 k = *(const float4*)(Kg + j*4);
            Ks[(d0+j*4+0)*128 + r] = k.x; Ks[(d0+j*4+1)*128 + r] = k.y;
            Ks[(d0+j*4+2)*128 + r] = k.z; Ks[(d0+j*4+3)*128 + r] = k.w;
        }
    }
    __syncthreads();

    ull acc[4][8];
    #pragma unroll
    for (int p=0;p<4;p++)
        #pragma unroll
        for (int j=0;j<8;j++) acc[p][j]=0ULL;

    int aull = wm*16 + lm*4;
    int boff = wn*64 + ln*8;
    #pragma unroll 8
    for (int d = 0; d < 64; ++d) {         // ascending d; fused fma per output
        const ull* Au = (const ull*)(Qs + d*128);
        ulonglong2 a0 = *(const ulonglong2*)&Au[aull];
        ulonglong2 a1 = *(const ulonglong2*)&Au[aull+2];
        ull am[4] = {a0.x, a0.y, a1.x, a1.y};
        const float* Brow = Ks + d*128 + boff;
        float4 bl = *(const float4*)Brow;
        float4 bh = *(const float4*)(Brow+4);
        ull bd[8];
        bd[0]=dup2(bl.x); bd[1]=dup2(bl.y); bd[2]=dup2(bl.z); bd[3]=dup2(bl.w);
        bd[4]=dup2(bh.x); bd[5]=dup2(bh.y); bd[6]=dup2(bh.z); bd[7]=dup2(bh.w);
        #pragma unroll
        for (int p=0;p<4;p++)
            #pragma unroll
            for (int j=0;j<8;j++)
                acc[p][j] = ffma2(am[p], bd[j], acc[p][j]);
    }

    int cb = n0 + wn*64 + ln*8;
    #pragma unroll
    for (int p=0;p<4;p++) {
        float ve[8], vo[8];
        #pragma unroll
        for (int j=0;j<8;j++) {
            float2 f = up2(acc[p][j]);
            ve[j] = __fmul_rn(f.x, 0.125f);
            vo[j] = __fmul_rn(f.y, 0.125f);
        }
        int gm = m0 + wm*32 + lm*8 + 2*p;
        float* se = g_P + ((size_t)bh*SS + gm)*SS + cb;
        float* so = g_P + ((size_t)bh*SS + gm + 1)*SS + cb;
        *(float4*)se     = make_float4(ve[0],ve[1],ve[2],ve[3]);
        *(float4*)(se+4) = make_float4(ve[4],ve[5],ve[6],ve[7]);
        *(float4*)so     = make_float4(vo[0],vo[1],vo[2],vo[3]);
        *(float4*)(so+4) = make_float4(vo[4],vo[5],vo[6],vo[7]);
    }
}

// ---------------- softmax (in-place on g_P): PLA exp, strict-seq sum, quantize ----------------
// warp per row; grid (96, 64), 8 warps/CTA.
__global__ void __launch_bounds__(256) smx(PLA pla) {
    __shared__ float eb[8][512];
    int t = threadIdx.x, w = t >> 5, lane = t & 31;
    int bh = blockIdx.x;
    int srow = blockIdx.y*8 + w;
    float* row = g_P + ((size_t)bh*SS + srow)*SS;

    float v[16];
    #pragma unroll
    for (int j=0;j<4;j++) *(float4*)&v[j*4] = *(const float4*)&row[j*128 + lane*4];

    float mx = v[0];
    #pragma unroll
    for (int j=1;j<16;j++) mx = fmaxf(mx, v[j]);
    #pragma unroll
    for (int o=16;o>0;o>>=1) mx = fmaxf(mx, __shfl_xor_sync(0xffffffffu, mx, o));

    #pragma unroll
    for (int j = 0; j < 16; j++) {
        float sh = __fadd_rn(v[j], -mx);
        float fr = rintf(__fmul_rn(sh, 67108864.0f));
        fr = fminf(fmaxf(fr, -2147483648.0f), 2147483648.0f);
        float fx = __fmul_rn(fr, 1.4901161193847656e-8f); // * 2^-26
        float xc = fminf(fmaxf(fx, -10.0f), 0.0f);
        int cnt = 0;
        #pragma unroll
        for (int i = 0; i < 13; i++) cnt += (xc >= pla.iv[i]) ? 1 : 0;
        int idx = cnt - 1; if (idx < 0) idx = 0; if (idx > 11) idx = 11;
        v[j] = __fadd_rn(__fmul_rn(pla.m[idx], xc), pla.c[idx]);
    }
    #pragma unroll
    for (int j=0;j<4;j++) *(float4*)&eb[w][j*128 + lane*4] = *(float4*)&v[j*4];
    __syncwarp();

    float ssum = 0.0f;
    if (lane == 0) {                       // strict in-order 512-add chain
        const float* er = eb[w];
        #pragma unroll 8
        for (int i = 0; i < 512; i++) ssum = __fadd_rn(ssum, er[i]);
    }
    ssum = __shfl_sync(0xffffffffu, ssum, 0);
    float denom = __fadd_rn(ssum, 1e-9f);

    float qmx = 0.0f;
    #pragma unroll
    for (int j = 0; j < 16; j++) {
        float smv = __fdiv_rn(v[j], denom);
        v[j] = smv;
        qmx = fmaxf(qmx, fabsf(smv));
    }
    #pragma unroll
    for (int o=16;o>0;o>>=1) qmx = fmaxf(qmx, __shfl_xor_sync(0xffffffffu, qmx, o));
    float sp = __fdiv_rn(qmx, 127.0f);
    if (sp == 0.0f) sp = 1.0f;
    #pragma unroll
    for (int j = 0; j < 16; j++)
        v[j] = __fmul_rn(fminf(fmaxf(rintf(__fdiv_rn(v[j], sp)), -127.0f), 127.0f), sp);
    #pragma unroll
    for (int j=0;j<4;j++) *(float4*)&row[j*128 + lane*4] = *(float4*)&v[j*4];
}

// ---------------- attention P@V: double-buffered 128-k V chunks, P from gmem ----------------
// grid (96, 4): head x 128 m-rows. 256 thr: tx(8)=8d, ty(32)=4m. smem 64KB -> ~3 CTAs/SM.
#define PV_SMEM (2*128*64*4)   // 65536
__global__ void __launch_bounds__(256,1) attnPV() {
    extern __shared__ float Vs[];          // [2][128][64]
    int t = threadIdx.x;
    int tx = t & 7, ty = t >> 3;
    int bh = blockIdx.x;
    int m0 = blockIdx.y * 128;

    const float* Vg = g_Vd + (size_t)bh*SS*HDIM;
    float4 buf[8];
    #pragma unroll
    for (int l=0;l<8;l++) buf[l] = *(const float4*)(Vg + l*1024 + t*4);
    #pragma unroll
    for (int l=0;l<8;l++) *(float4*)&Vs[l*1024 + t*4] = buf[l];
    __syncthreads();

    ull acc[4][4];
    #pragma unroll
    for (int i=0;i<4;i++)
        #pragma unroll
        for (int u=0;u<4;u++) acc[i][u]=0ULL;

    const float* Pg = g_P + ((size_t)bh*SS + m0 + ty*4)*SS;
    for (int kc = 0; kc < 4; ++kc) {       // ascending k chunks
        if (kc < 3) {
            const float* src = Vg + (kc+1)*8192;
            #pragma unroll
            for (int l=0;l<8;l++) buf[l] = *(const float4*)(src + l*1024 + t*4);
        }
        const ull* Vu = (const ull*)(Vs + (kc&1)*8192);
        #pragma unroll 4
        for (int kb = 0; kb < 32; ++kb) {
            float pa[4][4];
            #pragma unroll
            for (int i=0;i<4;i++)
                *(float4*)pa[i] = *(const float4*)&Pg[(size_t)i*SS + kc*128 + kb*4];
            #pragma unroll
            for (int kk = 0; kk < 4; ++kk) {    // ascending k, fused fma per output
                int k = kb*4 + kk;
                ulonglong2 v0 = *(const ulonglong2*)&Vu[k*32 + tx*4];
                ulonglong2 v1 = *(const ulonglong2*)&Vu[k*32 + tx*4 + 2];
                ull vp[4] = {v0.x, v0.y, v1.x, v1.y};
                #pragma unroll
                for (int i=0;i<4;i++) {
                    ull pd = dup2(pa[i][kk]);
                    acc[i][0] = ffma2(pd, vp[0], acc[i][0]);
                    acc[i][1] = ffma2(pd, vp[1], acc[i][1]);
                    acc[i][2] = ffma2(pd, vp[2], acc[i][2]);
                    acc[i][3] = ffma2(pd, vp[3], acc[i][3]);
                }
            }
        }
        if (kc < 3) {
            __syncthreads();
            float* dstb = Vs + ((kc+1)&1)*8192;
            #pragma unroll
            for (int l=0;l<8;l++) *(float4*)&dstb[l*1024 + t*4] = buf[l];
            __syncthreads();
        }
    }
    int b = bh / NHEADS, h = bh % NHEADS;
    #pragma unroll
    for (int i=0;i<4;i++) {
        int s = m0 + ty*4 + i;
        float* Co = g_CTX + ((size_t)(b*SS + s))*HIDDEN + h*HDIM + tx*8;
        float2 f0 = up2(acc[i][0]), f1 = up2(acc[i][1]);
        float2 f2 = up2(acc[i][2]), f3 = up2(acc[i][3]);
        *(float4*)Co     = make_float4(f0.x, f0.y, f1.x, f1.y);
        *(float4*)(Co+4) = make_float4(f2.x, f2.y, f3.x, f3.y);
    }
}

// ---------------- host: replicate np.polyfit coefficients in double ----------------
static void build_pla(PLA& p) {
    double xs[1001], ys[1001];
    double step = 10.0 / 1000.0;
    for (int j = 0; j <= 1000; j++) xs[j] = -10.0 + (double)j * step;
    xs[1000] = 0.0;
    for (int j = 0; j <= 1000; j++) ys[j] = exp(xs[j]);
    double iv[13];
    double st2 = 10.0 / 12.0;
    for (int i = 0; i < 13; i++) iv[i] = -10.0 + (double)i * st2;
    iv[12] = 0.0;
    for (int i = 0; i < 12; i++) {
        double a = iv[i], b = iv[i+1];
        double n = 0, Sx = 0, Sy = 0, Sxx = 0, Sxy = 0;
        for (int j = 0; j <= 1000; j++) {
            if (xs[j] >= a && xs[j] <= b) {
                n += 1.0; Sx += xs[j]; Sy += ys[j];
                Sxx += xs[j]*xs[j]; Sxy += xs[j]*ys[j];
            }
        }
        double m = (n*Sxy - Sx*Sy) / (n*Sxx - Sx*Sx);
        double c = (Sy - m*Sx) / n;
        p.m[i] = (float)m;
        p.c[i] = (float)c;
    }
    for (int i = 0; i < 13; i++) p.iv[i] = (float)iv[i];
}

extern "C" void kernel_launch(void* const* d_in, const int* in_sizes, int n_in,
                              void* d_out, int out_size) {
    (void)in_sizes; (void)n_in; (void)out_size;
    const float* hs = (const float*)d_in[0];
    const float* Wq = (const float*)d_in[1];
    const float* bq = (const float*)d_in[2];
    const float* Wk = (const float*)d_in[3];
    const float* bk = (const float*)d_in[4];
    const float* Wv = (const float*)d_in[5];
    const float* bv = (const float*)d_in[6];
    const float* Wo = (const float*)d_in[7];
    const float* bo = (const float*)d_in[8];

    void *pXd, *pWd, *pWod, *pCTX, *pCd, *pQd, *pKd, *pVd;
    cudaGetSymbolAddress(&pXd, g_Xd);
    cudaGetSymbolAddress(&pWd, g_Wd);
    cudaGetSymbolAddress(&pWod, g_Wod);
    cudaGetSymbolAddress(&pCTX, g_CTX);
    cudaGetSymbolAddress(&pCd, g_Cd);
    cudaGetSymbolAddress(&pQd, g_Qd);
    cudaGetSymbolAddress(&pKd, g_Kd);
    cudaGetSymbolAddress(&pVd, g_Vd);

    PLA pla;
    build_pla(pla);

    // 1) fake-quant (dequant fp32) activations + all weights (warp per row)
    wrowquant_all<<<896, 256>>>(hs, Wq, Wk, Wv, Wo,
                                (float*)pXd, (float*)pWd, (float*)pWod);

    // 2) QKV projection (256x128 FFMA2 GEMM) + per-head quantize epilogue
    cudaFuncSetAttribute(gemmQKV, cudaFuncAttributeMaxDynamicSharedMemorySize, QKV_SMEM);
    gemmQKV<<<dim3(18, 16), 256, QKV_SMEM>>>((const float*)pXd, (const float*)pWd,
                                             bq, bk, bv,
                                             (float*)pQd, (float*)pKd, (float*)pVd);

    // 3) scores GEMM -> g_P ; softmax in place ; P@V
    cudaFuncSetAttribute(attnSc, cudaFuncAttributeMaxDynamicSharedMemorySize, SC_SMEM);
    attnSc<<<dim3(96, 16), 256, SC_SMEM>>>();
    smx<<<dim3(96, 64), 256>>>(pla);
    cudaFuncSetAttribute(attnPV, cudaFuncAttributeMaxDynamicSharedMemorySize, PV_SMEM);
    attnPV<<<dim3(96, 4), 256, PV_SMEM>>>();

    // 4) fake-quant ctx rows + output projection
    wrowquant_one<<<512, 256>>>((const float*)pCTX, (float*)pCd);
    gemmOut<<<dim3(6, 32), 256>>>((const float*)pCd, (const float*)pWod, bo, (float*)d_out);
}

// round 7
// speedup vs baseline: 1.5075x; 1.0104x over previous
#include <cuda_runtime.h>
#include <cstdint>
#include <cmath>

#define HIDDEN 768
#define NHEADS 12
#define HDIM 64
#define BB 8
#define SS 512
#define ROWS (BB*SS)              // 4096
#define HEADROWS (BB*NHEADS*SS)   // 49152

// ---------------- scratch (static device allocations; no cudaMalloc) ----------------
__device__ float g_Xd[(size_t)ROWS*HIDDEN];        // dequant hidden_states
__device__ float g_Wd[(size_t)3*HIDDEN*HIDDEN];    // dequant Wq|Wk|Wv
__device__ float g_Wod[(size_t)HIDDEN*HIDDEN];     // dequant Wo
__device__ float g_Qd[(size_t)HEADROWS*HDIM];      // dequant per-head q
__device__ float g_Kd[(size_t)HEADROWS*HDIM];
__device__ float g_Vd[(size_t)HEADROWS*HDIM];
__device__ float g_P [(size_t)HEADROWS*SS];        // raw scores (fp32)
__device__ int8_t g_P8[(size_t)HEADROWS*SS];       // quantized probs (int levels)
__device__ float g_Psc[HEADROWS];                  // per-row prob scale sp
__device__ float g_CTX[(size_t)ROWS*HIDDEN];
__device__ float g_Cd[(size_t)ROWS*HIDDEN];        // dequant quantized ctx

struct PLA { float m[12]; float c[12]; float iv[13]; };

typedef unsigned long long ull;

// packed f32x2 FMA: two independent IEEE RN fmas in one instruction (FFMA2)
__device__ __forceinline__ ull ffma2(ull a, ull b, ull c) {
    ull d;
    asm("fma.rn.f32x2 %0, %1, %2, %3;" : "=l"(d) : "l"(a), "l"(b), "l"(c));
    return d;
}
__device__ __forceinline__ float2 up2(ull v) {
    float2 r;
    asm("mov.b64 {%0, %1}, %2;" : "=f"(r.x), "=f"(r.y) : "l"(v));
    return r;
}
__device__ __forceinline__ ull dup2(float x) {
    ull d;
    asm("mov.b64 %0, {%1, %1};" : "=l"(d) : "f"(x));
    return d;
}

// ---------------- warp-per-row (768) symmetric int8 fake-quant -> dequant fp32 ----------------
__device__ __forceinline__ void wrow_body(const float* __restrict__ x,
                                          float* __restrict__ d, int lane) {
    float v[24];
    #pragma unroll
    for (int j=0;j<6;j++) *(float4*)&v[j*4] = *(const float4*)&x[j*128 + lane*4];
    float mx = fabsf(v[0]);
    #pragma unroll
    for (int j=1;j<24;j++) mx = fmaxf(mx, fabsf(v[j]));
    #pragma unroll
    for (int o=16;o>0;o>>=1) mx = fmaxf(mx, __shfl_xor_sync(0xffffffffu, mx, o));
    float sc = __fdiv_rn(mx, 127.0f);
    if (sc == 0.0f) sc = 1.0f;
    #pragma unroll
    for (int j=0;j<24;j++)
        v[j] = __fmul_rn(fminf(fmaxf(rintf(__fdiv_rn(v[j], sc)), -127.0f), 127.0f), sc);
    #pragma unroll
    for (int j=0;j<6;j++) *(float4*)&d[j*128 + lane*4] = *(float4*)&v[j*4];
}

// merged: X (4096 rows) + Wq + Wk + Wv + Wo (768 each) = 7168 rows, warp per row
__global__ void __launch_bounds__(256) wrowquant_all(const float* __restrict__ x,
                             const float* __restrict__ wq, const float* __restrict__ wk,
                             const float* __restrict__ wv, const float* __restrict__ wo,
                             float* __restrict__ xd, float* __restrict__ wd,
                             float* __restrict__ wod) {
    int row = blockIdx.x*8 + (threadIdx.x>>5);
    int lane = threadIdx.x & 31;
    const float* src; float* dst; int r;
    if (row < 4096)      { r = row;      src = x;  dst = xd; }
    else if (row < 4864) { r = row-4096; src = wq; dst = wd; }
    else if (row < 5632) { r = row-4864; src = wk; dst = wd + (size_t)HIDDEN*HIDDEN; }
    else if (row < 6400) { r = row-5632; src = wv; dst = wd + (size_t)2*HIDDEN*HIDDEN; }
    else                 { r = row-6400; src = wo; dst = wod; }
    wrow_body(src + (size_t)r*HIDDEN, dst + (size_t)r*HIDDEN, lane);
}

__global__ void __launch_bounds__(256) wrowquant_one(const float* __restrict__ src,
                                                     float* __restrict__ dst) {
    int row = blockIdx.x*8 + (threadIdx.x>>5);
    int lane = threadIdx.x & 31;
    wrow_body(src + (size_t)row*HIDDEN, dst + (size_t)row*HIDDEN, lane);
}

// ---------------- QKV GEMM 256x128, 16m x 8n per thread, FFMA2 m-pairs, db smem ----------------
#define QKV_APAD 260
#define QKV_BPAD 132
#define QKV_SMEM ((2*16*QKV_APAD + 2*16*QKV_BPAD)*4)   // 50176
__global__ void __launch_bounds__(256,1) gemmQKV(const float* __restrict__ A,
                                                 const float* __restrict__ B,
                                                 const float* __restrict__ b0,
                                                 const float* __restrict__ b1,
                                                 const float* __restrict__ b2,
                                                 float* __restrict__ Qd,
                                                 float* __restrict__ Kd,
                                                 float* __restrict__ Vd) {
    extern __shared__ float sm[];
    float* As = sm;                        // [2][16][260]
    float* Bs = sm + 2*16*QKV_APAD;        // [2][16][132]
    int t = threadIdx.x;
    int m0 = blockIdx.y * 256;
    int n0 = blockIdx.x * 128;
    int w = t >> 5, lane = t & 31;
    int wm = w & 3, wn = w >> 2;           // warp: 64m x 64n
    int lm = lane & 3, ln = lane >> 2;     // lane: 16m x 8n
    int ar = t >> 2, ac4 = t & 3;

    ull acc[8][8];
    #pragma unroll
    for (int p=0;p<8;p++)
        #pragma unroll
        for (int j=0;j<8;j++) acc[p][j]=0ULL;

    float4 pa[4], pb[2];
    #define Q_LDG(kt) do { \
        const float* Ap = A + (size_t)(m0+ar)*HIDDEN + (kt)*16 + ac4*4; \
        pa[0] = *(const float4*)Ap; \
        pa[1] = *(const float4*)(Ap + (size_t)64*HIDDEN); \
        pa[2] = *(const float4*)(Ap + (size_t)128*HIDDEN); \
        pa[3] = *(const float4*)(Ap + (size_t)192*HIDDEN); \
        const float* Bp = B + (size_t)(n0+ar)*HIDDEN + (kt)*16 + ac4*4; \
        pb[0] = *(const float4*)Bp; \
        pb[1] = *(const float4*)(Bp + (size_t)64*HIDDEN); \
    } while(0)
    #define Q_STS(buf) do { \
        float* Ab = As + (buf)*16*QKV_APAD; \
        float* Bb = Bs + (buf)*16*QKV_BPAD; \
        _Pragma("unroll") \
        for (int l=0;l<4;l++) { \
            Ab[(ac4*4+0)*QKV_APAD + ar + 64*l] = pa[l].x; \
            Ab[(ac4*4+1)*QKV_APAD + ar + 64*l] = pa[l].y; \
            Ab[(ac4*4+2)*QKV_APAD + ar + 64*l] = pa[l].z; \
            Ab[(ac4*4+3)*QKV_APAD + ar + 64*l] = pa[l].w; \
        } \
        _Pragma("unroll") \
        for (int l=0;l<2;l++) { \
            Bb[(ac4*4+0)*QKV_BPAD + ar + 64*l] = pb[l].x; \
            Bb[(ac4*4+1)*QKV_BPAD + ar + 64*l] = pb[l].y; \
            Bb[(ac4*4+2)*QKV_BPAD + ar + 64*l] = pb[l].z; \
            Bb[(ac4*4+3)*QKV_BPAD + ar + 64*l] = pb[l].w; \
        } \
    } while(0)

    Q_LDG(0);
    Q_STS(0);
    __syncthreads();

    int aull = wm*32 + lm*8;
    int boff = wn*64 + ln*8;
    for (int kt = 0; kt < 48; ++kt) {
        int buf = kt & 1;
        if (kt < 47) Q_LDG(kt+1);
        const float* Ab = As + buf*16*QKV_APAD;
        const float* Bb = Bs + buf*16*QKV_BPAD;
        #pragma unroll
        for (int k = 0; k < 16; ++k) {     // ascending k; fused fma per output
            const ull* Au = (const ull*)(Ab + k*QKV_APAD);
            ulonglong2 a0 = *(const ulonglong2*)&Au[aull];
            ulonglong2 a1 = *(const ulonglong2*)&Au[aull+2];
            ulonglong2 a2 = *(const ulonglong2*)&Au[aull+4];
            ulonglong2 a3 = *(const ulonglong2*)&Au[aull+6];
            ull am[8] = {a0.x,a0.y,a1.x,a1.y,a2.x,a2.y,a3.x,a3.y};
            const float* Brow = Bb + k*QKV_BPAD + boff;
            float4 bl = *(const float4*)Brow;
            float4 bh = *(const float4*)(Brow+4);
            ull bd[8];
            bd[0]=dup2(bl.x); bd[1]=dup2(bl.y); bd[2]=dup2(bl.z); bd[3]=dup2(bl.w);
            bd[4]=dup2(bh.x); bd[5]=dup2(bh.y); bd[6]=dup2(bh.z); bd[7]=dup2(bh.w);
            #pragma unroll
            for (int p=0;p<8;p++)
                #pragma unroll
                for (int j=0;j<8;j++)
                    acc[p][j] = ffma2(am[p], bd[j], acc[p][j]);
        }
        if (kt < 47) {
            __syncthreads();
            Q_STS(buf ^ 1);
            __syncthreads();
        }
    }

    // epilogue: bias + per-head (64) quantize -> Qd/Kd/Vd
    int nrel = n0 % 768;
    int tsel = n0 / 768;
    const float* bias = (tsel==0) ? b0 : (tsel==1 ? b1 : b2);
    float* dstbase = (tsel==0) ? Qd : (tsel==1 ? Kd : Vd);
    int hh = (nrel >> 6) + wn;
    int cb = nrel + wn*64 + ln*8;
    #pragma unroll
    for (int p=0;p<8;p++) {
        float ve[8], vo[8];
        #pragma unroll
        for (int j=0;j<8;j++) {
            float2 f = up2(acc[p][j]);
            ve[j] = __fadd_rn(f.x, bias[cb+j]);
            vo[j] = __fadd_rn(f.y, bias[cb+j]);
        }
        #pragma unroll
        for (int half=0; half<2; ++half) {
            float* v = half ? vo : ve;
            int gm = m0 + wm*64 + lm*16 + 2*p + half;
            float mxv = fabsf(v[0]);
            #pragma unroll
            for (int j=1;j<8;j++) mxv = fmaxf(mxv, fabsf(v[j]));
            mxv = fmaxf(mxv, __shfl_xor_sync(0xffffffffu, mxv, 4));
            mxv = fmaxf(mxv, __shfl_xor_sync(0xffffffffu, mxv, 8));
            mxv = fmaxf(mxv, __shfl_xor_sync(0xffffffffu, mxv, 16));
            float sc = __fdiv_rn(mxv, 127.0f);
            if (sc == 0.0f) sc = 1.0f;
            float q[8];
            #pragma unroll
            for (int j=0;j<8;j++)
                q[j] = __fmul_rn(fminf(fmaxf(rintf(__fdiv_rn(v[j], sc)), -127.0f), 127.0f), sc);
            int b = gm >> 9, s = gm & 511;
            float* drow = dstbase + ((size_t)((b*NHEADS + hh)*SS + s))*HDIM + ln*8;
            *(float4*)drow       = make_float4(q[0],q[1],q[2],q[3]);
            *(float4*)(drow + 4) = make_float4(q[4],q[5],q[6],q[7]);
        }
    }
}

// ---------------- generic 128x128 GEMM (out projection), FFMA2 m-pairs ----------------
#define GPAD 136
__global__ void __launch_bounds__(256) gemmOut(const float* __restrict__ A,
                                               const float* __restrict__ B,
                                               const float* __restrict__ b0,
                                               float* __restrict__ C) {
    __shared__ __align__(16) float As[2*16*GPAD];
    __shared__ __align__(16) float Bs[2*16*GPAD];
    int t = threadIdx.x;
    int m0 = blockIdx.y * 128;
    int n0 = blockIdx.x * 128;
    int w = t >> 5, lane = t & 31;
    int wm = w & 3, wn = w >> 2;
    int lm = lane & 3, ln = lane >> 2;
    int ar = t >> 2, ac4 = t & 3;

    ull acc2[4][8];
    #pragma unroll
    for (int p=0;p<4;p++)
        #pragma unroll
        for (int j=0;j<8;j++) acc2[p][j]=0ULL;

    float4 pa0, pa1, pb0, pb1;
    #define O_LDG(kt) do { \
        const float* Ap = A + (size_t)(m0+ar)*HIDDEN + (kt)*16 + ac4*4; \
        pa0 = *(const float4*)Ap; \
        pa1 = *(const float4*)(Ap + (size_t)64*HIDDEN); \
        const float* Bp = B + (size_t)(n0+ar)*HIDDEN + (kt)*16 + ac4*4; \
        pb0 = *(const float4*)Bp; \
        pb1 = *(const float4*)(Bp + (size_t)64*HIDDEN); \
    } while(0)
    #define O_STS(buf) do { \
        float* Ab = As + (buf)*16*GPAD; \
        float* Bb = Bs + (buf)*16*GPAD; \
        Ab[(ac4*4+0)*GPAD + ar] = pa0.x; Ab[(ac4*4+1)*GPAD + ar] = pa0.y; \
        Ab[(ac4*4+2)*GPAD + ar] = pa0.z; Ab[(ac4*4+3)*GPAD + ar] = pa0.w; \
        Ab[(ac4*4+0)*GPAD + ar+64] = pa1.x; Ab[(ac4*4+1)*GPAD + ar+64] = pa1.y; \
        Ab[(ac4*4+2)*GPAD + ar+64] = pa1.z; Ab[(ac4*4+3)*GPAD + ar+64] = pa1.w; \
        Bb[(ac4*4+0)*GPAD + ar] = pb0.x; Bb[(ac4*4+1)*GPAD + ar] = pb0.y; \
        Bb[(ac4*4+2)*GPAD + ar] = pb0.z; Bb[(ac4*4+3)*GPAD + ar] = pb0.w; \
        Bb[(ac4*4+0)*GPAD + ar+64] = pb1.x; Bb[(ac4*4+1)*GPAD + ar+64] = pb1.y; \
        Bb[(ac4*4+2)*GPAD + ar+64] = pb1.z; Bb[(ac4*4+3)*GPAD + ar+64] = pb1.w; \
    } while(0)

    O_LDG(0);
    O_STS(0);
    __syncthreads();

    int aull = wm*16 + lm*4;
    int boff = wn*64 + ln*8;
    for (int kt = 0; kt < 48; ++kt) {
        int buf = kt & 1;
        if (kt < 47) O_LDG(kt+1);
        const float* Ab = As + buf*16*GPAD;
        const float* Bb = Bs + buf*16*GPAD;
        #pragma unroll
        for (int k = 0; k < 16; ++k) {
            const ull* Arow = (const ull*)(Ab + k*GPAD);
            ulonglong2 aA = *(const ulonglong2*)&Arow[aull];
            ulonglong2 aB = *(const ulonglong2*)&Arow[aull+2];
            ull am[4] = {aA.x, aA.y, aB.x, aB.y};
            const float* Brow = Bb + k*GPAD + boff;
            float4 bl = *(const float4*)Brow;
            float4 bh = *(const float4*)(Brow+4);
            ull bd[8];
            bd[0]=dup2(bl.x); bd[1]=dup2(bl.y); bd[2]=dup2(bl.z); bd[3]=dup2(bl.w);
            bd[4]=dup2(bh.x); bd[5]=dup2(bh.y); bd[6]=dup2(bh.z); bd[7]=dup2(bh.w);
            #pragma unroll
            for (int p=0;p<4;p++)
                #pragma unroll
                for (int j=0;j<8;j++)
                    acc2[p][j] = ffma2(am[p], bd[j], acc2[p][j]);
        }
        if (kt < 47) {
            __syncthreads();
            O_STS(buf ^ 1);
            __syncthreads();
        }
    }

    int cb = n0 + wn*64 + ln*8;
    #pragma unroll
    for (int p=0;p<4;p++) {
        float ve[8], vo[8];
        #pragma unroll
        for (int j=0;j<8;j++) {
            float2 f = up2(acc2[p][j]);
            ve[j] = __fadd_rn(f.x, b0[cb+j]);
            vo[j] = __fadd_rn(f.y, b0[cb+j]);
        }
        int gm = m0 + wm*32 + lm*8 + 2*p;
        float* ce = C + (size_t)gm*768 + cb;
        float* co = C + (size_t)(gm+1)*768 + cb;
        *(float4*)ce     = make_float4(ve[0],ve[1],ve[2],ve[3]);
        *(float4*)(ce+4) = make_float4(ve[4],ve[5],ve[6],ve[7]);
        *(float4*)co     = make_float4(vo[0],vo[1],vo[2],vo[3]);
        *(float4*)(co+4) = make_float4(vo[4],vo[5],vo[6],vo[7]);
    }
}

// ---------------- attention scores GEMM: S[m,n] = (q[m,:].k[n,:]) * 0.125 -> g_P ----------------
#define SC_SMEM (2*64*128*4)   // 65536
__global__ void __launch_bounds__(256,1) attnSc() {
    extern __shared__ float sm[];
    float* Qs = sm;            // [d 64][m 128]
    float* Ks = sm + 64*128;   // [d 64][n 128]
    int t = threadIdx.x;
    int bh = blockIdx.x;
    int m0 = (blockIdx.y & 3) * 128;
    int n0 = (blockIdx.y >> 2) * 128;
    int w = t >> 5, lane = t & 31;
    int wm = w & 3, wn = w >> 2;
    int lm = lane & 3, ln = lane >> 2;

    {
        int r = t & 127, d0 = (t >> 7) * 32;
        const float* Qg = g_Qd + ((size_t)bh*SS + m0 + r)*HDIM + d0;
        const float* Kg = g_Kd + ((size_t)bh*SS + n0 + r)*HDIM + d0;
        #pragma unroll
        for (int j=0;j<8;j++) {
            float4 q = *(const float4*)(Qg + j*4);
            Qs[(d0+j*4+0)*128 + r] = q.x; Qs[(d0+j*4+1)*128 + r] = q.y;
            Qs[(d0+j*4+2)*128 + r] = q.z; Qs[(d0+j*4+3)*128 + r] = q.w;
            float4 k = *(const float4*)(Kg + j*4);
            Ks[(d0+j*4+0)*128 + r] = k.x; Ks[(d0+j*4+1)*128 + r] = k.y;
            Ks[(d0+j*4+2)*128 + r] = k.z; Ks[(d0+j*4+3)*128 + r] = k.w;
        }
    }
    __syncthreads();

    ull acc[4][8];
    #pragma unroll
    for (int p=0;p<4;p++)
        #pragma unroll
        for (int j=0;j<8;j++) acc[p][j]=0ULL;

    int aull = wm*16 + lm*4;
    int boff = wn*64 + ln*8;
    #pragma unroll 8
    for (int d = 0; d < 64; ++d) {
        const ull* Au = (const ull*)(Qs + d*128);
        ulonglong2 a0 = *(const ulonglong2*)&Au[aull];
        ulonglong2 a1 = *(const ulonglong2*)&Au[aull+2];
        ull am[4] = {a0.x, a0.y, a1.x, a1.y};
        const float* Brow = Ks + d*128 + boff;
        float4 bl = *(const float4*)Brow;
        float4 bh = *(const float4*)(Brow+4);
        ull bd[8];
        bd[0]=dup2(bl.x); bd[1]=dup2(bl.y); bd[2]=dup2(bl.z); bd[3]=dup2(bl.w);
        bd[4]=dup2(bh.x); bd[5]=dup2(bh.y); bd[6]=dup2(bh.z); bd[7]=dup2(bh.w);
        #pragma unroll
        for (int p=0;p<4;p++)
            #pragma unroll
            for (int j=0;j<8;j++)
                acc[p][j] = ffma2(am[p], bd[j], acc[p][j]);
    }

    int cb = n0 + wn*64 + ln*8;
    #pragma unroll
    for (int p=0;p<4;p++) {
        float ve[8], vo[8];
        #pragma unroll
        for (int j=0;j<8;j++) {
            float2 f = up2(acc[p][j]);
            ve[j] = __fmul_rn(f.x, 0.125f);
            vo[j] = __fmul_rn(f.y, 0.125f);
        }
        int gm = m0 + wm*32 + lm*8 + 2*p;
        float* se = g_P + ((size_t)bh*SS + gm)*SS + cb;
        float* so = g_P + ((size_t)bh*SS + gm + 1)*SS + cb;
        *(float4*)se     = make_float4(ve[0],ve[1],ve[2],ve[3]);
        *(float4*)(se+4) = make_float4(ve[4],ve[5],ve[6],ve[7]);
        *(float4*)so     = make_float4(vo[0],vo[1],vo[2],vo[3]);
        *(float4*)(so+4) = make_float4(vo[4],vo[5],vo[6],vo[7]);
    }
}

// ---------------- softmax: PLA exp (O(1) index), strict-seq sum, quantize -> int8 + scale ----------------
// warp per row; grid (96, 64), 8 warps/CTA.
__global__ void __launch_bounds__(256) smx(PLA pla) {
    __shared__ float eb[8][512];
    int t = threadIdx.x, w = t >> 5, lane = t & 31;
    int bh = blockIdx.x;
    int srow = blockIdx.y*8 + w;
    const float* row = g_P + ((size_t)bh*SS + srow)*SS;

    float v[16];
    #pragma unroll
    for (int j=0;j<4;j++) *(float4*)&v[j*4] = *(const float4*)&row[j*128 + lane*4];

    float mx = v[0];
    #pragma unroll
    for (int j=1;j<16;j++) mx = fmaxf(mx, v[j]);
    #pragma unroll
    for (int o=16;o>0;o>>=1) mx = fmaxf(mx, __shfl_xor_sync(0xffffffffu, mx, o));

    #pragma unroll
    for (int j = 0; j < 16; j++) {
        float sh = __fadd_rn(v[j], -mx);
        float fr = rintf(__fmul_rn(sh, 67108864.0f));
        fr = fminf(fmaxf(fr, -2147483648.0f), 2147483648.0f);
        float fx = __fmul_rn(fr, 1.4901161193847656e-8f); // * 2^-26
        float xc = fminf(fmaxf(fx, -10.0f), 0.0f);
        // O(1) uniform-interval index guess (+/-1), then exact correction vs float iv[]
        int idx = (int)floorf(__fmul_rn(__fadd_rn(xc, 10.0f), 1.2f));
        idx = idx < 0 ? 0 : (idx > 11 ? 11 : idx);
        if (idx > 0 && xc < pla.iv[idx]) idx--;
        else if (idx < 11 && xc >= pla.iv[idx+1]) idx++;
        v[j] = __fadd_rn(__fmul_rn(pla.m[idx], xc), pla.c[idx]);
    }
    #pragma unroll
    for (int j=0;j<4;j++) *(float4*)&eb[w][j*128 + lane*4] = *(float4*)&v[j*4];
    __syncwarp();

    float ssum = 0.0f;
    if (lane == 0) {                       // strict in-order 512-add chain
        const float* er = eb[w];
        #pragma unroll 8
        for (int i = 0; i < 512; i++) ssum = __fadd_rn(ssum, er[i]);
    }
    ssum = __shfl_sync(0xffffffffu, ssum, 0);
    float denom = __fadd_rn(ssum, 1e-9f);

    float qmx = 0.0f;
    #pragma unroll
    for (int j = 0; j < 16; j++) {
        float smv = __fdiv_rn(v[j], denom);
        v[j] = smv;
        qmx = fmaxf(qmx, fabsf(smv));
    }
    #pragma unroll
    for (int o=16;o>0;o>>=1) qmx = fmaxf(qmx, __shfl_xor_sync(0xffffffffu, qmx, o));
    float sp = __fdiv_rn(qmx, 127.0f);
    if (sp == 0.0f) sp = 1.0f;
    if (lane == 0) g_Psc[bh*SS + srow] = sp;
    int8_t* row8 = g_P8 + ((size_t)bh*SS + srow)*SS;
    #pragma unroll
    for (int j = 0; j < 4; j++) {
        char4 c;
        float r0 = fminf(fmaxf(rintf(__fdiv_rn(v[j*4+0], sp)), -127.0f), 127.0f);
        float r1 = fminf(fmaxf(rintf(__fdiv_rn(v[j*4+1], sp)), -127.0f), 127.0f);
        float r2 = fminf(fmaxf(rintf(__fdiv_rn(v[j*4+2], sp)), -127.0f), 127.0f);
        float r3 = fminf(fmaxf(rintf(__fdiv_rn(v[j*4+3], sp)), -127.0f), 127.0f);
        c.x = (char)(int)r0; c.y = (char)(int)r1; c.z = (char)(int)r2; c.w = (char)(int)r3;
        *(char4*)&row8[j*128 + lane*4] = c;
    }
}

// ---------------- attention P@V: int8 P from gmem (dequant inline), db V chunks ----------------
// grid (96, 4): head x 128 m-rows. 256 thr: tx(8)=8d, ty(32)=4m.
#define PV_SMEM (2*128*64*4)   // 65536
__global__ void __launch_bounds__(256,1) attnPV() {
    extern __shared__ float Vs[];          // [2][128][64]
    int t = threadIdx.x;
    int tx = t & 7, ty = t >> 3;
    int bh = blockIdx.x;
    int m0 = blockIdx.y * 128;

    const float* Vg = g_Vd + (size_t)bh*SS*HDIM;
    float4 buf[8];
    #pragma unroll
    for (int l=0;l<8;l++) buf[l] = *(const float4*)(Vg + l*1024 + t*4);
    #pragma unroll
    for (int l=0;l<8;l++) *(float4*)&Vs[l*1024 + t*4] = buf[l];
    __syncthreads();

    float sp[4];
    #pragma unroll
    for (int i=0;i<4;i++) sp[i] = g_Psc[bh*SS + m0 + ty*4 + i];

    ull acc[4][4];
    #pragma unroll
    for (int i=0;i<4;i++)
        #pragma unroll
        for (int u=0;u<4;u++) acc[i][u]=0ULL;

    const int8_t* Pg = g_P8 + ((size_t)bh*SS + m0 + ty*4)*SS;
    for (int kc = 0; kc < 4; ++kc) {       // ascending k chunks
        if (kc < 3) {
            const float* src = Vg + (kc+1)*8192;
            #pragma unroll
            for (int l=0;l<8;l++) buf[l] = *(const float4*)(src + l*1024 + t*4);
        }
        const ull* Vu = (const ull*)(Vs + (kc&1)*8192);
        #pragma unroll 4
        for (int kb = 0; kb < 32; ++kb) {
            float pa[4][4];
            #pragma unroll
            for (int i=0;i<4;i++) {
                char4 c = *(const char4*)&Pg[(size_t)i*SS + kc*128 + kb*4];
                pa[i][0] = __fmul_rn((float)c.x, sp[i]);
                pa[i][1] = __fmul_rn((float)c.y, sp[i]);
                pa[i][2] = __fmul_rn((float)c.z, sp[i]);
                pa[i][3] = __fmul_rn((float)c.w, sp[i]);
            }
            #pragma unroll
            for (int kk = 0; kk < 4; ++kk) {    // ascending k, fused fma per output
                int k = kb*4 + kk;
                ulonglong2 v0 = *(const ulonglong2*)&Vu[k*32 + tx*4];
                ulonglong2 v1 = *(const ulonglong2*)&Vu[k*32 + tx*4 + 2];
                ull vp[4] = {v0.x, v0.y, v1.x, v1.y};
                #pragma unroll
                for (int i=0;i<4;i++) {
                    ull pd = dup2(pa[i][kk]);
                    acc[i][0] = ffma2(pd, vp[0], acc[i][0]);
                    acc[i][1] = ffma2(pd, vp[1], acc[i][1]);
                    acc[i][2] = ffma2(pd, vp[2], acc[i][2]);
                    acc[i][3] = ffma2(pd, vp[3], acc[i][3]);
                }
            }
        }
        if (kc < 3) {
            __syncthreads();
            float* dstb = Vs + ((kc+1)&1)*8192;
            #pragma unroll
            for (int l=0;l<8;l++) *(float4*)&dstb[l*1024 + t*4] = buf[l];
            __syncthreads();
        }
    }
    int b = bh / NHEADS, h = bh % NHEADS;
    #pragma unroll
    for (int i=0;i<4;i++) {
        int s = m0 + ty*4 + i;
        float* Co = g_CTX + ((size_t)(b*SS + s))*HIDDEN + h*HDIM + tx*8;
        float2 f0 = up2(acc[i][0]), f1 = up2(acc[i][1]);
        float2 f2 = up2(acc[i][2]), f3 = up2(acc[i][3]);
        *(float4*)Co     = make_float4(f0.x, f0.y, f1.x, f1.y);
        *(float4*)(Co+4) = make_float4(f2.x, f2.y, f3.x, f3.y);
    }
}

// ---------------- host: replicate np.polyfit coefficients in double ----------------
static void build_pla(PLA& p) {
    double xs[1001], ys[1001];
    double step = 10.0 / 1000.0;
    for (int j = 0; j <= 1000; j++) xs[j] = -10.0 + (double)j * step;
    xs[1000] = 0.0;
    for (int j = 0; j <= 1000; j++) ys[j] = exp(xs[j]);
    double iv[13];
    double st2 = 10.0 / 12.0;
    for (int i = 0; i < 13; i++) iv[i] = -10.0 + (double)i * st2;
    iv[12] = 0.0;
    for (int i = 0; i < 12; i++) {
        double a = iv[i], b = iv[i+1];
        double n = 0, Sx = 0, Sy = 0, Sxx = 0, Sxy = 0;
        for (int j = 0; j <= 1000; j++) {
            if (xs[j] >= a && xs[j] <= b) {
                n += 1.0; Sx += xs[j]; Sy += ys[j];
                Sxx += xs[j]*xs[j]; Sxy += xs[j]*ys[j];
            }
        }
        double m = (n*Sxy - Sx*Sy) / (n*Sxx - Sx*Sx);
        double c = (Sy - m*Sx) / n;
        p.m[i] = (float)m;
        p.c[i] = (float)c;
    }
    for (int i = 0; i < 13; i++) p.iv[i] = (float)iv[i];
}

extern "C" void kernel_launch(void* const* d_in, const int* in_sizes, int n_in,
                              void* d_out, int out_size) {
    (void)in_sizes; (void)n_in; (void)out_size;
    const float* hs = (const float*)d_in[0];
    const float* Wq = (const float*)d_in[1];
    const float* bq = (const float*)d_in[2];
    const float* Wk = (const float*)d_in[3];
    const float* bk = (const float*)d_in[4];
    const float* Wv = (const float*)d_in[5];
    const float* bv = (const float*)d_in[6];
    const float* Wo = (const float*)d_in[7];
    const float* bo = (const float*)d_in[8];

    void *pXd, *pWd, *pWod, *pCTX, *pCd, *pQd, *pKd, *pVd;
    cudaGetSymbolAddress(&pXd, g_Xd);
    cudaGetSymbolAddress(&pWd, g_Wd);
    cudaGetSymbolAddress(&pWod, g_Wod);
    cudaGetSymbolAddress(&pCTX, g_CTX);
    cudaGetSymbolAddress(&pCd, g_Cd);
    cudaGetSymbolAddress(&pQd, g_Qd);
    cudaGetSymbolAddress(&pKd, g_Kd);
    cudaGetSymbolAddress(&pVd, g_Vd);

    PLA pla;
    build_pla(pla);

    // 1) fake-quant (dequant fp32) activations + all weights (warp per row)
    wrowquant_all<<<896, 256>>>(hs, Wq, Wk, Wv, Wo,
                                (float*)pXd, (float*)pWd, (float*)pWod);

    // 2) QKV projection (256x128 FFMA2 GEMM) + per-head quantize epilogue
    cudaFuncSetAttribute(gemmQKV, cudaFuncAttributeMaxDynamicSharedMemorySize, QKV_SMEM);
    gemmQKV<<<dim3(18, 16), 256, QKV_SMEM>>>((const float*)pXd, (const float*)pWd,
                                             bq, bk, bv,
                                             (float*)pQd, (float*)pKd, (float*)pVd);

    // 3) scores GEMM -> g_P ; softmax -> int8 P ; P@V
    cudaFuncSetAttribute(attnSc, cudaFuncAttributeMaxDynamicSharedMemorySize, SC_SMEM);
    attnSc<<<dim3(96, 16), 256, SC_SMEM>>>();
    smx<<<dim3(96, 64), 256>>>(pla);
    cudaFuncSetAttribute(attnPV, cudaFuncAttributeMaxDynamicSharedMemorySize, PV_SMEM);
    attnPV<<<dim3(96, 4), 256, PV_SMEM>>>();

    // 4) fake-quant ctx rows + output projection
    wrowquant_one<<<512, 256>>>((const float*)pCTX, (float*)pCd);
    gemmOut<<<dim3(6, 32), 256>>>((const float*)pCd, (const float*)pWod, bo, (float*)d_out);
}

// round 8
// speedup vs baseline: 1.5643x; 1.0377x over previous
#include <cuda_runtime.h>
#include <cstdint>
#include <cmath>

#define HIDDEN 768
#define NHEADS 12
#define HDIM 64
#define BB 8
#define SS 512
#define ROWS (BB*SS)              // 4096
#define HEADROWS (BB*NHEADS*SS)   // 49152

// ---------------- scratch (static device allocations; no cudaMalloc) ----------------
__device__ float g_Xd[(size_t)ROWS*HIDDEN];        // dequant hidden_states
__device__ float g_Wd[(size_t)3*HIDDEN*HIDDEN];    // dequant Wq|Wk|Wv
__device__ float g_Wod[(size_t)HIDDEN*HIDDEN];     // dequant Wo
__device__ float g_Qd[(size_t)HEADROWS*HDIM];      // dequant per-head q
__device__ float g_Kd[(size_t)HEADROWS*HDIM];
__device__ float g_Vd[(size_t)HEADROWS*HDIM];
__device__ float g_P [(size_t)HEADROWS*SS];        // scores, then (in-place) dequant probs
__device__ float g_CTX[(size_t)ROWS*HIDDEN];
__device__ float g_Cd[(size_t)ROWS*HIDDEN];        // dequant quantized ctx

struct PLA { float m[12]; float c[12]; float iv[13]; };

typedef unsigned long long ull;

// packed f32x2 FMA: two independent IEEE RN fmas in one instruction (FFMA2)
__device__ __forceinline__ ull ffma2(ull a, ull b, ull c) {
    ull d;
    asm("fma.rn.f32x2 %0, %1, %2, %3;" : "=l"(d) : "l"(a), "l"(b), "l"(c));
    return d;
}
__device__ __forceinline__ float2 up2(ull v) {
    float2 r;
    asm("mov.b64 {%0, %1}, %2;" : "=f"(r.x), "=f"(r.y) : "l"(v));
    return r;
}
__device__ __forceinline__ ull dup2(float x) {
    ull d;
    asm("mov.b64 %0, {%1, %1};" : "=l"(d) : "f"(x));
    return d;
}
// Markstein correctly-rounded division given y = __frcp_rn(d). Bit-identical to __fdiv_rn(v,d).
__device__ __forceinline__ float divm(float v, float d, float y) {
    float q0 = __fmul_rn(v, y);
    float r  = __fmaf_rn(-q0, d, v);
    return __fmaf_rn(r, y, q0);
}

// ---------------- warp-per-row (768) symmetric int8 fake-quant -> dequant fp32 ----------------
__device__ __forceinline__ void wrow_body(const float* __restrict__ x,
                                          float* __restrict__ d, int lane) {
    float v[24];
    #pragma unroll
    for (int j=0;j<6;j++) *(float4*)&v[j*4] = *(const float4*)&x[j*128 + lane*4];
    float mx = fabsf(v[0]);
    #pragma unroll
    for (int j=1;j<24;j++) mx = fmaxf(mx, fabsf(v[j]));
    #pragma unroll
    for (int o=16;o>0;o>>=1) mx = fmaxf(mx, __shfl_xor_sync(0xffffffffu, mx, o));
    float sc = __fdiv_rn(mx, 127.0f);
    if (sc == 0.0f) sc = 1.0f;
    float y = __frcp_rn(sc);
    #pragma unroll
    for (int j=0;j<24;j++)
        v[j] = __fmul_rn(fminf(fmaxf(rintf(divm(v[j], sc, y)), -127.0f), 127.0f), sc);
    #pragma unroll
    for (int j=0;j<6;j++) *(float4*)&d[j*128 + lane*4] = *(float4*)&v[j*4];
}

// merged: X (4096 rows) + Wq + Wk + Wv + Wo (768 each) = 7168 rows, warp per row
__global__ void __launch_bounds__(256) wrowquant_all(const float* __restrict__ x,
                             const float* __restrict__ wq, const float* __restrict__ wk,
                             const float* __restrict__ wv, const float* __restrict__ wo,
                             float* __restrict__ xd, float* __restrict__ wd,
                             float* __restrict__ wod) {
    int row = blockIdx.x*8 + (threadIdx.x>>5);
    int lane = threadIdx.x & 31;
    const float* src; float* dst; int r;
    if (row < 4096)      { r = row;      src = x;  dst = xd; }
    else if (row < 4864) { r = row-4096; src = wq; dst = wd; }
    else if (row < 5632) { r = row-4864; src = wk; dst = wd + (size_t)HIDDEN*HIDDEN; }
    else if (row < 6400) { r = row-5632; src = wv; dst = wd + (size_t)2*HIDDEN*HIDDEN; }
    else                 { r = row-6400; src = wo; dst = wod; }
    wrow_body(src + (size_t)r*HIDDEN, dst + (size_t)r*HIDDEN, lane);
}

__global__ void __launch_bounds__(256) wrowquant_one(const float* __restrict__ src,
                                                     float* __restrict__ dst) {
    int row = blockIdx.x*8 + (threadIdx.x>>5);
    int lane = threadIdx.x & 31;
    wrow_body(src + (size_t)row*HIDDEN, dst + (size_t)row*HIDDEN, lane);
}

// ---------------- QKV GEMM 256x128, 16m x 8n per thread, FFMA2 m-pairs, db smem ----------------
#define QKV_APAD 260
#define QKV_BPAD 132
#define QKV_SMEM ((2*16*QKV_APAD + 2*16*QKV_BPAD)*4)   // 50176
__global__ void __launch_bounds__(256,1) gemmQKV(const float* __restrict__ A,
                                                 const float* __restrict__ B,
                                                 const float* __restrict__ b0,
                                                 const float* __restrict__ b1,
                                                 const float* __restrict__ b2,
                                                 float* __restrict__ Qd,
                                                 float* __restrict__ Kd,
                                                 float* __restrict__ Vd) {
    extern __shared__ float sm[];
    float* As = sm;                        // [2][16][260]
    float* Bs = sm + 2*16*QKV_APAD;        // [2][16][132]
    int t = threadIdx.x;
    int m0 = blockIdx.y * 256;
    int n0 = blockIdx.x * 128;
    int w = t >> 5, lane = t & 31;
    int wm = w & 3, wn = w >> 2;           // warp: 64m x 64n
    int lm = lane & 3, ln = lane >> 2;     // lane: 16m x 8n
    int ar = t >> 2, ac4 = t & 3;

    ull acc[8][8];
    #pragma unroll
    for (int p=0;p<8;p++)
        #pragma unroll
        for (int j=0;j<8;j++) acc[p][j]=0ULL;

    float4 pa[4], pb[2];
    #define Q_LDG(kt) do { \
        const float* Ap = A + (size_t)(m0+ar)*HIDDEN + (kt)*16 + ac4*4; \
        pa[0] = *(const float4*)Ap; \
        pa[1] = *(const float4*)(Ap + (size_t)64*HIDDEN); \
        pa[2] = *(const float4*)(Ap + (size_t)128*HIDDEN); \
        pa[3] = *(const float4*)(Ap + (size_t)192*HIDDEN); \
        const float* Bp = B + (size_t)(n0+ar)*HIDDEN + (kt)*16 + ac4*4; \
        pb[0] = *(const float4*)Bp; \
        pb[1] = *(const float4*)(Bp + (size_t)64*HIDDEN); \
    } while(0)
    #define Q_STS(buf) do { \
        float* Ab = As + (buf)*16*QKV_APAD; \
        float* Bb = Bs + (buf)*16*QKV_BPAD; \
        _Pragma("unroll") \
        for (int l=0;l<4;l++) { \
            Ab[(ac4*4+0)*QKV_APAD + ar + 64*l] = pa[l].x; \
            Ab[(ac4*4+1)*QKV_APAD + ar + 64*l] = pa[l].y; \
            Ab[(ac4*4+2)*QKV_APAD + ar + 64*l] = pa[l].z; \
            Ab[(ac4*4+3)*QKV_APAD + ar + 64*l] = pa[l].w; \
        } \
        _Pragma("unroll") \
        for (int l=0;l<2;l++) { \
            Bb[(ac4*4+0)*QKV_BPAD + ar + 64*l] = pb[l].x; \
            Bb[(ac4*4+1)*QKV_BPAD + ar + 64*l] = pb[l].y; \
            Bb[(ac4*4+2)*QKV_BPAD + ar + 64*l] = pb[l].z; \
            Bb[(ac4*4+3)*QKV_BPAD + ar + 64*l] = pb[l].w; \
        } \
    } while(0)

    Q_LDG(0);
    Q_STS(0);
    __syncthreads();

    int aull = wm*32 + lm*8;
    int boff = wn*64 + ln*8;
    for (int kt = 0; kt < 48; ++kt) {
        int buf = kt & 1;
        if (kt < 47) Q_LDG(kt+1);
        const float* Ab = As + buf*16*QKV_APAD;
        const float* Bb = Bs + buf*16*QKV_BPAD;
        #pragma unroll
        for (int k = 0; k < 16; ++k) {     // ascending k; fused fma per output
            const ull* Au = (const ull*)(Ab + k*QKV_APAD);
            ulonglong2 a0 = *(const ulonglong2*)&Au[aull];
            ulonglong2 a1 = *(const ulonglong2*)&Au[aull+2];
            ulonglong2 a2 = *(const ulonglong2*)&Au[aull+4];
            ulonglong2 a3 = *(const ulonglong2*)&Au[aull+6];
            ull am[8] = {a0.x,a0.y,a1.x,a1.y,a2.x,a2.y,a3.x,a3.y};
            const float* Brow = Bb + k*QKV_BPAD + boff;
            float4 bl = *(const float4*)Brow;
            float4 bh = *(const float4*)(Brow+4);
            ull bd[8];
            bd[0]=dup2(bl.x); bd[1]=dup2(bl.y); bd[2]=dup2(bl.z); bd[3]=dup2(bl.w);
            bd[4]=dup2(bh.x); bd[5]=dup2(bh.y); bd[6]=dup2(bh.z); bd[7]=dup2(bh.w);
            #pragma unroll
            for (int p=0;p<8;p++)
                #pragma unroll
                for (int j=0;j<8;j++)
                    acc[p][j] = ffma2(am[p], bd[j], acc[p][j]);
        }
        if (kt < 47) {
            __syncthreads();
            Q_STS(buf ^ 1);
            __syncthreads();
        }
    }

    // epilogue: bias + per-head (64) quantize -> Qd/Kd/Vd
    int nrel = n0 % 768;
    int tsel = n0 / 768;
    const float* bias = (tsel==0) ? b0 : (tsel==1 ? b1 : b2);
    float* dstbase = (tsel==0) ? Qd : (tsel==1 ? Kd : Vd);
    int hh = (nrel >> 6) + wn;
    int cb = nrel + wn*64 + ln*8;
    #pragma unroll
    for (int p=0;p<8;p++) {
        float ve[8], vo[8];
        #pragma unroll
        for (int j=0;j<8;j++) {
            float2 f = up2(acc[p][j]);
            ve[j] = __fadd_rn(f.x, bias[cb+j]);
            vo[j] = __fadd_rn(f.y, bias[cb+j]);
        }
        #pragma unroll
        for (int half=0; half<2; ++half) {
            float* v = half ? vo : ve;
            int gm = m0 + wm*64 + lm*16 + 2*p + half;
            float mxv = fabsf(v[0]);
            #pragma unroll
            for (int j=1;j<8;j++) mxv = fmaxf(mxv, fabsf(v[j]));
            mxv = fmaxf(mxv, __shfl_xor_sync(0xffffffffu, mxv, 4));
            mxv = fmaxf(mxv, __shfl_xor_sync(0xffffffffu, mxv, 8));
            mxv = fmaxf(mxv, __shfl_xor_sync(0xffffffffu, mxv, 16));
            float sc = __fdiv_rn(mxv, 127.0f);
            if (sc == 0.0f) sc = 1.0f;
            float y = __frcp_rn(sc);
            float q[8];
            #pragma unroll
            for (int j=0;j<8;j++)
                q[j] = __fmul_rn(fminf(fmaxf(rintf(divm(v[j], sc, y)), -127.0f), 127.0f), sc);
            int b = gm >> 9, s = gm & 511;
            float* drow = dstbase + ((size_t)((b*NHEADS + hh)*SS + s))*HDIM + ln*8;
            *(float4*)drow       = make_float4(q[0],q[1],q[2],q[3]);
            *(float4*)(drow + 4) = make_float4(q[4],q[5],q[6],q[7]);
        }
    }
}

// ---------------- out projection GEMM 64x128, 8m x 4n per thread, 2 CTAs/SM ----------------
#define GPAD 136
__global__ void __launch_bounds__(256,2) gemmOut(const float* __restrict__ A,
                                                 const float* __restrict__ B,
                                                 const float* __restrict__ b0,
                                                 float* __restrict__ C) {
    __shared__ __align__(16) float As[2*16*72];
    __shared__ __align__(16) float Bs[2*16*GPAD];
    int t = threadIdx.x;
    int m0 = blockIdx.y * 64;
    int n0 = blockIdx.x * 128;
    int w = t >> 5, lane = t & 31;
    int wm = w & 1, wn = w >> 1;           // warps: 2m x 4n -> 32m x 32n each
    int lm = lane & 3, ln = lane >> 2;     // lanes: 4m x 8n -> 8m x 4n each
    int ar4 = t >> 2, ac4 = t & 3;

    ull acc2[4][4];
    #pragma unroll
    for (int p=0;p<4;p++)
        #pragma unroll
        for (int j=0;j<4;j++) acc2[p][j]=0ULL;

    float4 pa0, pb0, pb1;
    #define O_LDG(kt) do { \
        pa0 = *(const float4*)(A + (size_t)(m0 + ar4)*HIDDEN + (kt)*16 + ac4*4); \
        const float* Bp = B + (size_t)(n0+ar4)*HIDDEN + (kt)*16 + ac4*4; \
        pb0 = *(const float4*)Bp; \
        pb1 = *(const float4*)(Bp + (size_t)64*HIDDEN); \
    } while(0)
    #define O_STS(buf) do { \
        float* Ab = As + (buf)*16*72; \
        float* Bb = Bs + (buf)*16*GPAD; \
        Ab[(ac4*4+0)*72 + ar4] = pa0.x; Ab[(ac4*4+1)*72 + ar4] = pa0.y; \
        Ab[(ac4*4+2)*72 + ar4] = pa0.z; Ab[(ac4*4+3)*72 + ar4] = pa0.w; \
        Bb[(ac4*4+0)*GPAD + ar4] = pb0.x; Bb[(ac4*4+1)*GPAD + ar4] = pb0.y; \
        Bb[(ac4*4+2)*GPAD + ar4] = pb0.z; Bb[(ac4*4+3)*GPAD + ar4] = pb0.w; \
        Bb[(ac4*4+0)*GPAD + ar4+64] = pb1.x; Bb[(ac4*4+1)*GPAD + ar4+64] = pb1.y; \
        Bb[(ac4*4+2)*GPAD + ar4+64] = pb1.z; Bb[(ac4*4+3)*GPAD + ar4+64] = pb1.w; \
    } while(0)

    O_LDG(0);
    O_STS(0);
    __syncthreads();

    int aull = wm*16 + lm*4;               // 8 m = 4 ull
    int boff = wn*32 + ln*4;
    for (int kt = 0; kt < 48; ++kt) {
        int buf = kt & 1;
        if (kt < 47) O_LDG(kt+1);
        const float* Ab = As + buf*16*72;
        const float* Bb = Bs + buf*16*GPAD;
        #pragma unroll
        for (int k = 0; k < 16; ++k) {     // ascending k; fused fma per output
            const ull* Arow = (const ull*)(Ab + k*72);
            ulonglong2 aA = *(const ulonglong2*)&Arow[aull];
            ulonglong2 aB = *(const ulonglong2*)&Arow[aull+2];
            ull am[4] = {aA.x, aA.y, aB.x, aB.y};
            float4 bl = *(const float4*)(Bb + k*GPAD + boff);
            ull bd[4];
            bd[0]=dup2(bl.x); bd[1]=dup2(bl.y); bd[2]=dup2(bl.z); bd[3]=dup2(bl.w);
            #pragma unroll
            for (int p=0;p<4;p++)
                #pragma unroll
                for (int j=0;j<4;j++)
                    acc2[p][j] = ffma2(am[p], bd[j], acc2[p][j]);
        }
        if (kt < 47) {
            __syncthreads();
            O_STS(buf ^ 1);
            __syncthreads();
        }
    }

    int cb = n0 + wn*32 + ln*4;
    #pragma unroll
    for (int p=0;p<4;p++) {
        float ve[4], vo[4];
        #pragma unroll
        for (int j=0;j<4;j++) {
            float2 f = up2(acc2[p][j]);
            ve[j] = __fadd_rn(f.x, b0[cb+j]);
            vo[j] = __fadd_rn(f.y, b0[cb+j]);
        }
        int gm = m0 + wm*32 + lm*8 + 2*p;
        *(float4*)(C + (size_t)gm*768 + cb)     = make_float4(ve[0],ve[1],ve[2],ve[3]);
        *(float4*)(C + (size_t)(gm+1)*768 + cb) = make_float4(vo[0],vo[1],vo[2],vo[3]);
    }
}

// ---------------- attention scores GEMM: S[m,n] = (q[m,:].k[n,:]) * 0.125 -> g_P ----------------
#define SC_SMEM (2*64*128*4)   // 65536
__global__ void __launch_bounds__(256,1) attnSc() {
    extern __shared__ float sm[];
    float* Qs = sm;            // [d 64][m 128]
    float* Ks = sm + 64*128;   // [d 64][n 128]
    int t = threadIdx.x;
    int bh = blockIdx.x;
    int m0 = (blockIdx.y & 3) * 128;
    int n0 = (blockIdx.y >> 2) * 128;
    int w = t >> 5, lane = t & 31;
    int wm = w & 3, wn = w >> 2;
    int lm = lane & 3, ln = lane >> 2;

    {
        int r = t & 127, d0 = (t >> 7) * 32;
        const float* Qg = g_Qd + ((size_t)bh*SS + m0 + r)*HDIM + d0;
        const float* Kg = g_Kd + ((size_t)bh*SS + n0 + r)*HDIM + d0;
        #pragma unroll
        for (int j=0;j<8;j++) {
            float4 q = *(const float4*)(Qg + j*4);
            Qs[(d0+j*4+0)*128 + r] = q.x; Qs[(d0+j*4+1)*128 + r] = q.y;
            Qs[(d0+j*4+2)*128 + r] = q.z; Qs[(d0+j*4+3)*128 + r] = q.w;
            float4 k = *(const float4*)(Kg + j*4);
            Ks[(d0+j*4+0)*128 + r] = k.x; Ks[(d0+j*4+1)*128 + r] = k.y;
            Ks[(d0+j*4+2)*128 + r] = k.z; Ks[(d0+j*4+3)*128 + r] = k.w;
        }
    }
    __syncthreads();

    ull acc[4][8];
    #pragma unroll
    for (int p=0;p<4;p++)
        #pragma unroll
        for (int j=0;j<8;j++) acc[p][j]=0ULL;

    int aull = wm*16 + lm*4;
    int boff = wn*64 + ln*8;
    #pragma unroll 8
    for (int d = 0; d < 64; ++d) {
        const ull* Au = (const ull*)(Qs + d*128);
        ulonglong2 a0 = *(const ulonglong2*)&Au[aull];
        ulonglong2 a1 = *(const ulonglong2*)&Au[aull+2];
        ull am[4] = {a0.x, a0.y, a1.x, a1.y};
        const float* Brow = Ks + d*128 + boff;
        float4 bl = *(const float4*)Brow;
        float4 bh = *(const float4*)(Brow+4);
        ull bd[8];
        bd[0]=dup2(bl.x); bd[1]=dup2(bl.y); bd[2]=dup2(bl.z); bd[3]=dup2(bl.w);
        bd[4]=dup2(bh.x); bd[5]=dup2(bh.y); bd[6]=dup2(bh.z); bd[7]=dup2(bh.w);
        #pragma unroll
        for (int p=0;p<4;p++)
            #pragma unroll
            for (int j=0;j<8;j++)
                acc[p][j] = ffma2(am[p], bd[j], acc[p][j]);
    }

    int cb = n0 + wn*64 + ln*8;
    #pragma unroll
    for (int p=0;p<4;p++) {
        float ve[8], vo[8];
        #pragma unroll
        for (int j=0;j<8;j++) {
            float2 f = up2(acc[p][j]);
            ve[j] = __fmul_rn(f.x, 0.125f);
            vo[j] = __fmul_rn(f.y, 0.125f);
        }
        int gm = m0 + wm*32 + lm*8 + 2*p;
        float* se = g_P + ((size_t)bh*SS + gm)*SS + cb;
        float* so = g_P + ((size_t)bh*SS + gm + 1)*SS + cb;
        *(float4*)se     = make_float4(ve[0],ve[1],ve[2],ve[3]);
        *(float4*)(se+4) = make_float4(ve[4],ve[5],ve[6],ve[7]);
        *(float4*)so     = make_float4(vo[0],vo[1],vo[2],vo[3]);
        *(float4*)(so+4) = make_float4(vo[4],vo[5],vo[6],vo[7]);
    }
}

// ---------------- softmax (in-place on g_P): PLA exp (smem tables), Markstein divs ----------------
// warp per row; grid (96, 64), 8 warps/CTA.
__global__ void __launch_bounds__(256) smx(PLA pla) {
    __shared__ float eb[8][512];
    __shared__ float2 sm_mc[12];   // (m, c)
    __shared__ float2 sm_iv2[12];  // (iv[i], iv[i+1])
    int t = threadIdx.x, w = t >> 5, lane = t & 31;
    if (t < 12) {
        sm_mc[t]  = make_float2(pla.m[t], pla.c[t]);
        sm_iv2[t] = make_float2(pla.iv[t], pla.iv[t+1]);
    }
    __syncthreads();
    int bh = blockIdx.x;
    int srow = blockIdx.y*8 + w;
    float* row = g_P + ((size_t)bh*SS + srow)*SS;

    float v[16];
    #pragma unroll
    for (int j=0;j<4;j++) *(float4*)&v[j*4] = *(const float4*)&row[j*128 + lane*4];

    float mx = v[0];
    #pragma unroll
    for (int j=1;j<16;j++) mx = fmaxf(mx, v[j]);
    #pragma unroll
    for (int o=16;o>0;o>>=1) mx = fmaxf(mx, __shfl_xor_sync(0xffffffffu, mx, o));

    #pragma unroll
    for (int j = 0; j < 16; j++) {
        float sh = __fadd_rn(v[j], -mx);
        float fr = rintf(__fmul_rn(sh, 67108864.0f));
        fr = fminf(fmaxf(fr, -2147483648.0f), 2147483648.0f);
        float fx = __fmul_rn(fr, 1.4901161193847656e-8f); // * 2^-26
        float xc = fminf(fmaxf(fx, -10.0f), 0.0f);
        // O(1) uniform-interval index guess (+/-1), exact correction vs float iv[]
        int idx = (int)floorf(__fmul_rn(__fadd_rn(xc, 10.0f), 1.2f));
        idx = idx < 0 ? 0 : (idx > 11 ? 11 : idx);
        float2 bnd = sm_iv2[idx];
        if (idx > 0 && xc < bnd.x) idx--;
        else if (idx < 11 && xc >= bnd.y) idx++;
        float2 mc = sm_mc[idx];
        v[j] = __fadd_rn(__fmul_rn(mc.x, xc), mc.y);
    }
    #pragma unroll
    for (int j=0;j<4;j++) *(float4*)&eb[w][j*128 + lane*4] = *(float4*)&v[j*4];
    __syncwarp();

    float ssum = 0.0f;
    if (lane == 0) {                       // strict in-order 512-add chain
        const float* er = eb[w];
        #pragma unroll 8
        for (int i = 0; i < 512; i++) ssum = __fadd_rn(ssum, er[i]);
    }
    ssum = __shfl_sync(0xffffffffu, ssum, 0);
    float denom = __fadd_rn(ssum, 1e-9f);
    float yd = __frcp_rn(denom);

    float qmx = 0.0f;
    #pragma unroll
    for (int j = 0; j < 16; j++) {
        float smv = divm(v[j], denom, yd);
        v[j] = smv;
        qmx = fmaxf(qmx, fabsf(smv));
    }
    #pragma unroll
    for (int o=16;o>0;o>>=1) qmx = fmaxf(qmx, __shfl_xor_sync(0xffffffffu, qmx, o));
    float sp = __fdiv_rn(qmx, 127.0f);
    if (sp == 0.0f) sp = 1.0f;
    float ys = __frcp_rn(sp);
    #pragma unroll
    for (int j = 0; j < 16; j++)
        v[j] = __fmul_rn(fminf(fmaxf(rintf(divm(v[j], sp, ys)), -127.0f), 127.0f), sp);
    #pragma unroll
    for (int j=0;j<4;j++) *(float4*)&row[j*128 + lane*4] = *(float4*)&v[j*4];
}

// ---------------- attention P@V: fp32 P from gmem, double-buffered V chunks ----------------
// grid (96, 4): head x 128 m-rows. 256 thr: tx(8)=8d, ty(32)=4m.
#define PV_SMEM (2*128*64*4)   // 65536
__global__ void __launch_bounds__(256,1) attnPV() {
    extern __shared__ float Vs[];          // [2][128][64]
    int t = threadIdx.x;
    int tx = t & 7, ty = t >> 3;
    int bh = blockIdx.x;
    int m0 = blockIdx.y * 128;

    const float* Vg = g_Vd + (size_t)bh*SS*HDIM;
    float4 buf[8];
    #pragma unroll
    for (int l=0;l<8;l++) buf[l] = *(const float4*)(Vg + l*1024 + t*4);
    #pragma unroll
    for (int l=0;l<8;l++) *(float4*)&Vs[l*1024 + t*4] = buf[l];
    __syncthreads();

    ull acc[4][4];
    #pragma unroll
    for (int i=0;i<4;i++)
        #pragma unroll
        for (int u=0;u<4;u++) acc[i][u]=0ULL;

    const float* Pg = g_P + ((size_t)bh*SS + m0 + ty*4)*SS;
    for (int kc = 0; kc < 4; ++kc) {       // ascending k chunks
        if (kc < 3) {
            const float* src = Vg + (kc+1)*8192;
            #pragma unroll
            for (int l=0;l<8;l++) buf[l] = *(const float4*)(src + l*1024 + t*4);
        }
        const ull* Vu = (const ull*)(Vs + (kc&1)*8192);
        #pragma unroll 4
        for (int kb = 0; kb < 32; ++kb) {
            float pa[4][4];
            #pragma unroll
            for (int i=0;i<4;i++)
                *(float4*)pa[i] = *(const float4*)&Pg[(size_t)i*SS + kc*128 + kb*4];
            #pragma unroll
            for (int kk = 0; kk < 4; ++kk) {    // ascending k, fused fma per output
                int k = kb*4 + kk;
                ulonglong2 v0 = *(const ulonglong2*)&Vu[k*32 + tx*4];
                ulonglong2 v1 = *(const ulonglong2*)&Vu[k*32 + tx*4 + 2];
                ull vp[4] = {v0.x, v0.y, v1.x, v1.y};
                #pragma unroll
                for (int i=0;i<4;i++) {
                    ull pd = dup2(pa[i][kk]);
                    acc[i][0] = ffma2(pd, vp[0], acc[i][0]);
                    acc[i][1] = ffma2(pd, vp[1], acc[i][1]);
                    acc[i][2] = ffma2(pd, vp[2], acc[i][2]);
                    acc[i][3] = ffma2(pd, vp[3], acc[i][3]);
                }
            }
        }
        if (kc < 3) {
            __syncthreads();
            float* dstb = Vs + ((kc+1)&1)*8192;
            #pragma unroll
            for (int l=0;l<8;l++) *(float4*)&dstb[l*1024 + t*4] = buf[l];
            __syncthreads();
        }
    }
    int b = bh / NHEADS, h = bh % NHEADS;
    #pragma unroll
    for (int i=0;i<4;i++) {
        int s = m0 + ty*4 + i;
        float* Co = g_CTX + ((size_t)(b*SS + s))*HIDDEN + h*HDIM + tx*8;
        float2 f0 = up2(acc[i][0]), f1 = up2(acc[i][1]);
        float2 f2 = up2(acc[i][2]), f3 = up2(acc[i][3]);
        *(float4*)Co     = make_float4(f0.x, f0.y, f1.x, f1.y);
        *(float4*)(Co+4) = make_float4(f2.x, f2.y, f3.x, f3.y);
    }
}

// ---------------- host: replicate np.polyfit coefficients in double ----------------
static void build_pla(PLA& p) {
    double xs[1001], ys[1001];
    double step = 10.0 / 1000.0;
    for (int j = 0; j <= 1000; j++) xs[j] = -10.0 + (double)j * step;
    xs[1000] = 0.0;
    for (int j = 0; j <= 1000; j++) ys[j] = exp(xs[j]);
    double iv[13];
    double st2 = 10.0 / 12.0;
    for (int i = 0; i < 13; i++) iv[i] = -10.0 + (double)i * st2;
    iv[12] = 0.0;
    for (int i = 0; i < 12; i++) {
        double a = iv[i], b = iv[i+1];
        double n = 0, Sx = 0, Sy = 0, Sxx = 0, Sxy = 0;
        for (int j = 0; j <= 1000; j++) {
            if (xs[j] >= a && xs[j] <= b) {
                n += 1.0; Sx += xs[j]; Sy += ys[j];
                Sxx += xs[j]*xs[j]; Sxy += xs[j]*ys[j];
            }
        }
        double m = (n*Sxy - Sx*Sy) / (n*Sxx - Sx*Sx);
        double c = (Sy - m*Sx) / n;
        p.m[i] = (float)m;
        p.c[i] = (float)c;
    }
    for (int i = 0; i < 13; i++) p.iv[i] = (float)iv[i];
}

extern "C" void kernel_launch(void* const* d_in, const int* in_sizes, int n_in,
                              void* d_out, int out_size) {
    (void)in_sizes; (void)n_in; (void)out_size;
    const float* hs = (const float*)d_in[0];
    const float* Wq = (const float*)d_in[1];
    const float* bq = (const float*)d_in[2];
    const float* Wk = (const float*)d_in[3];
    const float* bk = (const float*)d_in[4];
    const float* Wv = (const float*)d_in[5];
    const float* bv = (const float*)d_in[6];
    const float* Wo = (const float*)d_in[7];
    const float* bo = (const float*)d_in[8];

    void *pXd, *pWd, *pWod, *pCTX, *pCd, *pQd, *pKd, *pVd;
    cudaGetSymbolAddress(&pXd, g_Xd);
    cudaGetSymbolAddress(&pWd, g_Wd);
    cudaGetSymbolAddress(&pWod, g_Wod);
    cudaGetSymbolAddress(&pCTX, g_CTX);
    cudaGetSymbolAddress(&pCd, g_Cd);
    cudaGetSymbolAddress(&pQd, g_Qd);
    cudaGetSymbolAddress(&pKd, g_Kd);
    cudaGetSymbolAddress(&pVd, g_Vd);

    PLA pla;
    build_pla(pla);

    // 1) fake-quant (dequant fp32) activations + all weights (warp per row)
    wrowquant_all<<<896, 256>>>(hs, Wq, Wk, Wv, Wo,
                                (float*)pXd, (float*)pWd, (float*)pWod);

    // 2) QKV projection (256x128 FFMA2 GEMM) + per-head quantize epilogue
    cudaFuncSetAttribute(gemmQKV, cudaFuncAttributeMaxDynamicSharedMemorySize, QKV_SMEM);
    gemmQKV<<<dim3(18, 16), 256, QKV_SMEM>>>((const float*)pXd, (const float*)pWd,
                                             bq, bk, bv,
                                             (float*)pQd, (float*)pKd, (float*)pVd);

    // 3) scores GEMM -> g_P ; softmax in place ; P@V
    cudaFuncSetAttribute(attnSc, cudaFuncAttributeMaxDynamicSharedMemorySize, SC_SMEM);
    attnSc<<<dim3(96, 16), 256, SC_SMEM>>>();
    smx<<<dim3(96, 64), 256>>>(pla);
    cudaFuncSetAttribute(attnPV, cudaFuncAttributeMaxDynamicSharedMemorySize, PV_SMEM);
    attnPV<<<dim3(96, 4), 256, PV_SMEM>>>();

    // 4) fake-quant ctx rows + output projection
    wrowquant_one<<<512, 256>>>((const float*)pCTX, (float*)pCd);
    gemmOut<<<dim3(6, 64), 256>>>((const float*)pCd, (const float*)pWod, bo, (float*)d_out);
}

// round 9
// speedup vs baseline: 1.5835x; 1.0123x over previous
#include <cuda_runtime.h>
#include <cstdint>
#include <cmath>

#define HIDDEN 768
#define NHEADS 12
#define HDIM 64
#define BB 8
#define SS 512
#define ROWS (BB*SS)              // 4096
#define HEADROWS (BB*NHEADS*SS)   // 49152

// ---------------- scratch (static device allocations; no cudaMalloc) ----------------
__device__ float g_Xd[(size_t)ROWS*HIDDEN];        // dequant hidden_states
__device__ float g_Wd[(size_t)3*HIDDEN*HIDDEN];    // dequant Wq|Wk|Wv
__device__ float g_Wod[(size_t)HIDDEN*HIDDEN];     // dequant Wo
__device__ float g_Qd[(size_t)HEADROWS*HDIM];      // dequant per-head q
__device__ float g_Kd[(size_t)HEADROWS*HDIM];
__device__ float g_Vd[(size_t)HEADROWS*HDIM];
__device__ float g_P [(size_t)HEADROWS*SS];        // scores, then (in-place) dequant probs
__device__ float g_CTX[(size_t)ROWS*HIDDEN];
__device__ float g_Cd[(size_t)ROWS*HIDDEN];        // dequant quantized ctx

struct PLA { float m[12]; float c[12]; float iv[13]; };

typedef unsigned long long ull;

// packed f32x2 ops: two independent IEEE RN ops in one instruction
__device__ __forceinline__ ull ffma2(ull a, ull b, ull c) {
    ull d;
    asm("fma.rn.f32x2 %0, %1, %2, %3;" : "=l"(d) : "l"(a), "l"(b), "l"(c));
    return d;
}
__device__ __forceinline__ ull fmul2(ull a, ull b) {
    ull d;
    asm("mul.rn.f32x2 %0, %1, %2;" : "=l"(d) : "l"(a), "l"(b));
    return d;
}
__device__ __forceinline__ float2 up2(ull v) {
    float2 r;
    asm("mov.b64 {%0, %1}, %2;" : "=f"(r.x), "=f"(r.y) : "l"(v));
    return r;
}
__device__ __forceinline__ ull dup2(float x) {
    ull d;
    asm("mov.b64 %0, {%1, %1};" : "=l"(d) : "f"(x));
    return d;
}
__device__ __forceinline__ ull pk2(float a, float b) {
    ull d;
    asm("mov.b64 %0, {%1, %2};" : "=l"(d) : "f"(a), "f"(b));
    return d;
}
// Markstein correctly-rounded division given y = __frcp_rn(d). Bit-identical to __fdiv_rn(v,d).
__device__ __forceinline__ float divm(float v, float d, float y) {
    float q0 = __fmul_rn(v, y);
    float r  = __fmaf_rn(-q0, d, v);
    return __fmaf_rn(r, y, q0);
}
// packed Markstein: dn = dup2(-d), yp = dup2(y). Per-lane bit-identical to divm.
__device__ __forceinline__ ull divm2(ull vp, ull dn, ull yp) {
    ull q0 = fmul2(vp, yp);
    ull r  = ffma2(q0, dn, vp);
    return ffma2(r, yp, q0);
}

// ---------------- warp-per-row (768) symmetric int8 fake-quant -> dequant fp32 ----------------
__device__ __forceinline__ void wrow_body(const float* __restrict__ x,
                                          float* __restrict__ d, int lane) {
    float v[24];
    #pragma unroll
    for (int j=0;j<6;j++) *(float4*)&v[j*4] = *(const float4*)&x[j*128 + lane*4];
    float mx = fabsf(v[0]);
    #pragma unroll
    for (int j=1;j<24;j++) mx = fmaxf(mx, fabsf(v[j]));
    #pragma unroll
    for (int o=16;o>0;o>>=1) mx = fmaxf(mx, __shfl_xor_sync(0xffffffffu, mx, o));
    float sc = __fdiv_rn(mx, 127.0f);
    if (sc == 0.0f) sc = 1.0f;
    float y = __frcp_rn(sc);
    ull scn = dup2(-sc), yp = dup2(y), scp = dup2(sc);
    #pragma unroll
    for (int j=0;j<12;j++) {
        ull q = divm2(pk2(v[2*j], v[2*j+1]), scn, yp);
        float2 f = up2(q);
        float r0 = fminf(fmaxf(rintf(f.x), -127.0f), 127.0f);
        float r1 = fminf(fmaxf(rintf(f.y), -127.0f), 127.0f);
        float2 o = up2(fmul2(pk2(r0, r1), scp));
        v[2*j] = o.x; v[2*j+1] = o.y;
    }
    #pragma unroll
    for (int j=0;j<6;j++) *(float4*)&d[j*128 + lane*4] = *(float4*)&v[j*4];
}

// merged: X (4096 rows) + Wq + Wk + Wv + Wo (768 each) = 7168 rows, warp per row
__global__ void __launch_bounds__(256) wrowquant_all(const float* __restrict__ x,
                             const float* __restrict__ wq, const float* __restrict__ wk,
                             const float* __restrict__ wv, const float* __restrict__ wo,
                             float* __restrict__ xd, float* __restrict__ wd,
                             float* __restrict__ wod) {
    int row = blockIdx.x*8 + (threadIdx.x>>5);
    int lane = threadIdx.x & 31;
    const float* src; float* dst; int r;
    if (row < 4096)      { r = row;      src = x;  dst = xd; }
    else if (row < 4864) { r = row-4096; src = wq; dst = wd; }
    else if (row < 5632) { r = row-4864; src = wk; dst = wd + (size_t)HIDDEN*HIDDEN; }
    else if (row < 6400) { r = row-5632; src = wv; dst = wd + (size_t)2*HIDDEN*HIDDEN; }
    else                 { r = row-6400; src = wo; dst = wod; }
    wrow_body(src + (size_t)r*HIDDEN, dst + (size_t)r*HIDDEN, lane);
}

__global__ void __launch_bounds__(256) wrowquant_one(const float* __restrict__ src,
                                                     float* __restrict__ dst) {
    int row = blockIdx.x*8 + (threadIdx.x>>5);
    int lane = threadIdx.x & 31;
    wrow_body(src + (size_t)row*HIDDEN, dst + (size_t)row*HIDDEN, lane);
}

// ---------------- QKV GEMM 256x128, 16m x 8n per thread, FFMA2 m-pairs, db smem ----------------
#define QKV_APAD 260
#define QKV_BPAD 132
#define QKV_SMEM ((2*16*QKV_APAD + 2*16*QKV_BPAD)*4)   // 50176
__global__ void __launch_bounds__(256,1) gemmQKV(const float* __restrict__ A,
                                                 const float* __restrict__ B,
                                                 const float* __restrict__ b0,
                                                 const float* __restrict__ b1,
                                                 const float* __restrict__ b2,
                                                 float* __restrict__ Qd,
                                                 float* __restrict__ Kd,
                                                 float* __restrict__ Vd) {
    extern __shared__ float sm[];
    float* As = sm;                        // [2][16][260]
    float* Bs = sm + 2*16*QKV_APAD;        // [2][16][132]
    int t = threadIdx.x;
    int m0 = blockIdx.y * 256;
    int n0 = blockIdx.x * 128;
    int w = t >> 5, lane = t & 31;
    int wm = w & 3, wn = w >> 2;           // warp: 64m x 64n
    int lm = lane & 3, ln = lane >> 2;     // lane: 16m x 8n
    int ar = t >> 2, ac4 = t & 3;

    ull acc[8][8];
    #pragma unroll
    for (int p=0;p<8;p++)
        #pragma unroll
        for (int j=0;j<8;j++) acc[p][j]=0ULL;

    float4 pa[4], pb[2];
    #define Q_LDG(kt) do { \
        const float* Ap = A + (size_t)(m0+ar)*HIDDEN + (kt)*16 + ac4*4; \
        pa[0] = *(const float4*)Ap; \
        pa[1] = *(const float4*)(Ap + (size_t)64*HIDDEN); \
        pa[2] = *(const float4*)(Ap + (size_t)128*HIDDEN); \
        pa[3] = *(const float4*)(Ap + (size_t)192*HIDDEN); \
        const float* Bp = B + (size_t)(n0+ar)*HIDDEN + (kt)*16 + ac4*4; \
        pb[0] = *(const float4*)Bp; \
        pb[1] = *(const float4*)(Bp + (size_t)64*HIDDEN); \
    } while(0)
    #define Q_STS(buf) do { \
        float* Ab = As + (buf)*16*QKV_APAD; \
        float* Bb = Bs + (buf)*16*QKV_BPAD; \
        _Pragma("unroll") \
        for (int l=0;l<4;l++) { \
            Ab[(ac4*4+0)*QKV_APAD + ar + 64*l] = pa[l].x; \
            Ab[(ac4*4+1)*QKV_APAD + ar + 64*l] = pa[l].y; \
            Ab[(ac4*4+2)*QKV_APAD + ar + 64*l] = pa[l].z; \
            Ab[(ac4*4+3)*QKV_APAD + ar + 64*l] = pa[l].w; \
        } \
        _Pragma("unroll") \
        for (int l=0;l<2;l++) { \
            Bb[(ac4*4+0)*QKV_BPAD + ar + 64*l] = pb[l].x; \
            Bb[(ac4*4+1)*QKV_BPAD + ar + 64*l] = pb[l].y; \
            Bb[(ac4*4+2)*QKV_BPAD + ar + 64*l] = pb[l].z; \
            Bb[(ac4*4+3)*QKV_BPAD + ar + 64*l] = pb[l].w; \
        } \
    } while(0)

    Q_LDG(0);
    Q_STS(0);
    __syncthreads();

    int aull = wm*32 + lm*8;
    int boff = wn*64 + ln*8;
    for (int kt = 0; kt < 48; ++kt) {
        int buf = kt & 1;
        if (kt < 47) Q_LDG(kt+1);
        const float* Ab = As + buf*16*QKV_APAD;
        const float* Bb = Bs + buf*16*QKV_BPAD;
        #pragma unroll
        for (int k = 0; k < 16; ++k) {     // ascending k; fused fma per output
            const ull* Au = (const ull*)(Ab + k*QKV_APAD);
            ulonglong2 a0 = *(const ulonglong2*)&Au[aull];
            ulonglong2 a1 = *(const ulonglong2*)&Au[aull+2];
            ulonglong2 a2 = *(const ulonglong2*)&Au[aull+4];
            ulonglong2 a3 = *(const ulonglong2*)&Au[aull+6];
            ull am[8] = {a0.x,a0.y,a1.x,a1.y,a2.x,a2.y,a3.x,a3.y};
            const float* Brow = Bb + k*QKV_BPAD + boff;
            float4 bl = *(const float4*)Brow;
            float4 bh = *(const float4*)(Brow+4);
            ull bd[8];
            bd[0]=dup2(bl.x); bd[1]=dup2(bl.y); bd[2]=dup2(bl.z); bd[3]=dup2(bl.w);
            bd[4]=dup2(bh.x); bd[5]=dup2(bh.y); bd[6]=dup2(bh.z); bd[7]=dup2(bh.w);
            #pragma unroll
            for (int p=0;p<8;p++)
                #pragma unroll
                for (int j=0;j<8;j++)
                    acc[p][j] = ffma2(am[p], bd[j], acc[p][j]);
        }
        if (kt < 47) {
            __syncthreads();
            Q_STS(buf ^ 1);
            __syncthreads();
        }
    }

    // epilogue: bias + per-head (64) quantize -> Qd/Kd/Vd
    int nrel = n0 % 768;
    int tsel = n0 / 768;
    const float* bias = (tsel==0) ? b0 : (tsel==1 ? b1 : b2);
    float* dstbase = (tsel==0) ? Qd : (tsel==1 ? Kd : Vd);
    int hh = (nrel >> 6) + wn;
    int cb = nrel + wn*64 + ln*8;
    #pragma unroll
    for (int p=0;p<8;p++) {
        float ve[8], vo[8];
        #pragma unroll
        for (int j=0;j<8;j++) {
            float2 f = up2(acc[p][j]);
            ve[j] = __fadd_rn(f.x, bias[cb+j]);
            vo[j] = __fadd_rn(f.y, bias[cb+j]);
        }
        #pragma unroll
        for (int half=0; half<2; ++half) {
            float* v = half ? vo : ve;
            int gm = m0 + wm*64 + lm*16 + 2*p + half;
            float mxv = fabsf(v[0]);
            #pragma unroll
            for (int j=1;j<8;j++) mxv = fmaxf(mxv, fabsf(v[j]));
            mxv = fmaxf(mxv, __shfl_xor_sync(0xffffffffu, mxv, 4));
            mxv = fmaxf(mxv, __shfl_xor_sync(0xffffffffu, mxv, 8));
            mxv = fmaxf(mxv, __shfl_xor_sync(0xffffffffu, mxv, 16));
            float sc = __fdiv_rn(mxv, 127.0f);
            if (sc == 0.0f) sc = 1.0f;
            float y = __frcp_rn(sc);
            float q[8];
            #pragma unroll
            for (int j=0;j<8;j++)
                q[j] = __fmul_rn(fminf(fmaxf(rintf(divm(v[j], sc, y)), -127.0f), 127.0f), sc);
            int b = gm >> 9, s = gm & 511;
            float* drow = dstbase + ((size_t)((b*NHEADS + hh)*SS + s))*HDIM + ln*8;
            *(float4*)drow       = make_float4(q[0],q[1],q[2],q[3]);
            *(float4*)(drow + 4) = make_float4(q[4],q[5],q[6],q[7]);
        }
    }
}

// ---------------- out projection GEMM 64x128, 8m x 4n per thread, 2 CTAs/SM ----------------
#define GPAD 136
__global__ void __launch_bounds__(256,2) gemmOut(const float* __restrict__ A,
                                                 const float* __restrict__ B,
                                                 const float* __restrict__ b0,
                                                 float* __restrict__ C) {
    __shared__ __align__(16) float As[2*16*72];
    __shared__ __align__(16) float Bs[2*16*GPAD];
    int t = threadIdx.x;
    int m0 = blockIdx.y * 64;
    int n0 = blockIdx.x * 128;
    int w = t >> 5, lane = t & 31;
    int wm = w & 1, wn = w >> 1;           // warps: 2m x 4n -> 32m x 32n each
    int lm = lane & 3, ln = lane >> 2;     // lanes: 4m x 8n -> 8m x 4n each
    int ar4 = t >> 2, ac4 = t & 3;

    ull acc2[4][4];
    #pragma unroll
    for (int p=0;p<4;p++)
        #pragma unroll
        for (int j=0;j<4;j++) acc2[p][j]=0ULL;

    float4 pa0, pb0, pb1;
    #define O_LDG(kt) do { \
        pa0 = *(const float4*)(A + (size_t)(m0 + ar4)*HIDDEN + (kt)*16 + ac4*4); \
        const float* Bp = B + (size_t)(n0+ar4)*HIDDEN + (kt)*16 + ac4*4; \
        pb0 = *(const float4*)Bp; \
        pb1 = *(const float4*)(Bp + (size_t)64*HIDDEN); \
    } while(0)
    #define O_STS(buf) do { \
        float* Ab = As + (buf)*16*72; \
        float* Bb = Bs + (buf)*16*GPAD; \
        Ab[(ac4*4+0)*72 + ar4] = pa0.x; Ab[(ac4*4+1)*72 + ar4] = pa0.y; \
        Ab[(ac4*4+2)*72 + ar4] = pa0.z; Ab[(ac4*4+3)*72 + ar4] = pa0.w; \
        Bb[(ac4*4+0)*GPAD + ar4] = pb0.x; Bb[(ac4*4+1)*GPAD + ar4] = pb0.y; \
        Bb[(ac4*4+2)*GPAD + ar4] = pb0.z; Bb[(ac4*4+3)*GPAD + ar4] = pb0.w; \
        Bb[(ac4*4+0)*GPAD + ar4+64] = pb1.x; Bb[(ac4*4+1)*GPAD + ar4+64] = pb1.y; \
        Bb[(ac4*4+2)*GPAD + ar4+64] = pb1.z; Bb[(ac4*4+3)*GPAD + ar4+64] = pb1.w; \
    } while(0)

    O_LDG(0);
    O_STS(0);
    __syncthreads();

    int aull = wm*16 + lm*4;               // 8 m = 4 ull
    int boff = wn*32 + ln*4;
    for (int kt = 0; kt < 48; ++kt) {
        int buf = kt & 1;
        if (kt < 47) O_LDG(kt+1);
        const float* Ab = As + buf*16*72;
        const float* Bb = Bs + buf*16*GPAD;
        #pragma unroll
        for (int k = 0; k < 16; ++k) {     // ascending k; fused fma per output
            const ull* Arow = (const ull*)(Ab + k*72);
            ulonglong2 aA = *(const ulonglong2*)&Arow[aull];
            ulonglong2 aB = *(const ulonglong2*)&Arow[aull+2];
            ull am[4] = {aA.x, aA.y, aB.x, aB.y};
            float4 bl = *(const float4*)(Bb + k*GPAD + boff);
            ull bd[4];
            bd[0]=dup2(bl.x); bd[1]=dup2(bl.y); bd[2]=dup2(bl.z); bd[3]=dup2(bl.w);
            #pragma unroll
            for (int p=0;p<4;p++)
                #pragma unroll
                for (int j=0;j<4;j++)
                    acc2[p][j] = ffma2(am[p], bd[j], acc2[p][j]);
        }
        if (kt < 47) {
            __syncthreads();
            O_STS(buf ^ 1);
            __syncthreads();
        }
    }

    int cb = n0 + wn*32 + ln*4;
    #pragma unroll
    for (int p=0;p<4;p++) {
        float ve[4], vo[4];
        #pragma unroll
        for (int j=0;j<4;j++) {
            float2 f = up2(acc2[p][j]);
            ve[j] = __fadd_rn(f.x, b0[cb+j]);
            vo[j] = __fadd_rn(f.y, b0[cb+j]);
        }
        int gm = m0 + wm*32 + lm*8 + 2*p;
        *(float4*)(C + (size_t)gm*768 + cb)     = make_float4(ve[0],ve[1],ve[2],ve[3]);
        *(float4*)(C + (size_t)(gm+1)*768 + cb) = make_float4(vo[0],vo[1],vo[2],vo[3]);
    }
}

// ---------------- attention scores GEMM: S[m,n] = (q[m,:].k[n,:]) * 0.125 -> g_P ----------------
#define SC_SMEM (2*64*128*4)   // 65536
__global__ void __launch_bounds__(256,1) attnSc() {
    extern __shared__ float sm[];
    float* Qs = sm;            // [d 64][m 128]
    float* Ks = sm + 64*128;   // [d 64][n 128]
    int t = threadIdx.x;
    int bh = blockIdx.x;
    int m0 = (blockIdx.y & 3) * 128;
    int n0 = (blockIdx.y >> 2) * 128;
    int w = t >> 5, lane = t & 31;
    int wm = w & 3, wn = w >> 2;
    int lm = lane & 3, ln = lane >> 2;

    {
        int r = t & 127, d0 = (t >> 7) * 32;
        const float* Qg = g_Qd + ((size_t)bh*SS + m0 + r)*HDIM + d0;
        const float* Kg = g_Kd + ((size_t)bh*SS + n0 + r)*HDIM + d0;
        #pragma unroll
        for (int j=0;j<8;j++) {
            float4 q = *(const float4*)(Qg + j*4);
            Qs[(d0+j*4+0)*128 + r] = q.x; Qs[(d0+j*4+1)*128 + r] = q.y;
            Qs[(d0+j*4+2)*128 + r] = q.z; Qs[(d0+j*4+3)*128 + r] = q.w;
            float4 k = *(const float4*)(Kg + j*4);
            Ks[(d0+j*4+0)*128 + r] = k.x; Ks[(d0+j*4+1)*128 + r] = k.y;
            Ks[(d0+j*4+2)*128 + r] = k.z; Ks[(d0+j*4+3)*128 + r] = k.w;
        }
    }
    __syncthreads();

    ull acc[4][8];
    #pragma unroll
    for (int p=0;p<4;p++)
        #pragma unroll
        for (int j=0;j<8;j++) acc[p][j]=0ULL;

    int aull = wm*16 + lm*4;
    int boff = wn*64 + ln*8;
    #pragma unroll 8
    for (int d = 0; d < 64; ++d) {
        const ull* Au = (const ull*)(Qs + d*128);
        ulonglong2 a0 = *(const ulonglong2*)&Au[aull];
        ulonglong2 a1 = *(const ulonglong2*)&Au[aull+2];
        ull am[4] = {a0.x, a0.y, a1.x, a1.y};
        const float* Brow = Ks + d*128 + boff;
        float4 bl = *(const float4*)Brow;
        float4 bh = *(const float4*)(Brow+4);
        ull bd[8];
        bd[0]=dup2(bl.x); bd[1]=dup2(bl.y); bd[2]=dup2(bl.z); bd[3]=dup2(bl.w);
        bd[4]=dup2(bh.x); bd[5]=dup2(bh.y); bd[6]=dup2(bh.z); bd[7]=dup2(bh.w);
        #pragma unroll
        for (int p=0;p<4;p++)
            #pragma unroll
            for (int j=0;j<8;j++)
                acc[p][j] = ffma2(am[p], bd[j], acc[p][j]);
    }

    int cb = n0 + wn*64 + ln*8;
    #pragma unroll
    for (int p=0;p<4;p++) {
        float ve[8], vo[8];
        #pragma unroll
        for (int j=0;j<8;j++) {
            float2 f = up2(acc[p][j]);
            ve[j] = __fmul_rn(f.x, 0.125f);
            vo[j] = __fmul_rn(f.y, 0.125f);
        }
        int gm = m0 + wm*32 + lm*8 + 2*p;
        float* se = g_P + ((size_t)bh*SS + gm)*SS + cb;
        float* so = g_P + ((size_t)bh*SS + gm + 1)*SS + cb;
        *(float4*)se     = make_float4(ve[0],ve[1],ve[2],ve[3]);
        *(float4*)(se+4) = make_float4(ve[4],ve[5],ve[6],ve[7]);
        *(float4*)so     = make_float4(vo[0],vo[1],vo[2],vo[3]);
        *(float4*)(so+4) = make_float4(vo[4],vo[5],vo[6],vo[7]);
    }
}

// ---------------- softmax (in-place on g_P): PLA exp, packed Markstein divs ----------------
// warp per row; grid (96, 64), 8 warps/CTA.
__global__ void __launch_bounds__(256) smx(PLA pla) {
    __shared__ float eb[8][512];
    __shared__ float2 sm_mc[12];   // (m, c)
    __shared__ float2 sm_iv2[12];  // (iv[i], iv[i+1])
    int t = threadIdx.x, w = t >> 5, lane = t & 31;
    if (t < 12) {
        sm_mc[t]  = make_float2(pla.m[t], pla.c[t]);
        sm_iv2[t] = make_float2(pla.iv[t], pla.iv[t+1]);
    }
    __syncthreads();
    int bh = blockIdx.x;
    int srow = blockIdx.y*8 + w;
    float* row = g_P + ((size_t)bh*SS + srow)*SS;

    float v[16];
    #pragma unroll
    for (int j=0;j<4;j++) *(float4*)&v[j*4] = *(const float4*)&row[j*128 + lane*4];

    float mx = v[0];
    #pragma unroll
    for (int j=1;j<16;j++) mx = fmaxf(mx, v[j]);
    #pragma unroll
    for (int o=16;o>0;o>>=1) mx = fmaxf(mx, __shfl_xor_sync(0xffffffffu, mx, o));

    float amax = 0.0f;   // max |e| over this thread's elements (folded)
    #pragma unroll
    for (int j = 0; j < 16; j++) {
        float sh = __fadd_rn(v[j], -mx);
        float fr = rintf(__fmul_rn(sh, 67108864.0f));
        fr = fminf(fmaxf(fr, -2147483648.0f), 2147483648.0f);
        float fx = __fmul_rn(fr, 1.4901161193847656e-8f); // * 2^-26
        float xc = fminf(fmaxf(fx, -10.0f), 0.0f);
        // O(1) uniform-interval index guess (+/-1), exact correction vs float iv[]
        int idx = (int)floorf(__fmul_rn(__fadd_rn(xc, 10.0f), 1.2f));
        idx = idx < 0 ? 0 : (idx > 11 ? 11 : idx);
        float2 bnd = sm_iv2[idx];
        if (idx > 0 && xc < bnd.x) idx--;
        else if (idx < 11 && xc >= bnd.y) idx++;
        float2 mc = sm_mc[idx];
        float e = __fadd_rn(__fmul_rn(mc.x, xc), mc.y);
        v[j] = e;
        amax = fmaxf(amax, fabsf(e));
    }
    #pragma unroll
    for (int j=0;j<4;j++) *(float4*)&eb[w][j*128 + lane*4] = *(float4*)&v[j*4];
    __syncwarp();

    float ssum = 0.0f;
    if (lane == 0) {                       // strict in-order 512-add chain
        const float* er = eb[w];
        #pragma unroll 8
        for (int i = 0; i < 512; i++) ssum = __fadd_rn(ssum, er[i]);
    }
    ssum = __shfl_sync(0xffffffffu, ssum, 0);
    float denom = __fadd_rn(ssum, 1e-9f);
    float yd = __frcp_rn(denom);

    // packed normalize: smv = e / denom (bit-identical per lane)
    ull pv[8];
    {
        ull dnp = dup2(-denom), ydp = dup2(yd);
        #pragma unroll
        for (int j=0;j<8;j++)
            pv[j] = divm2(pk2(v[2*j], v[2*j+1]), dnp, ydp);
    }
    // qmx = max|smv| = fl(max|e| / denom)  (monotonic correctly-rounded div, denom>0)
    #pragma unroll
    for (int o=16;o>0;o>>=1) amax = fmaxf(amax, __shfl_xor_sync(0xffffffffu, amax, o));
    float qmx = divm(amax, denom, yd);
    float sp = __fdiv_rn(qmx, 127.0f);
    if (sp == 0.0f) sp = 1.0f;
    float ys = __frcp_rn(sp);
    {
        ull spn = dup2(-sp), ysp = dup2(ys), spp = dup2(sp);
        ulonglong2 outp[4];
        #pragma unroll
        for (int j=0;j<8;j++) {
            float2 f = up2(divm2(pv[j], spn, ysp));
            float r0 = fminf(fmaxf(rintf(f.x), -127.0f), 127.0f);
            float r1 = fminf(fmaxf(rintf(f.y), -127.0f), 127.0f);
            ((ull*)outp)[j] = fmul2(pk2(r0, r1), spp);
        }
        #pragma unroll
        for (int j=0;j<4;j++)
            *(ulonglong2*)&row[j*128 + lane*4] = outp[j];
    }
}

// ---------------- attention P@V: fp32 P from gmem, single-buffer 32KB V chunks (3 CTAs/SM) ----------------
// grid (96, 4): head x 128 m-rows. 256 thr: tx(8)=8d, ty(32)=4m.
#define PV_SMEM (128*64*4)   // 32768
__global__ void __launch_bounds__(256) attnPV() {
    extern __shared__ float Vs[];          // [128][64]
    int t = threadIdx.x;
    int tx = t & 7, ty = t >> 3;
    int bh = blockIdx.x;
    int m0 = blockIdx.y * 128;

    const float* Vg = g_Vd + (size_t)bh*SS*HDIM;

    ull acc[4][4];
    #pragma unroll
    for (int i=0;i<4;i++)
        #pragma unroll
        for (int u=0;u<4;u++) acc[i][u]=0ULL;

    const float* Pg = g_P + ((size_t)bh*SS + m0 + ty*4)*SS;
    for (int kc = 0; kc < 4; ++kc) {       // ascending k chunks
        if (kc > 0) __syncthreads();
        #pragma unroll
        for (int l=0;l<8;l++)
            *(float4*)&Vs[l*1024 + t*4] = *(const float4*)(Vg + kc*8192 + l*1024 + t*4);
        __syncthreads();
        const ull* Vu = (const ull*)Vs;
        #pragma unroll 4
        for (int kb = 0; kb < 32; ++kb) {
            float pa[4][4];
            #pragma unroll
            for (int i=0;i<4;i++)
                *(float4*)pa[i] = *(const float4*)&Pg[(size_t)i*SS + kc*128 + kb*4];
            #pragma unroll
            for (int kk = 0; kk < 4; ++kk) {    // ascending k, fused fma per output
                int k = kb*4 + kk;
                ulonglong2 v0 = *(const ulonglong2*)&Vu[k*32 + tx*4];
                ulonglong2 v1 = *(const ulonglong2*)&Vu[k*32 + tx*4 + 2];
                ull vp[4] = {v0.x, v0.y, v1.x, v1.y};
                #pragma unroll
                for (int i=0;i<4;i++) {
                    ull pd = dup2(pa[i][kk]);
                    acc[i][0] = ffma2(pd, vp[0], acc[i][0]);
                    acc[i][1] = ffma2(pd, vp[1], acc[i][1]);
                    acc[i][2] = ffma2(pd, vp[2], acc[i][2]);
                    acc[i][3] = ffma2(pd, vp[3], acc[i][3]);
                }
            }
        }
    }
    int b = bh / NHEADS, h = bh % NHEADS;
    #pragma unroll
    for (int i=0;i<4;i++) {
        int s = m0 + ty*4 + i;
        float* Co = g_CTX + ((size_t)(b*SS + s))*HIDDEN + h*HDIM + tx*8;
        float2 f0 = up2(acc[i][0]), f1 = up2(acc[i][1]);
        float2 f2 = up2(acc[i][2]), f3 = up2(acc[i][3]);
        *(float4*)Co     = make_float4(f0.x, f0.y, f1.x, f1.y);
        *(float4*)(Co+4) = make_float4(f2.x, f2.y, f3.x, f3.y);
    }
}

// ---------------- host: replicate np.polyfit coefficients in double ----------------
static void build_pla(PLA& p) {
    double xs[1001], ys[1001];
    double step = 10.0 / 1000.0;
    for (int j = 0; j <= 1000; j++) xs[j] = -10.0 + (double)j * step;
    xs[1000] = 0.0;
    for (int j = 0; j <= 1000; j++) ys[j] = exp(xs[j]);
    double iv[13];
    double st2 = 10.0 / 12.0;
    for (int i = 0; i < 13; i++) iv[i] = -10.0 + (double)i * st2;
    iv[12] = 0.0;
    for (int i = 0; i < 12; i++) {
        double a = iv[i], b = iv[i+1];
        double n = 0, Sx = 0, Sy = 0, Sxx = 0, Sxy = 0;
        for (int j = 0; j <= 1000; j++) {
            if (xs[j] >= a && xs[j] <= b) {
                n += 1.0; Sx += xs[j]; Sy += ys[j];
                Sxx += xs[j]*xs[j]; Sxy += xs[j]*ys[j];
            }
        }
        double m = (n*Sxy - Sx*Sy) / (n*Sxx - Sx*Sx);
        double c = (Sy - m*Sx) / n;
        p.m[i] = (float)m;
        p.c[i] = (float)c;
    }
    for (int i = 0; i < 13; i++) p.iv[i] = (float)iv[i];
}

extern "C" void kernel_launch(void* const* d_in, const int* in_sizes, int n_in,
                              void* d_out, int out_size) {
    (void)in_sizes; (void)n_in; (void)out_size;
    const float* hs = (const float*)d_in[0];
    const float* Wq = (const float*)d_in[1];
    const float* bq = (const float*)d_in[2];
    const float* Wk = (const float*)d_in[3];
    const float* bk = (const float*)d_in[4];
    const float* Wv = (const float*)d_in[5];
    const float* bv = (const float*)d_in[6];
    const float* Wo = (const float*)d_in[7];
    const float* bo = (const float*)d_in[8];

    void *pXd, *pWd, *pWod, *pCTX, *pCd, *pQd, *pKd, *pVd;
    cudaGetSymbolAddress(&pXd, g_Xd);
    cudaGetSymbolAddress(&pWd, g_Wd);
    cudaGetSymbolAddress(&pWod, g_Wod);
    cudaGetSymbolAddress(&pCTX, g_CTX);
    cudaGetSymbolAddress(&pCd, g_Cd);
    cudaGetSymbolAddress(&pQd, g_Qd);
    cudaGetSymbolAddress(&pKd, g_Kd);
    cudaGetSymbolAddress(&pVd, g_Vd);

    PLA pla;
    build_pla(pla);

    // 1) fake-quant (dequant fp32) activations + all weights (warp per row)
    wrowquant_all<<<896, 256>>>(hs, Wq, Wk, Wv, Wo,
                                (float*)pXd, (float*)pWd, (float*)pWod);

    // 2) QKV projection (256x128 FFMA2 GEMM) + per-head quantize epilogue
    cudaFuncSetAttribute(gemmQKV, cudaFuncAttributeMaxDynamicSharedMemorySize, QKV_SMEM);
    gemmQKV<<<dim3(18, 16), 256, QKV_SMEM>>>((const float*)pXd, (const float*)pWd,
                                             bq, bk, bv,
                                             (float*)pQd, (float*)pKd, (float*)pVd);

    // 3) scores GEMM -> g_P ; softmax in place ; P@V
    cudaFuncSetAttribute(attnSc, cudaFuncAttributeMaxDynamicSharedMemorySize, SC_SMEM);
    attnSc<<<dim3(96, 16), 256, SC_SMEM>>>();
    smx<<<dim3(96, 64), 256>>>(pla);
    cudaFuncSetAttribute(attnPV, cudaFuncAttributeMaxDynamicSharedMemorySize, PV_SMEM);
    attnPV<<<dim3(96, 4), 256, PV_SMEM>>>();

    // 4) fake-quant ctx rows + output projection
    wrowquant_one<<<512, 256>>>((const float*)pCTX, (float*)pCd);
    gemmOut<<<dim3(6, 64), 256>>>((const float*)pCd, (const float*)pWod, bo, (float*)d_out);
}